// round 4
// baseline (speedup 1.0000x reference)
#include <cuda_runtime.h>
#include <math.h>

#define N_ 8
#define S_ 1024
#define F_ 64
#define E_ 512
#define H_ 8
#define HD_ 64
#define O_ 64
#define L_ 6
#define FF_ 2048
#define NS_ (N_*S_)

// ---------------- scratch (no allocations allowed) ----------------
__device__ float g_h[NS_*E_];       // running hidden state (n,s,e)
__device__ float g_q[NS_*E_];       // (n,h,s,d)
__device__ float g_k[NS_*E_];
__device__ float g_v[NS_*E_];
__device__ float g_attn[NS_*E_];    // attention output (n,s,e)
__device__ float g_buf[NS_*E_];     // pre-LN sum
__device__ float g_hx[NS_*E_];      // post-LN1
__device__ float g_ff[NS_*FF_];     // FFN hidden

// ---------------- kernel 1: embed = relu(x @ W_first + b) + pos ----------------
__global__ __launch_bounds__(512) void embed_kernel(
    const float* __restrict__ x, const float* __restrict__ W,
    const float* __restrict__ b, const float* __restrict__ pos)
{
    int ns = blockIdx.x;                 // (n,s) row
    int n = ns >> 10, s = ns & (S_-1);
    int e = threadIdx.x;                 // 512 threads = E
    __shared__ float xs[F_];
    if (e < F_) xs[e] = x[(size_t)n*F_*S_ + (size_t)e*S_ + s];
    __syncthreads();
    float acc = b[e];
    #pragma unroll 16
    for (int f = 0; f < F_; ++f)
        acc = fmaf(xs[f], W[f*E_ + e], acc);
    acc = fmaxf(acc, 0.0f) + pos[s*E_ + e];
    g_h[(size_t)ns*E_ + e] = acc;
}

// ---------------- kernel 2: per-head QKV projection ----------------
__global__ __launch_bounds__(512) void qkv_kernel(
    const float* __restrict__ Wq, const float* __restrict__ bq,
    const float* __restrict__ Wk, const float* __restrict__ bk,
    const float* __restrict__ Wv, const float* __restrict__ bv)
{
    int ns0 = blockIdx.x * 4;            // 4 (n,s) rows per block
    int t = threadIdx.x;
    int hh = t >> 6, dp = t & 63;
    __shared__ float hs[4][E_];
    #pragma unroll
    for (int r = 0; r < 4; ++r)
        hs[r][t] = g_h[(size_t)(ns0 + r)*E_ + t];
    __syncthreads();
    float aq[4], ak[4], av[4];
    float bqv = bq[dp], bkv = bk[dp], bvv = bv[dp];
    #pragma unroll
    for (int r = 0; r < 4; ++r) { aq[r]=bqv; ak[r]=bkv; av[r]=bvv; }
    #pragma unroll 4
    for (int d = 0; d < HD_; ++d) {
        float wq = Wq[d*HD_+dp], wk = Wk[d*HD_+dp], wv = Wv[d*HD_+dp];
        #pragma unroll
        for (int r = 0; r < 4; ++r) {
            float hv = hs[r][hh*HD_ + d];
            aq[r] = fmaf(hv, wq, aq[r]);
            ak[r] = fmaf(hv, wk, ak[r]);
            av[r] = fmaf(hv, wv, av[r]);
        }
    }
    #pragma unroll
    for (int r = 0; r < 4; ++r) {
        int ns = ns0 + r;
        int n = ns >> 10, s = ns & (S_-1);
        size_t o = ((size_t)(n*H_ + hh)*S_ + s)*HD_ + dp;
        g_q[o] = aq[r]; g_k[o] = ak[r]; g_v[o] = av[r];
    }
}

// ---------------- kernel 3: flash attention, Tq=64 Tk=64, 4x4 micro-tiles ----------------
// 256 threads (16x16). QsT[d][q], KP[d][k] (reused as Ps[q][k]), Vs[k][d].
// All smem reads are float4 (Q broadcast, K/V conflict-free 4-phase).
__global__ __launch_bounds__(256) void attn_kernel()
{
    __shared__ float QsT[64][64];   // [d][q]  (48 KB total static)
    __shared__ float KP [64][64];   // KsT[d][k], reused as Ps[q][k]
    __shared__ float Vs [64][64];   // [k][d]

    int bid = blockIdx.x;
    int qt = bid & 15;             // 16 q-tiles of 64
    int nh = bid >> 4;             // n*H + h
    const float* Qb = g_q + (size_t)nh*S_*HD_ + (size_t)qt*64*HD_;
    const float* Kb = g_k + (size_t)nh*S_*HD_;
    const float* Vb = g_v + (size_t)nh*S_*HD_;

    int tid = threadIdx.x;
    int tx = tid & 15, ty = tid >> 4;
    const float isc = 0.044194173824159216f;   // 1/sqrt(E)

    // load + pre-scale Q tile, store transposed
    {
        int qrow = tid >> 2;
        int dbase = (tid & 3) * 16;
        const float* qp = Qb + qrow*64 + dbase;
        #pragma unroll
        for (int u = 0; u < 4; ++u) {
            float4 t4 = *(const float4*)(qp + u*4);
            QsT[dbase+u*4+0][qrow] = t4.x*isc;
            QsT[dbase+u*4+1][qrow] = t4.y*isc;
            QsT[dbase+u*4+2][qrow] = t4.z*isc;
            QsT[dbase+u*4+3][qrow] = t4.w*isc;
        }
    }

    float o[4][4] = {};
    float m[4], l[4];
    #pragma unroll
    for (int i = 0; i < 4; ++i) { m[i] = -1e30f; l[i] = 0.0f; }

    for (int kt = 0; kt < 16; ++kt) {
        __syncthreads();           // prev PV reads of KP/Vs done
        {
            int krow = tid >> 2;
            int dbase = (tid & 3) * 16;
            const float* kp = Kb + (size_t)(kt*64 + krow)*64 + dbase;
            const float* vp = Vb + (size_t)(kt*64 + krow)*64 + dbase;
            #pragma unroll
            for (int u = 0; u < 4; ++u) {
                float4 k4 = *(const float4*)(kp + u*4);
                KP[dbase+u*4+0][krow] = k4.x;
                KP[dbase+u*4+1][krow] = k4.y;
                KP[dbase+u*4+2][krow] = k4.z;
                KP[dbase+u*4+3][krow] = k4.w;
                *(float4*)&Vs[krow][dbase+u*4] = *(const float4*)(vp + u*4);
            }
        }
        __syncthreads();

        // S tile 64x64: s[i][j] = sum_d QsT[d][ty*4+i] * KP[d][tx*4+j]
        float s[4][4] = {};
        #pragma unroll 8
        for (int d = 0; d < 64; ++d) {
            float4 qv = *(const float4*)&QsT[d][ty*4];
            float4 kv = *(const float4*)&KP[d][tx*4];
            float a0=qv.x, a1=qv.y, a2=qv.z, a3=qv.w;
            float b0=kv.x, b1=kv.y, b2=kv.z, b3=kv.w;
            s[0][0]=fmaf(a0,b0,s[0][0]); s[0][1]=fmaf(a0,b1,s[0][1]); s[0][2]=fmaf(a0,b2,s[0][2]); s[0][3]=fmaf(a0,b3,s[0][3]);
            s[1][0]=fmaf(a1,b0,s[1][0]); s[1][1]=fmaf(a1,b1,s[1][1]); s[1][2]=fmaf(a1,b2,s[1][2]); s[1][3]=fmaf(a1,b3,s[1][3]);
            s[2][0]=fmaf(a2,b0,s[2][0]); s[2][1]=fmaf(a2,b1,s[2][1]); s[2][2]=fmaf(a2,b2,s[2][2]); s[2][3]=fmaf(a2,b3,s[2][3]);
            s[3][0]=fmaf(a3,b0,s[3][0]); s[3][1]=fmaf(a3,b1,s[3][1]); s[3][2]=fmaf(a3,b2,s[3][2]); s[3][3]=fmaf(a3,b3,s[3][3]);
        }
        __syncthreads();           // all KP (K) reads done before Ps writes

        // online softmax per row (row in 16-lane shfl group), write P into KP
        #pragma unroll
        for (int i = 0; i < 4; ++i) {
            float mloc = fmaxf(fmaxf(s[i][0], s[i][1]), fmaxf(s[i][2], s[i][3]));
            #pragma unroll
            for (int off = 8; off; off >>= 1)
                mloc = fmaxf(mloc, __shfl_xor_sync(0xffffffffu, mloc, off));
            float mnew = fmaxf(m[i], mloc);
            float alpha = __expf(m[i] - mnew);
            float4 p;
            p.x = __expf(s[i][0] - mnew);
            p.y = __expf(s[i][1] - mnew);
            p.z = __expf(s[i][2] - mnew);
            p.w = __expf(s[i][3] - mnew);
            float ls = p.x + p.y + p.z + p.w;
            #pragma unroll
            for (int off = 8; off; off >>= 1)
                ls += __shfl_xor_sync(0xffffffffu, ls, off);
            m[i] = mnew;
            l[i] = l[i]*alpha + ls;
            #pragma unroll
            for (int j = 0; j < 4; ++j) o[i][j] *= alpha;
            *(float4*)&KP[ty*4+i][tx*4] = p;
        }
        __syncthreads();

        // O += P V: per k, p broadcast scalars + V float4
        #pragma unroll 8
        for (int k = 0; k < 64; ++k) {
            float4 vv = *(const float4*)&Vs[k][tx*4];
            float p0=KP[ty*4+0][k], p1=KP[ty*4+1][k], p2=KP[ty*4+2][k], p3=KP[ty*4+3][k];
            o[0][0]=fmaf(p0,vv.x,o[0][0]); o[0][1]=fmaf(p0,vv.y,o[0][1]); o[0][2]=fmaf(p0,vv.z,o[0][2]); o[0][3]=fmaf(p0,vv.w,o[0][3]);
            o[1][0]=fmaf(p1,vv.x,o[1][0]); o[1][1]=fmaf(p1,vv.y,o[1][1]); o[1][2]=fmaf(p1,vv.z,o[1][2]); o[1][3]=fmaf(p1,vv.w,o[1][3]);
            o[2][0]=fmaf(p2,vv.x,o[2][0]); o[2][1]=fmaf(p2,vv.y,o[2][1]); o[2][2]=fmaf(p2,vv.z,o[2][2]); o[2][3]=fmaf(p2,vv.w,o[2][3]);
            o[3][0]=fmaf(p3,vv.x,o[3][0]); o[3][1]=fmaf(p3,vv.y,o[3][1]); o[3][2]=fmaf(p3,vv.z,o[3][2]); o[3][3]=fmaf(p3,vv.w,o[3][3]);
        }
    }

    // write O in (n,s,e) layout
    int n = nh >> 3, hh = nh & 7;
    float* Ob = g_attn + ((size_t)n*S_ + qt*64)*E_ + hh*HD_;
    #pragma unroll
    for (int i = 0; i < 4; ++i) {
        float invl = 1.0f / l[i];
        int r = ty*4 + i;
        float4 v;
        v.x = o[i][0]*invl; v.y = o[i][1]*invl; v.z = o[i][2]*invl; v.w = o[i][3]*invl;
        *(float4*)(Ob + (size_t)r*E_ + tx*4) = v;
    }
}

// ---------------- kernel 4: big GEMM, 128x128x16 tiles, 8x8 per thread ----------------
// C = A@B + bias (+R) (+relu). All smem reads float4; register-staged prefetch.
template<int RELU, int RESID>
__global__ __launch_bounds__(256) void gemm128_kernel(
    const float* __restrict__ A, const float* __restrict__ B,
    const float* __restrict__ bias, const float* __restrict__ R,
    float* __restrict__ C, int M, int Nn, int K)
{
    __shared__ float As[16][128];   // [k][m] transposed
    __shared__ float Bs[16][128];   // [k][n]
    int m0 = blockIdx.y * 128, n0 = blockIdx.x * 128;
    int tid = threadIdx.x;
    int tx = tid & 15, ty = tid >> 4;

    int arow = tid >> 1, acol = (tid & 1) * 8;
    int brow = tid >> 4, bcol = (tid & 15) * 8;
    const float* Ap = A + (size_t)(m0 + arow)*K + acol;
    const float* Bp = B + (size_t)brow*Nn + n0 + bcol;

    float4 a0 = *(const float4*)(Ap);
    float4 a1 = *(const float4*)(Ap + 4);
    float4 b0 = *(const float4*)(Bp);
    float4 b1 = *(const float4*)(Bp + 4);

    float acc[8][8] = {};
    for (int k0 = 16; ; k0 += 16) {
        As[acol+0][arow]=a0.x; As[acol+1][arow]=a0.y; As[acol+2][arow]=a0.z; As[acol+3][arow]=a0.w;
        As[acol+4][arow]=a1.x; As[acol+5][arow]=a1.y; As[acol+6][arow]=a1.z; As[acol+7][arow]=a1.w;
        *(float4*)&Bs[brow][bcol]   = b0;
        *(float4*)&Bs[brow][bcol+4] = b1;
        __syncthreads();
        if (k0 < K) {
            a0 = *(const float4*)(Ap + k0);
            a1 = *(const float4*)(Ap + k0 + 4);
            b0 = *(const float4*)(Bp + (size_t)k0*Nn);
            b1 = *(const float4*)(Bp + (size_t)k0*Nn + 4);
        }
        #pragma unroll
        for (int kk = 0; kk < 16; ++kk) {
            float4 av0 = *(const float4*)&As[kk][ty*4];
            float4 av1 = *(const float4*)&As[kk][64 + ty*4];
            float4 bv0 = *(const float4*)&Bs[kk][tx*4];
            float4 bv1 = *(const float4*)&Bs[kk][64 + tx*4];
            float a[8] = {av0.x,av0.y,av0.z,av0.w,av1.x,av1.y,av1.z,av1.w};
            float b[8] = {bv0.x,bv0.y,bv0.z,bv0.w,bv1.x,bv1.y,bv1.z,bv1.w};
            #pragma unroll
            for (int i = 0; i < 8; ++i)
                #pragma unroll
                for (int j = 0; j < 8; ++j)
                    acc[i][j] = fmaf(a[i], b[j], acc[i][j]);
        }
        __syncthreads();
        if (k0 >= K) break;
    }

    #pragma unroll
    for (int gi = 0; gi < 2; ++gi)
    #pragma unroll
    for (int i = 0; i < 4; ++i) {
        int mrow = m0 + gi*64 + ty*4 + i;
        #pragma unroll
        for (int gj = 0; gj < 2; ++gj) {
            int nn = n0 + gj*64 + tx*4;
            float4 bi = *(const float4*)(bias + nn);
            float4 v;
            v.x = acc[gi*4+i][gj*4+0] + bi.x;
            v.y = acc[gi*4+i][gj*4+1] + bi.y;
            v.z = acc[gi*4+i][gj*4+2] + bi.z;
            v.w = acc[gi*4+i][gj*4+3] + bi.w;
            if (RESID) {
                float4 r4 = *(const float4*)(R + (size_t)mrow*Nn + nn);
                v.x += r4.x; v.y += r4.y; v.z += r4.z; v.w += r4.w;
            }
            if (RELU) { v.x=fmaxf(v.x,0.f); v.y=fmaxf(v.y,0.f); v.z=fmaxf(v.z,0.f); v.w=fmaxf(v.w,0.f); }
            *(float4*)(C + (size_t)mrow*Nn + nn) = v;
        }
    }
}

// ---------------- kernel 4b: small GEMM (final conv, N=64) ----------------
template<int RELU, int RESID, int FINAL>
__global__ __launch_bounds__(256) void gemm_kernel(
    const float* __restrict__ A, const float* __restrict__ B,
    const float* __restrict__ bias, const float* __restrict__ R,
    float* __restrict__ C, int M, int Nn, int K)
{
    __shared__ float As[16][65];
    __shared__ float Bs[16][64];
    int m0 = blockIdx.y * 64, n0 = blockIdx.x * 64;
    int tid = threadIdx.x;
    int tx = tid & 15, ty = tid >> 4;

    int ar = tid >> 2;
    int ac = (tid & 3) * 4;
    int br = tid >> 4;
    int bc = (tid & 15) * 4;
    const float* Ap = A + (size_t)(m0 + ar)*K + ac;
    const float* Bp = B + (size_t)br*Nn + n0 + bc;

    float acc[4][4] = {};
    for (int k0 = 0; k0 < K; k0 += 16) {
        float4 a4 = *(const float4*)(Ap + k0);
        float4 b4 = *(const float4*)(Bp + (size_t)k0*Nn);
        As[ac+0][ar]=a4.x; As[ac+1][ar]=a4.y; As[ac+2][ar]=a4.z; As[ac+3][ar]=a4.w;
        *(float4*)&Bs[br][bc] = b4;
        __syncthreads();
        #pragma unroll
        for (int kk = 0; kk < 16; ++kk) {
            float a[4], b[4];
            #pragma unroll
            for (int i = 0; i < 4; ++i) a[i] = As[kk][ty + 16*i];
            #pragma unroll
            for (int j = 0; j < 4; ++j) b[j] = Bs[kk][tx + 16*j];
            #pragma unroll
            for (int i = 0; i < 4; ++i)
                #pragma unroll
                for (int j = 0; j < 4; ++j)
                    acc[i][j] = fmaf(a[i], b[j], acc[i][j]);
        }
        __syncthreads();
    }
    #pragma unroll
    for (int i = 0; i < 4; ++i) {
        int mrow = m0 + ty + 16*i;
        #pragma unroll
        for (int j = 0; j < 4; ++j) {
            int nn = n0 + tx + 16*j;
            float v = acc[i][j] + bias[nn];
            if (RESID) v += R[(size_t)mrow*Nn + nn];
            if (RELU)  v = fmaxf(v, 0.0f);
            if (FINAL) {
                C[((size_t)(mrow >> 10)*O_ + nn)*S_ + (mrow & (S_-1))] = v;
            } else {
                C[(size_t)mrow*Nn + nn] = v;
            }
        }
    }
}

// ---------------- kernel 5: layernorm over E=512 ----------------
__global__ __launch_bounds__(128) void ln_kernel(
    const float* __restrict__ in, float* __restrict__ out,
    const float* __restrict__ g, const float* __restrict__ b)
{
    int row = blockIdx.x;
    int t = threadIdx.x;
    const float* p = in + (size_t)row*E_;
    float v[4], s = 0.0f, sq = 0.0f;
    #pragma unroll
    for (int q = 0; q < 4; ++q) {
        v[q] = p[t + 128*q];
        s += v[q]; sq += v[q]*v[q];
    }
    #pragma unroll
    for (int off = 16; off; off >>= 1) {
        s  += __shfl_xor_sync(0xffffffffu, s,  off);
        sq += __shfl_xor_sync(0xffffffffu, sq, off);
    }
    __shared__ float red[2][4];
    int w = t >> 5;
    if ((t & 31) == 0) { red[0][w] = s; red[1][w] = sq; }
    __syncthreads();
    s  = red[0][0] + red[0][1] + red[0][2] + red[0][3];
    sq = red[1][0] + red[1][1] + red[1][2] + red[1][3];
    float mean = s * (1.0f/E_);
    float var = sq * (1.0f/E_) - mean*mean;
    float inv = rsqrtf(var + 1e-5f);
    float* q_ = out + (size_t)row*E_;
    #pragma unroll
    for (int q = 0; q < 4; ++q) {
        int e = t + 128*q;
        q_[e] = (v[q] - mean)*inv*g[e] + b[e];
    }
}

// ---------------- launch ----------------
extern "C" void kernel_launch(void* const* d_in, const int* in_sizes, int n_in,
                              void* d_out, int out_size)
{
    const float* x       = (const float*)d_in[0];
    const float* W_first = (const float*)d_in[1];
    const float* b_first = (const float*)d_in[2];
    const float* pos_emb = (const float*)d_in[3];
    const float* Wq      = (const float*)d_in[4];
    const float* bq      = (const float*)d_in[5];
    const float* Wk      = (const float*)d_in[6];
    const float* bk      = (const float*)d_in[7];
    const float* Wv      = (const float*)d_in[8];
    const float* bv      = (const float*)d_in[9];
    const float* Wo      = (const float*)d_in[10];
    const float* bo      = (const float*)d_in[11];
    const float* g1      = (const float*)d_in[12];
    const float* be1     = (const float*)d_in[13];
    const float* Wf1     = (const float*)d_in[14];
    const float* bf1     = (const float*)d_in[15];
    const float* Wf2     = (const float*)d_in[16];
    const float* bf2     = (const float*)d_in[17];
    const float* g2      = (const float*)d_in[18];
    const float* be2     = (const float*)d_in[19];
    const float* Wfin    = (const float*)d_in[20];
    const float* bfin    = (const float*)d_in[21];
    (void)in_sizes; (void)n_in; (void)out_size;

    float *h_p, *attn_p, *buf_p, *hx_p, *ff_p;
    cudaGetSymbolAddress((void**)&h_p,   g_h);
    cudaGetSymbolAddress((void**)&attn_p,g_attn);
    cudaGetSymbolAddress((void**)&buf_p, g_buf);
    cudaGetSymbolAddress((void**)&hx_p,  g_hx);
    cudaGetSymbolAddress((void**)&ff_p,  g_ff);

    embed_kernel<<<NS_, 512>>>(x, W_first, b_first, pos_emb);

    for (int i = 0; i < L_; ++i) {
        qkv_kernel<<<NS_/4, 512>>>(Wq + i*HD_*HD_, bq + i*HD_,
                                   Wk + i*HD_*HD_, bk + i*HD_,
                                   Wv + i*HD_*HD_, bv + i*HD_);
        attn_kernel<<<N_*H_*(S_/64), 256>>>();
        // o@Wo + bo + h -> buf ; LN -> hx
        gemm128_kernel<0,1><<<dim3(E_/128, NS_/128), 256>>>(
            attn_p, Wo + (size_t)i*E_*E_, bo + i*E_, h_p, buf_p, NS_, E_, E_);
        ln_kernel<<<NS_, 128>>>(buf_p, hx_p, g1 + i*E_, be1 + i*E_);
        // relu(hx@Wf1 + bf1) -> ff
        gemm128_kernel<1,0><<<dim3(FF_/128, NS_/128), 256>>>(
            hx_p, Wf1 + (size_t)i*E_*FF_, bf1 + i*FF_, (const float*)0, ff_p, NS_, FF_, E_);
        // ff@Wf2 + bf2 + hx -> buf ; LN -> h
        gemm128_kernel<0,1><<<dim3(E_/128, NS_/128), 256>>>(
            ff_p, Wf2 + (size_t)i*FF_*E_, bf2 + i*E_, hx_p, buf_p, NS_, E_, FF_);
        ln_kernel<<<NS_, 128>>>(buf_p, h_p, g2 + i*E_, be2 + i*E_);
    }

    // final pointwise conv: out[n,o,s] = h @ Wfin + bfin
    gemm_kernel<0,0,1><<<dim3(O_/64, NS_/64), 256>>>(
        h_p, Wfin, bfin, (const float*)0, (float*)d_out, NS_, O_, E_);
}

// round 6
// speedup vs baseline: 2.1254x; 2.1254x over previous
#include <cuda_runtime.h>
#include <cuda_bf16.h>
#include <math.h>
#include <stdint.h>

#define N_ 8
#define S_ 1024
#define F_ 64
#define E_ 512
#define H_ 8
#define HD_ 64
#define O_ 64
#define L_ 6
#define FF_ 2048
#define NS_ (N_*S_)

// ---------------- scratch (no allocations allowed) ----------------
__device__ float g_h[NS_*E_];       // running hidden state (n,s,e)
__device__ float g_q[NS_*E_];       // (n,h,s,d)
__device__ float g_k[NS_*E_];
__device__ float g_v[NS_*E_];
__device__ float g_buf[NS_*E_];     // pre-LN sum
__device__ float g_hx[NS_*E_];      // post-LN1 (fp32 residual for FF2)

// bf16 split activations
__device__ __nv_bfloat16 g_attnhi[NS_*E_], g_attnlo[NS_*E_];
__device__ __nv_bfloat16 g_hxhi[NS_*E_],   g_hxlo[NS_*E_];
__device__ __nv_bfloat16 g_ffhi[NS_*FF_],  g_fflo[NS_*FF_];

// bf16 split transposed weights  Wt[n][k]
__device__ __nv_bfloat16 g_wothi[L_*E_*E_],   g_wotlo[L_*E_*E_];
__device__ __nv_bfloat16 g_wf1thi[L_*E_*FF_], g_wf1tlo[L_*E_*FF_];
__device__ __nv_bfloat16 g_wf2thi[L_*FF_*E_], g_wf2tlo[L_*FF_*E_];

// ================= helpers =================
static __device__ __forceinline__ uint32_t smem_u32(const void* p){
    uint32_t a;
    asm("{ .reg .u64 t; cvta.to.shared.u64 t, %1; cvt.u32.u64 %0, t; }" : "=r"(a) : "l"(p));
    return a;
}
static __device__ __forceinline__ void cp16(uint32_t dst, const void* src){
    asm volatile("cp.async.cg.shared.global [%0], [%1], 16;" :: "r"(dst), "l"(src));
}
#define CP_COMMIT() asm volatile("cp.async.commit_group;" ::: "memory")
#define CP_WAIT1()  asm volatile("cp.async.wait_group 1;" ::: "memory")
#define CP_WAIT0()  asm volatile("cp.async.wait_group 0;" ::: "memory")

static __device__ __forceinline__ void mma16816(
    float* d, const uint32_t* a, uint32_t b0, uint32_t b1)
{
    asm volatile("mma.sync.aligned.m16n8k16.row.col.f32.bf16.bf16.f32 "
        "{%0,%1,%2,%3}, {%4,%5,%6,%7}, {%8,%9}, {%0,%1,%2,%3};"
        : "+f"(d[0]), "+f"(d[1]), "+f"(d[2]), "+f"(d[3])
        : "r"(a[0]), "r"(a[1]), "r"(a[2]), "r"(a[3]), "r"(b0), "r"(b1));
}

static __device__ __forceinline__ void split2(float v, __nv_bfloat16& hi, __nv_bfloat16& lo){
    hi = __float2bfloat16(v);
    lo = __float2bfloat16(v - __bfloat162float(hi));
}

// ================= kernel 1: embed =================
__global__ __launch_bounds__(512) void embed_kernel(
    const float* __restrict__ x, const float* __restrict__ W,
    const float* __restrict__ b, const float* __restrict__ pos)
{
    int ns = blockIdx.x;
    int n = ns >> 10, s = ns & (S_-1);
    int e = threadIdx.x;
    __shared__ float xs[F_];
    if (e < F_) xs[e] = x[(size_t)n*F_*S_ + (size_t)e*S_ + s];
    __syncthreads();
    float acc = b[e];
    #pragma unroll 16
    for (int f = 0; f < F_; ++f)
        acc = fmaf(xs[f], W[f*E_ + e], acc);
    acc = fmaxf(acc, 0.0f) + pos[s*E_ + e];
    g_h[(size_t)ns*E_ + e] = acc;
}

// ================= kernel 2: QKV projection =================
__global__ __launch_bounds__(512) void qkv_kernel(
    const float* __restrict__ Wq, const float* __restrict__ bq,
    const float* __restrict__ Wk, const float* __restrict__ bk,
    const float* __restrict__ Wv, const float* __restrict__ bv)
{
    int ns0 = blockIdx.x * 4;
    int t = threadIdx.x;
    int hh = t >> 6, dp = t & 63;
    __shared__ float hs[4][E_];
    #pragma unroll
    for (int r = 0; r < 4; ++r)
        hs[r][t] = g_h[(size_t)(ns0 + r)*E_ + t];
    __syncthreads();
    float aq[4], ak[4], av[4];
    float bqv = bq[dp], bkv = bk[dp], bvv = bv[dp];
    #pragma unroll
    for (int r = 0; r < 4; ++r) { aq[r]=bqv; ak[r]=bkv; av[r]=bvv; }
    #pragma unroll 4
    for (int d = 0; d < HD_; ++d) {
        float wq = Wq[d*HD_+dp], wk = Wk[d*HD_+dp], wv = Wv[d*HD_+dp];
        #pragma unroll
        for (int r = 0; r < 4; ++r) {
            float hv = hs[r][hh*HD_ + d];
            aq[r] = fmaf(hv, wq, aq[r]);
            ak[r] = fmaf(hv, wk, ak[r]);
            av[r] = fmaf(hv, wv, av[r]);
        }
    }
    #pragma unroll
    for (int r = 0; r < 4; ++r) {
        int ns = ns0 + r;
        int n = ns >> 10, s = ns & (S_-1);
        size_t o = ((size_t)(n*H_ + hh)*S_ + s)*HD_ + dp;
        g_q[o] = aq[r]; g_k[o] = ak[r]; g_v[o] = av[r];
    }
}

// ================= kernel 3: flash attention (known-good Tk=32) =================
// epilogue writes split bf16 (feeds Wo tensor GEMM)
__global__ __launch_bounds__(256) void attn_kernel()
{
    __shared__ float Qs[64][64];
    __shared__ float Ks[32][65];
    __shared__ float Vs[32][64];
    __shared__ float Ps[64][33];

    int bid = blockIdx.x;
    int qt = bid & 15;
    int nh = bid >> 4;
    const float* Qb = g_q + (size_t)nh*S_*HD_ + (size_t)qt*64*HD_;
    const float* Kb = g_k + (size_t)nh*S_*HD_;
    const float* Vb = g_v + (size_t)nh*S_*HD_;

    int tid = threadIdx.x;
    int tx = tid & 15, ty = tid >> 4;
    const float isc = 0.044194173824159216f;   // 1/sqrt(E)

    for (int idx = tid*4; idx < 4096; idx += 1024) {
        float4 t4 = *(const float4*)(Qb + idx);
        int r = idx >> 6, c = idx & 63;
        Qs[r][c]   = t4.x*isc; Qs[r][c+1] = t4.y*isc;
        Qs[r][c+2] = t4.z*isc; Qs[r][c+3] = t4.w*isc;
    }

    float o[4][4] = {};
    float m[4], l[4];
    #pragma unroll
    for (int i = 0; i < 4; ++i) { m[i] = -1e30f; l[i] = 0.0f; }

    for (int kt = 0; kt < 32; ++kt) {
        __syncthreads();
        {
            const float* kp = Kb + kt*32*64;
            const float* vp = Vb + kt*32*64;
            int idx = tid*8;
            #pragma unroll
            for (int u = 0; u < 2; ++u) {
                int id = idx + u*4;
                float4 k4 = *(const float4*)(kp + id);
                float4 v4 = *(const float4*)(vp + id);
                int r = id >> 6, c = id & 63;
                Ks[r][c]=k4.x; Ks[r][c+1]=k4.y; Ks[r][c+2]=k4.z; Ks[r][c+3]=k4.w;
                *(float4*)&Vs[r][c] = v4;
            }
        }
        __syncthreads();

        float s[4][2] = {};
        #pragma unroll 4
        for (int d = 0; d < 64; ++d) {
            float q0=Qs[ty][d], q1=Qs[ty+16][d], q2=Qs[ty+32][d], q3=Qs[ty+48][d];
            float k0=Ks[tx][d], k1=Ks[tx+16][d];
            s[0][0]=fmaf(q0,k0,s[0][0]); s[1][0]=fmaf(q1,k0,s[1][0]);
            s[2][0]=fmaf(q2,k0,s[2][0]); s[3][0]=fmaf(q3,k0,s[3][0]);
            s[0][1]=fmaf(q0,k1,s[0][1]); s[1][1]=fmaf(q1,k1,s[1][1]);
            s[2][1]=fmaf(q2,k1,s[2][1]); s[3][1]=fmaf(q3,k1,s[3][1]);
        }

        #pragma unroll
        for (int i = 0; i < 4; ++i) {
            float mloc = fmaxf(s[i][0], s[i][1]);
            #pragma unroll
            for (int off = 8; off; off >>= 1)
                mloc = fmaxf(mloc, __shfl_xor_sync(0xffffffffu, mloc, off));
            float mnew = fmaxf(m[i], mloc);
            float alpha = __expf(m[i] - mnew);
            float p0 = __expf(s[i][0] - mnew);
            float p1 = __expf(s[i][1] - mnew);
            m[i] = mnew;
            float ls = p0 + p1;
            #pragma unroll
            for (int off = 8; off; off >>= 1)
                ls += __shfl_xor_sync(0xffffffffu, ls, off);
            l[i] = l[i]*alpha + ls;
            #pragma unroll
            for (int j = 0; j < 4; ++j) o[i][j] *= alpha;
            Ps[ty+16*i][tx]    = p0;
            Ps[ty+16*i][tx+16] = p1;
        }
        __syncthreads();

        #pragma unroll 4
        for (int k = 0; k < 32; ++k) {
            float p0=Ps[ty][k], p1=Ps[ty+16][k], p2=Ps[ty+32][k], p3=Ps[ty+48][k];
            float v0=Vs[k][tx], v1=Vs[k][tx+16], v2=Vs[k][tx+32], v3=Vs[k][tx+48];
            o[0][0]=fmaf(p0,v0,o[0][0]); o[0][1]=fmaf(p0,v1,o[0][1]); o[0][2]=fmaf(p0,v2,o[0][2]); o[0][3]=fmaf(p0,v3,o[0][3]);
            o[1][0]=fmaf(p1,v0,o[1][0]); o[1][1]=fmaf(p1,v1,o[1][1]); o[1][2]=fmaf(p1,v2,o[1][2]); o[1][3]=fmaf(p1,v3,o[1][3]);
            o[2][0]=fmaf(p2,v0,o[2][0]); o[2][1]=fmaf(p2,v1,o[2][1]); o[2][2]=fmaf(p2,v2,o[2][2]); o[2][3]=fmaf(p2,v3,o[2][3]);
            o[3][0]=fmaf(p3,v0,o[3][0]); o[3][1]=fmaf(p3,v1,o[3][1]); o[3][2]=fmaf(p3,v2,o[3][2]); o[3][3]=fmaf(p3,v3,o[3][3]);
        }
    }

    int n = nh >> 3, hh = nh & 7;
    size_t base = ((size_t)n*S_ + (size_t)qt*64)*E_ + hh*HD_;
    #pragma unroll
    for (int i = 0; i < 4; ++i) {
        float invl = 1.0f / l[i];
        int r = ty + 16*i;
        #pragma unroll
        for (int j = 0; j < 4; ++j) {
            float v = o[i][j]*invl;
            size_t idx = base + (size_t)r*E_ + tx + 16*j;
            __nv_bfloat16 hi, lo; split2(v, hi, lo);
            g_attnhi[idx] = hi; g_attnlo[idx] = lo;
        }
    }
}

// ================= weight transpose + split =================
// in: W [K][N] fp32 (layer z stride K*N) -> out hi/lo [N][K] bf16
__global__ __launch_bounds__(256) void wsplit_kernel(
    const float* __restrict__ W, __nv_bfloat16* __restrict__ hi,
    __nv_bfloat16* __restrict__ lo, int K, int N)
{
    __shared__ float t[32][33];
    size_t lstr = (size_t)K*N*blockIdx.z;
    const float* Wl = W + lstr;
    __nv_bfloat16* hil = hi + lstr;
    __nv_bfloat16* lol = lo + lstr;
    int kb = blockIdx.y*32, nb = blockIdx.x*32;
    int x = threadIdx.x, y0 = threadIdx.y;
    for (int y = y0; y < 32; y += 8)
        t[y][x] = Wl[(size_t)(kb+y)*N + nb + x];
    __syncthreads();
    for (int y = y0; y < 32; y += 8) {
        float v = t[x][y];                       // W[kb+x][nb+y]
        __nv_bfloat16 h, l2; split2(v, h, l2);
        size_t o = (size_t)(nb+y)*K + kb + x;    // out[n][k]
        hil[o] = h; lol[o] = l2;
    }
}

// ================= mma.sync GEMM: C[M,Nn] = A[M,K] * Bt[Nn,K]^T =================
// A,B pre-split bf16 (hi/lo). BM=BN=128, BK=32, 8 warps (4m x 2n), warp tile 32x64.
// 3 mma per (frag, kstep): hi*hi + lo*hi + hi*lo. fp32 accum in registers.
// SMEM stage: 4 arrays [128][40] bf16 (pad 40 -> conflict-free frag LDS), 40960 B; x2 stages.
#define GSTAGE_B 40960
#define GARR_B   10240

static __device__ __forceinline__ void mma_load_stage(
    uint32_t sbase, int st,
    const __nv_bfloat16* __restrict__ Ahi, const __nv_bfloat16* __restrict__ Alo,
    const __nv_bfloat16* __restrict__ Bhi, const __nv_bfloat16* __restrict__ Blo,
    int m0, int n0, int k0, int K, int tid)
{
    uint32_t s0 = sbase + st*GSTAGE_B;
    #pragma unroll
    for (int i = 0; i < 2; ++i) {
        int id = tid + i*256;               // 0..511
        int r = id >> 2, c = id & 3;        // row 0..127, 16B-chunk 0..3
        uint32_t off = (uint32_t)(r*80 + c*16);
        size_t ga = (size_t)(m0 + r)*K + k0 + c*8;
        size_t gb = (size_t)(n0 + r)*K + k0 + c*8;
        cp16(s0 +            off, Ahi + ga);
        cp16(s0 +   GARR_B + off, Alo + ga);
        cp16(s0 + 2*GARR_B + off, Bhi + gb);
        cp16(s0 + 3*GARR_B + off, Blo + gb);
    }
    CP_COMMIT();
}

template<int RELU, int RESID, int SPLITOUT>
__global__ __launch_bounds__(256) void gemm_mma(
    const __nv_bfloat16* __restrict__ Ahi, const __nv_bfloat16* __restrict__ Alo,
    const __nv_bfloat16* __restrict__ Bhi, const __nv_bfloat16* __restrict__ Blo,
    const float* __restrict__ bias, const float* __restrict__ Rres,
    float* __restrict__ Cf, __nv_bfloat16* __restrict__ Chi, __nv_bfloat16* __restrict__ Clo,
    int Nn, int K)
{
    extern __shared__ __nv_bfloat16 sm[];
    uint32_t sbase = smem_u32(sm);
    int tid = threadIdx.x;
    int warp = tid >> 5, lane = tid & 31;
    int m0 = blockIdx.y * 128, n0 = blockIdx.x * 128;
    int wm0 = (warp & 3) * 32, wn0 = (warp >> 2) * 64;
    int lr = lane >> 2, lc2 = (lane & 3) * 2;

    float acc[2][8][4];
    #pragma unroll
    for (int a = 0; a < 2; ++a)
        #pragma unroll
        for (int b = 0; b < 8; ++b)
            #pragma unroll
            for (int c = 0; c < 4; ++c) acc[a][b][c] = 0.0f;

    int NKB = K >> 5;   // BK=32

    mma_load_stage(sbase, 0, Ahi, Alo, Bhi, Blo, m0, n0, 0,  K, tid);
    mma_load_stage(sbase, 1, Ahi, Alo, Bhi, Blo, m0, n0, 32, K, tid);

    for (int kb = 0; kb < NKB; ++kb) {
        int st = kb & 1;
        if (kb == NKB-1) { CP_WAIT0(); } else { CP_WAIT1(); }
        __syncthreads();

        const __nv_bfloat16* sA  = sm + st*(GSTAGE_B/2);
        const __nv_bfloat16* sAl = sA + GARR_B/2;
        const __nv_bfloat16* sB  = sA + 2*(GARR_B/2);
        const __nv_bfloat16* sBl = sA + 3*(GARR_B/2);

        #pragma unroll
        for (int ks = 0; ks < 2; ++ks) {
            int kk = ks*16 + lc2;
            uint32_t ahi[2][4], alo[2][4];
            #pragma unroll
            for (int mt = 0; mt < 2; ++mt) {
                int r = wm0 + mt*16 + lr;
                ahi[mt][0] = *(const uint32_t*)(sA  + r*40 + kk);
                ahi[mt][1] = *(const uint32_t*)(sA  + (r+8)*40 + kk);
                ahi[mt][2] = *(const uint32_t*)(sA  + r*40 + kk + 8);
                ahi[mt][3] = *(const uint32_t*)(sA  + (r+8)*40 + kk + 8);
                alo[mt][0] = *(const uint32_t*)(sAl + r*40 + kk);
                alo[mt][1] = *(const uint32_t*)(sAl + (r+8)*40 + kk);
                alo[mt][2] = *(const uint32_t*)(sAl + r*40 + kk + 8);
                alo[mt][3] = *(const uint32_t*)(sAl + (r+8)*40 + kk + 8);
            }
            #pragma unroll
            for (int nt = 0; nt < 8; ++nt) {
                int n = wn0 + nt*8 + lr;
                uint32_t bh0 = *(const uint32_t*)(sB  + n*40 + kk);
                uint32_t bh1 = *(const uint32_t*)(sB  + n*40 + kk + 8);
                uint32_t bl0 = *(const uint32_t*)(sBl + n*40 + kk);
                uint32_t bl1 = *(const uint32_t*)(sBl + n*40 + kk + 8);
                #pragma unroll
                for (int mt = 0; mt < 2; ++mt) {
                    mma16816(acc[mt][nt], ahi[mt], bh0, bh1);
                    mma16816(acc[mt][nt], alo[mt], bh0, bh1);
                    mma16816(acc[mt][nt], ahi[mt], bl0, bl1);
                }
            }
        }
        __syncthreads();
        if (kb + 2 < NKB)
            mma_load_stage(sbase, st, Ahi, Alo, Bhi, Blo, m0, n0, (kb+2)*32, K, tid);
    }

    // epilogue: d0,d1 -> row lr, cols lc2..+1 ; d2,d3 -> row lr+8
    #pragma unroll
    for (int mt = 0; mt < 2; ++mt) {
        #pragma unroll
        for (int half = 0; half < 2; ++half) {
            int m = m0 + wm0 + mt*16 + half*8 + lr;
            #pragma unroll
            for (int nt = 0; nt < 8; ++nt) {
                int c0 = n0 + wn0 + nt*8 + lc2;
                float2 bi = *(const float2*)(bias + c0);
                float v0 = acc[mt][nt][half*2+0] + bi.x;
                float v1 = acc[mt][nt][half*2+1] + bi.y;
                if (RESID) {
                    float2 rr = *(const float2*)(Rres + (size_t)m*Nn + c0);
                    v0 += rr.x; v1 += rr.y;
                }
                if (RELU) { v0 = fmaxf(v0, 0.f); v1 = fmaxf(v1, 0.f); }
                if (SPLITOUT) {
                    __nv_bfloat16 h0,l0,h1,l1;
                    split2(v0,h0,l0); split2(v1,h1,l1);
                    *(__nv_bfloat162*)(Chi + (size_t)m*Nn + c0) = __nv_bfloat162(h0,h1);
                    *(__nv_bfloat162*)(Clo + (size_t)m*Nn + c0) = __nv_bfloat162(l0,l1);
                } else {
                    *(float2*)(Cf + (size_t)m*Nn + c0) = make_float2(v0, v1);
                }
            }
        }
    }
}

// ================= small SIMT GEMM (final conv, N=64) =================
template<int FINAL>
__global__ __launch_bounds__(256) void gemm_kernel(
    const float* __restrict__ A, const float* __restrict__ B,
    const float* __restrict__ bias, float* __restrict__ C,
    int M, int Nn, int K)
{
    __shared__ float As[16][65];
    __shared__ float Bs[16][64];
    int m0 = blockIdx.y * 64, n0 = blockIdx.x * 64;
    int tid = threadIdx.x;
    int tx = tid & 15, ty = tid >> 4;

    int ar = tid >> 2;
    int ac = (tid & 3) * 4;
    int br = tid >> 4;
    int bc = (tid & 15) * 4;
    const float* Ap = A + (size_t)(m0 + ar)*K + ac;
    const float* Bp = B + (size_t)br*Nn + n0 + bc;

    float acc[4][4] = {};
    for (int k0 = 0; k0 < K; k0 += 16) {
        float4 a4 = *(const float4*)(Ap + k0);
        float4 b4 = *(const float4*)(Bp + (size_t)k0*Nn);
        As[ac+0][ar]=a4.x; As[ac+1][ar]=a4.y; As[ac+2][ar]=a4.z; As[ac+3][ar]=a4.w;
        *(float4*)&Bs[br][bc] = b4;
        __syncthreads();
        #pragma unroll
        for (int kk = 0; kk < 16; ++kk) {
            float a[4], b[4];
            #pragma unroll
            for (int i = 0; i < 4; ++i) a[i] = As[kk][ty + 16*i];
            #pragma unroll
            for (int j = 0; j < 4; ++j) b[j] = Bs[kk][tx + 16*j];
            #pragma unroll
            for (int i = 0; i < 4; ++i)
                #pragma unroll
                for (int j = 0; j < 4; ++j)
                    acc[i][j] = fmaf(a[i], b[j], acc[i][j]);
        }
        __syncthreads();
    }
    #pragma unroll
    for (int i = 0; i < 4; ++i) {
        int mrow = m0 + ty + 16*i;
        #pragma unroll
        for (int j = 0; j < 4; ++j) {
            int nn = n0 + tx + 16*j;
            float v = acc[i][j] + bias[nn];
            if (FINAL) {
                C[((size_t)(mrow >> 10)*O_ + nn)*S_ + (mrow & (S_-1))] = v;
            } else {
                C[(size_t)mrow*Nn + nn] = v;
            }
        }
    }
}

// ================= layernorm (optional split output) =================
template<int SPLIT>
__global__ __launch_bounds__(128) void ln_kernel(
    const float* __restrict__ in, float* __restrict__ out,
    const float* __restrict__ g, const float* __restrict__ b,
    __nv_bfloat16* __restrict__ ohi, __nv_bfloat16* __restrict__ olo)
{
    int row = blockIdx.x;
    int t = threadIdx.x;
    const float* p = in + (size_t)row*E_;
    float v[4], s = 0.0f, sq = 0.0f;
    #pragma unroll
    for (int q = 0; q < 4; ++q) {
        v[q] = p[t + 128*q];
        s += v[q]; sq += v[q]*v[q];
    }
    #pragma unroll
    for (int off = 16; off; off >>= 1) {
        s  += __shfl_xor_sync(0xffffffffu, s,  off);
        sq += __shfl_xor_sync(0xffffffffu, sq, off);
    }
    __shared__ float red[2][4];
    int w = t >> 5;
    if ((t & 31) == 0) { red[0][w] = s; red[1][w] = sq; }
    __syncthreads();
    s  = red[0][0] + red[0][1] + red[0][2] + red[0][3];
    sq = red[1][0] + red[1][1] + red[1][2] + red[1][3];
    float mean = s * (1.0f/E_);
    float var = sq * (1.0f/E_) - mean*mean;
    float inv = rsqrtf(var + 1e-5f);
    float* q_ = out + (size_t)row*E_;
    #pragma unroll
    for (int q = 0; q < 4; ++q) {
        int e = t + 128*q;
        float val = (v[q] - mean)*inv*g[e] + b[e];
        q_[e] = val;
        if (SPLIT) {
            __nv_bfloat16 hi, lo; split2(val, hi, lo);
            size_t o = (size_t)row*E_ + e;
            ohi[o] = hi; olo[o] = lo;
        }
    }
}

// ================= launch =================
#define GEMM_MMA_SMEM (2*GSTAGE_B)

extern "C" void kernel_launch(void* const* d_in, const int* in_sizes, int n_in,
                              void* d_out, int out_size)
{
    const float* x       = (const float*)d_in[0];
    const float* W_first = (const float*)d_in[1];
    const float* b_first = (const float*)d_in[2];
    const float* pos_emb = (const float*)d_in[3];
    const float* Wq      = (const float*)d_in[4];
    const float* bq      = (const float*)d_in[5];
    const float* Wk      = (const float*)d_in[6];
    const float* bk      = (const float*)d_in[7];
    const float* Wv      = (const float*)d_in[8];
    const float* bv      = (const float*)d_in[9];
    const float* Wo      = (const float*)d_in[10];
    const float* bo      = (const float*)d_in[11];
    const float* g1      = (const float*)d_in[12];
    const float* be1     = (const float*)d_in[13];
    const float* Wf1     = (const float*)d_in[14];
    const float* bf1     = (const float*)d_in[15];
    const float* Wf2     = (const float*)d_in[16];
    const float* bf2     = (const float*)d_in[17];
    const float* g2      = (const float*)d_in[18];
    const float* be2     = (const float*)d_in[19];
    const float* Wfin    = (const float*)d_in[20];
    const float* bfin    = (const float*)d_in[21];
    (void)in_sizes; (void)n_in; (void)out_size;

    cudaFuncSetAttribute(gemm_mma<0,1,0>, cudaFuncAttributeMaxDynamicSharedMemorySize, GEMM_MMA_SMEM);
    cudaFuncSetAttribute(gemm_mma<1,0,1>, cudaFuncAttributeMaxDynamicSharedMemorySize, GEMM_MMA_SMEM);

    float *h_p, *buf_p, *hx_p;
    cudaGetSymbolAddress((void**)&h_p,   g_h);
    cudaGetSymbolAddress((void**)&buf_p, g_buf);
    cudaGetSymbolAddress((void**)&hx_p,  g_hx);
    __nv_bfloat16 *attnhi, *attnlo, *hxhi, *hxlo, *ffhi, *fflo;
    __nv_bfloat16 *wothi, *wotlo, *wf1thi, *wf1tlo, *wf2thi, *wf2tlo;
    cudaGetSymbolAddress((void**)&attnhi, g_attnhi);
    cudaGetSymbolAddress((void**)&attnlo, g_attnlo);
    cudaGetSymbolAddress((void**)&hxhi,   g_hxhi);
    cudaGetSymbolAddress((void**)&hxlo,   g_hxlo);
    cudaGetSymbolAddress((void**)&ffhi,   g_ffhi);
    cudaGetSymbolAddress((void**)&fflo,   g_fflo);
    cudaGetSymbolAddress((void**)&wothi,  g_wothi);
    cudaGetSymbolAddress((void**)&wotlo,  g_wotlo);
    cudaGetSymbolAddress((void**)&wf1thi, g_wf1thi);
    cudaGetSymbolAddress((void**)&wf1tlo, g_wf1tlo);
    cudaGetSymbolAddress((void**)&wf2thi, g_wf2thi);
    cudaGetSymbolAddress((void**)&wf2tlo, g_wf2tlo);

    // weight prep: transpose + bf16 split (all layers)
    wsplit_kernel<<<dim3(E_/32,  E_/32,  L_), dim3(32,8)>>>(Wo,  wothi,  wotlo,  E_,  E_);
    wsplit_kernel<<<dim3(FF_/32, E_/32,  L_), dim3(32,8)>>>(Wf1, wf1thi, wf1tlo, E_,  FF_);
    wsplit_kernel<<<dim3(E_/32,  FF_/32, L_), dim3(32,8)>>>(Wf2, wf2thi, wf2tlo, FF_, E_);

    embed_kernel<<<NS_, 512>>>(x, W_first, b_first, pos_emb);

    for (int i = 0; i < L_; ++i) {
        qkv_kernel<<<NS_/4, 512>>>(Wq + i*HD_*HD_, bq + i*HD_,
                                   Wk + i*HD_*HD_, bk + i*HD_,
                                   Wv + i*HD_*HD_, bv + i*HD_);
        attn_kernel<<<N_*H_*(S_/64), 256>>>();

        // Wo GEMM: buf = attn @ Wo + bo + h   (tensor core)
        gemm_mma<0,1,0><<<dim3(E_/128, NS_/128), 256, GEMM_MMA_SMEM>>>(
            attnhi, attnlo,
            wothi + (size_t)i*E_*E_, wotlo + (size_t)i*E_*E_,
            bo + i*E_, h_p, buf_p, (__nv_bfloat16*)0, (__nv_bfloat16*)0, E_, E_);
        ln_kernel<1><<<NS_, 128>>>(buf_p, hx_p, g1 + i*E_, be1 + i*E_, hxhi, hxlo);

        // FF1: ff = relu(hx @ Wf1 + bf1), split output only
        gemm_mma<1,0,1><<<dim3(FF_/128, NS_/128), 256, GEMM_MMA_SMEM>>>(
            hxhi, hxlo,
            wf1thi + (size_t)i*(size_t)E_*FF_, wf1tlo + (size_t)i*(size_t)E_*FF_,
            bf1 + i*FF_, (const float*)0, (float*)0, ffhi, fflo, FF_, E_);

        // FF2: buf = ff @ Wf2 + bf2 + hx
        gemm_mma<0,1,0><<<dim3(E_/128, NS_/128), 256, GEMM_MMA_SMEM>>>(
            ffhi, fflo,
            wf2thi + (size_t)i*(size_t)FF_*E_, wf2tlo + (size_t)i*(size_t)FF_*E_,
            bf2 + i*E_, hx_p, buf_p, (__nv_bfloat16*)0, (__nv_bfloat16*)0, E_, FF_);
        ln_kernel<0><<<NS_, 128>>>(buf_p, h_p, g2 + i*E_, be2 + i*E_,
                                   (__nv_bfloat16*)0, (__nv_bfloat16*)0);
    }

    // final pointwise conv: out[n,o,s] = h @ Wfin + bfin
    gemm_kernel<1><<<dim3(O_/64, NS_/64), 256>>>(
        h_p, Wfin, bfin, (float*)d_out, NS_, O_, E_);
}

// round 7
// speedup vs baseline: 2.9864x; 1.4051x over previous
#include <cuda_runtime.h>
#include <cuda_bf16.h>
#include <math.h>
#include <stdint.h>

#define N_ 8
#define S_ 1024
#define F_ 64
#define E_ 512
#define H_ 8
#define HD_ 64
#define O_ 64
#define L_ 6
#define FF_ 2048
#define NS_ (N_*S_)

// ---------------- scratch (no allocations allowed) ----------------
__device__ float g_h[NS_*E_];       // running hidden state (n,s,e)
__device__ float g_buf[NS_*E_];     // pre-LN sum
__device__ float g_hx[NS_*E_];      // post-LN1 (fp32 residual for FF2)
__device__ float g_xt[NS_*F_];      // transposed input (n,s,f)

// bf16 split q/k/v in (n,h,s,d)
__device__ __nv_bfloat16 g_qhi[NS_*E_], g_qlo[NS_*E_];
__device__ __nv_bfloat16 g_khi[NS_*E_], g_klo[NS_*E_];
__device__ __nv_bfloat16 g_vhi[NS_*E_], g_vlo[NS_*E_];

// bf16 split activations
__device__ __nv_bfloat16 g_attnhi[NS_*E_], g_attnlo[NS_*E_];
__device__ __nv_bfloat16 g_hxhi[NS_*E_],   g_hxlo[NS_*E_];
__device__ __nv_bfloat16 g_ffhi[NS_*FF_],  g_fflo[NS_*FF_];

// bf16 split transposed weights  Wt[n][k]
__device__ __nv_bfloat16 g_wothi[L_*E_*E_],   g_wotlo[L_*E_*E_];
__device__ __nv_bfloat16 g_wf1thi[L_*E_*FF_], g_wf1tlo[L_*E_*FF_];
__device__ __nv_bfloat16 g_wf2thi[L_*FF_*E_], g_wf2tlo[L_*FF_*E_];

// ================= helpers =================
static __device__ __forceinline__ uint32_t smem_u32(const void* p){
    uint32_t a;
    asm("{ .reg .u64 t; cvta.to.shared.u64 t, %1; cvt.u32.u64 %0, t; }" : "=r"(a) : "l"(p));
    return a;
}
static __device__ __forceinline__ void cp16(uint32_t dst, const void* src){
    asm volatile("cp.async.cg.shared.global [%0], [%1], 16;" :: "r"(dst), "l"(src));
}
#define CP_COMMIT() asm volatile("cp.async.commit_group;" ::: "memory")
#define CP_WAIT1()  asm volatile("cp.async.wait_group 1;" ::: "memory")
#define CP_WAIT0()  asm volatile("cp.async.wait_group 0;" ::: "memory")

static __device__ __forceinline__ void mma16816(
    float* d, const uint32_t* a, uint32_t b0, uint32_t b1)
{
    asm volatile("mma.sync.aligned.m16n8k16.row.col.f32.bf16.bf16.f32 "
        "{%0,%1,%2,%3}, {%4,%5,%6,%7}, {%8,%9}, {%0,%1,%2,%3};"
        : "+f"(d[0]), "+f"(d[1]), "+f"(d[2]), "+f"(d[3])
        : "r"(a[0]), "r"(a[1]), "r"(a[2]), "r"(a[3]), "r"(b0), "r"(b1));
}

static __device__ __forceinline__ void split2(float v, __nv_bfloat16& hi, __nv_bfloat16& lo){
    hi = __float2bfloat16(v);
    lo = __float2bfloat16(v - __bfloat162float(hi));
}
static __device__ __forceinline__ uint32_t pack2(float a, float b){
    __nv_bfloat162 t(__float2bfloat16(a), __float2bfloat16(b));
    return *(uint32_t*)&t;
}
static __device__ __forceinline__ uint32_t pack2lo(float a, float b){
    float ah = __bfloat162float(__float2bfloat16(a));
    float bh = __bfloat162float(__float2bfloat16(b));
    __nv_bfloat162 t(__float2bfloat16(a - ah), __float2bfloat16(b - bh));
    return *(uint32_t*)&t;
}

// fast exp on fma/alu pipes (no MUFU): exp2 range reduction + deg-5 Taylor
static __device__ __forceinline__ float fexp(float x){
    x = fmaxf(x, -87.0f);
    float t = x * 1.4426950408889634f;
    float z = t + 12582912.0f;                    // round to nearest int
    int   i = __float_as_int(z) - 0x4B400000;
    float f = t - (z - 12582912.0f);              // f in [-0.5, 0.5]
    float xf = f * 0.6931471805599453f;
    float p = fmaf(xf, 0.0083333333f, 0.0416666667f);
    p = fmaf(xf, p, 0.1666666667f);
    p = fmaf(xf, p, 0.5f);
    p = fmaf(xf, p, 1.0f);
    p = fmaf(xf, p, 1.0f);
    return p * __int_as_float((i + 127) << 23);
}

// ================= x transpose: x[n][f][s] -> xt[n][s][f] =================
__global__ __launch_bounds__(256) void xt_kernel(const float* __restrict__ x)
{
    __shared__ float t[32][33];
    int n = blockIdx.z;
    int s0 = blockIdx.x * 32, f0 = blockIdx.y * 32;
    int tx = threadIdx.x, ty = threadIdx.y;
    for (int y = ty; y < 32; y += 8)
        t[y][tx] = x[(size_t)n*F_*S_ + (size_t)(f0 + y)*S_ + s0 + tx];
    __syncthreads();
    for (int y = ty; y < 32; y += 8)
        g_xt[((size_t)n*S_ + s0 + y)*F_ + f0 + tx] = t[tx][y];
}

// ================= kernel 1: embed =================
__global__ __launch_bounds__(512) void embed_kernel(
    const float* __restrict__ W,
    const float* __restrict__ b, const float* __restrict__ pos)
{
    int ns = blockIdx.x;
    int s = ns & (S_-1);
    int e = threadIdx.x;
    __shared__ float xs[F_];
    if (e < F_) xs[e] = g_xt[(size_t)ns*F_ + e];
    __syncthreads();
    float acc = b[e];
    #pragma unroll 16
    for (int f = 0; f < F_; ++f)
        acc = fmaf(xs[f], W[f*E_ + e], acc);
    acc = fmaxf(acc, 0.0f) + pos[s*E_ + e];
    g_h[(size_t)ns*E_ + e] = acc;
}

// ================= kernel 2: QKV projection -> split bf16 (n,h,s,d) =================
__global__ __launch_bounds__(512) void qkv_kernel(
    const float* __restrict__ Wq, const float* __restrict__ bq,
    const float* __restrict__ Wk, const float* __restrict__ bk,
    const float* __restrict__ Wv, const float* __restrict__ bv)
{
    int ns0 = blockIdx.x * 4;
    int t = threadIdx.x;
    int hh = t >> 6, dp = t & 63;
    __shared__ float hs[4][E_];
    #pragma unroll
    for (int r = 0; r < 4; ++r)
        hs[r][t] = g_h[(size_t)(ns0 + r)*E_ + t];
    __syncthreads();
    float aq[4], ak[4], av[4];
    float bqv = bq[dp], bkv = bk[dp], bvv = bv[dp];
    #pragma unroll
    for (int r = 0; r < 4; ++r) { aq[r]=bqv; ak[r]=bkv; av[r]=bvv; }
    #pragma unroll 4
    for (int d = 0; d < HD_; ++d) {
        float wq = Wq[d*HD_+dp], wk = Wk[d*HD_+dp], wv = Wv[d*HD_+dp];
        #pragma unroll
        for (int r = 0; r < 4; ++r) {
            float hv = hs[r][hh*HD_ + d];
            aq[r] = fmaf(hv, wq, aq[r]);
            ak[r] = fmaf(hv, wk, ak[r]);
            av[r] = fmaf(hv, wv, av[r]);
        }
    }
    #pragma unroll
    for (int r = 0; r < 4; ++r) {
        int ns = ns0 + r;
        int n = ns >> 10, s = ns & (S_-1);
        size_t o = ((size_t)(n*H_ + hh)*S_ + s)*HD_ + dp;
        __nv_bfloat16 hi, lo;
        split2(aq[r], hi, lo); g_qhi[o] = hi; g_qlo[o] = lo;
        split2(ak[r], hi, lo); g_khi[o] = hi; g_klo[o] = lo;
        split2(av[r], hi, lo); g_vhi[o] = hi; g_vlo[o] = lo;
    }
}

// ================= kernel 3: flash attention on tensor cores =================
// block = 256 threads (8 warps), one (n,h), q-tile 128 (warp owns 16 rows).
// K tile 64 keys. QK^T and PV via mma.sync with hi/lo split; online softmax in frags.
#define KPAD 72
__global__ __launch_bounds__(256) void attn_kernel()
{
    __shared__ __nv_bfloat16 sKhi[64*KPAD], sKlo[64*KPAD];
    __shared__ __nv_bfloat16 sVthi[64*KPAD], sVtlo[64*KPAD];

    int bid = blockIdx.x;
    int qt = bid & 7;              // 8 q-tiles of 128
    int nh = bid >> 3;
    int tid = threadIdx.x;
    int warp = tid >> 5, lane = tid & 31;
    int lr = lane >> 2, lc2 = (lane & 3) * 2;
    const float isc = 0.044194173824159216f;   // 1/sqrt(E)

    size_t qkv_base = (size_t)nh * S_ * HD_;
    int qrow0 = qt*128 + warp*16;

    // Q fragments (hi/lo), loaded once from global
    uint32_t qh[4][4], ql[4][4];
    #pragma unroll
    for (int ks = 0; ks < 4; ++ks) {
        int d = ks*16 + lc2;
        size_t r0 = qkv_base + (size_t)(qrow0 + lr)*HD_;
        size_t r1 = qkv_base + (size_t)(qrow0 + lr + 8)*HD_;
        qh[ks][0] = *(const uint32_t*)(g_qhi + r0 + d);
        qh[ks][1] = *(const uint32_t*)(g_qhi + r1 + d);
        qh[ks][2] = *(const uint32_t*)(g_qhi + r0 + d + 8);
        qh[ks][3] = *(const uint32_t*)(g_qhi + r1 + d + 8);
        ql[ks][0] = *(const uint32_t*)(g_qlo + r0 + d);
        ql[ks][1] = *(const uint32_t*)(g_qlo + r1 + d);
        ql[ks][2] = *(const uint32_t*)(g_qlo + r0 + d + 8);
        ql[ks][3] = *(const uint32_t*)(g_qlo + r1 + d + 8);
    }

    float oacc[8][4];
    #pragma unroll
    for (int dt = 0; dt < 8; ++dt)
        #pragma unroll
        for (int j = 0; j < 4; ++j) oacc[dt][j] = 0.0f;
    float m0 = -1e30f, m1 = -1e30f, l0 = 0.0f, l1 = 0.0f;

    for (int kt = 0; kt < 16; ++kt) {
        __syncthreads();   // previous iteration's reads done
        // load K tile (hi/lo): 64 rows x 64 bf16, row-major padded
        {
            #pragma unroll
            for (int i = 0; i < 2; ++i) {
                int id = tid + 256*i;
                int r = id >> 3, c = id & 7;
                size_t g = qkv_base + (size_t)(kt*64 + r)*HD_ + c*8;
                *(float4*)&sKhi[r*KPAD + c*8] = *(const float4*)(g_khi + g);
                *(float4*)&sKlo[r*KPAD + c*8] = *(const float4*)(g_klo + g);
            }
        }
        // load + transpose V tile: sVt[d][k]
        {
            int k = tid >> 2, dg = (tid & 3) * 16;
            size_t g = qkv_base + (size_t)(kt*64 + k)*HD_ + dg;
            #pragma unroll
            for (int j = 0; j < 8; ++j) {
                uint32_t vh = *(const uint32_t*)(g_vhi + g + 2*j);
                uint32_t vl = *(const uint32_t*)(g_vlo + g + 2*j);
                __nv_bfloat162 h2 = *(__nv_bfloat162*)&vh;
                __nv_bfloat162 l2 = *(__nv_bfloat162*)&vl;
                sVthi[(dg + 2*j)*KPAD + k]     = h2.x;
                sVthi[(dg + 2*j + 1)*KPAD + k] = h2.y;
                sVtlo[(dg + 2*j)*KPAD + k]     = l2.x;
                sVtlo[(dg + 2*j + 1)*KPAD + k] = l2.y;
            }
        }
        __syncthreads();

        // S = Q K^T  (16 x 64 per warp, fp32 accum)
        float sacc[8][4];
        #pragma unroll
        for (int nt = 0; nt < 8; ++nt)
            #pragma unroll
            for (int j = 0; j < 4; ++j) sacc[nt][j] = 0.0f;
        #pragma unroll
        for (int ks = 0; ks < 4; ++ks) {
            #pragma unroll
            for (int nt = 0; nt < 8; ++nt) {
                int roff = (nt*8 + lr)*KPAD + ks*16 + lc2;
                uint32_t kh0 = *(const uint32_t*)&sKhi[roff];
                uint32_t kh1 = *(const uint32_t*)&sKhi[roff + 8];
                uint32_t kl0 = *(const uint32_t*)&sKlo[roff];
                uint32_t kl1 = *(const uint32_t*)&sKlo[roff + 8];
                mma16816(sacc[nt], qh[ks], kh0, kh1);
                mma16816(sacc[nt], ql[ks], kh0, kh1);
                mma16816(sacc[nt], qh[ks], kl0, kl1);
            }
        }

        // online softmax (rows lr and lr+8; a row lives in 4 consecutive lanes)
        #pragma unroll
        for (int nt = 0; nt < 8; ++nt)
            #pragma unroll
            for (int j = 0; j < 4; ++j) sacc[nt][j] *= isc;

        float mx0 = -1e30f, mx1 = -1e30f;
        #pragma unroll
        for (int nt = 0; nt < 8; ++nt) {
            mx0 = fmaxf(mx0, fmaxf(sacc[nt][0], sacc[nt][1]));
            mx1 = fmaxf(mx1, fmaxf(sacc[nt][2], sacc[nt][3]));
        }
        mx0 = fmaxf(mx0, __shfl_xor_sync(0xffffffffu, mx0, 1));
        mx0 = fmaxf(mx0, __shfl_xor_sync(0xffffffffu, mx0, 2));
        mx1 = fmaxf(mx1, __shfl_xor_sync(0xffffffffu, mx1, 1));
        mx1 = fmaxf(mx1, __shfl_xor_sync(0xffffffffu, mx1, 2));
        float mn0 = fmaxf(m0, mx0), mn1 = fmaxf(m1, mx1);
        float al0 = fexp(m0 - mn0), al1 = fexp(m1 - mn1);
        m0 = mn0; m1 = mn1;

        uint32_t pah[4][4], pal[4][4];
        float ls0 = 0.0f, ls1 = 0.0f;
        #pragma unroll
        for (int nt = 0; nt < 8; ++nt) {
            float p0 = fexp(sacc[nt][0] - mn0);
            float p1 = fexp(sacc[nt][1] - mn0);
            float p2 = fexp(sacc[nt][2] - mn1);
            float p3 = fexp(sacc[nt][3] - mn1);
            ls0 += p0 + p1; ls1 += p2 + p3;
            int ks = nt >> 1, hf = (nt & 1) * 2;
            pah[ks][hf+0] = pack2(p0, p1);
            pah[ks][hf+1] = pack2(p2, p3);
            pal[ks][hf+0] = pack2lo(p0, p1);
            pal[ks][hf+1] = pack2lo(p2, p3);
        }
        ls0 += __shfl_xor_sync(0xffffffffu, ls0, 1);
        ls0 += __shfl_xor_sync(0xffffffffu, ls0, 2);
        ls1 += __shfl_xor_sync(0xffffffffu, ls1, 1);
        ls1 += __shfl_xor_sync(0xffffffffu, ls1, 2);
        l0 = l0*al0 + ls0; l1 = l1*al1 + ls1;
        #pragma unroll
        for (int dt = 0; dt < 8; ++dt) {
            oacc[dt][0] *= al0; oacc[dt][1] *= al0;
            oacc[dt][2] *= al1; oacc[dt][3] *= al1;
        }

        // wait: pa a-frags need fixing: a-frag order is {row lr k0-1, row lr+8 k0-1, row lr k8-9, row lr+8 k8-9}
        // our mapping above: pah[ks] = {(2ks:p0,p1), (2ks:p2,p3), (2ks+1:p0,p1), (2ks+1:p2,p3)} which is exactly
        // {row lr keys ks*16+lc2..+1, row lr+8 same, row lr keys ks*16+8+lc2..+1, row lr+8 same} -- correct.

        // O += P V
        #pragma unroll
        for (int ks = 0; ks < 4; ++ks) {
            #pragma unroll
            for (int dt = 0; dt < 8; ++dt) {
                int roff = (dt*8 + lr)*KPAD + ks*16 + lc2;
                uint32_t vh0 = *(const uint32_t*)&sVthi[roff];
                uint32_t vh1 = *(const uint32_t*)&sVthi[roff + 8];
                uint32_t vl0 = *(const uint32_t*)&sVtlo[roff];
                uint32_t vl1 = *(const uint32_t*)&sVtlo[roff + 8];
                mma16816(oacc[dt], pah[ks], vh0, vh1);
                mma16816(oacc[dt], pal[ks], vh0, vh1);
                mma16816(oacc[dt], pah[ks], vl0, vl1);
            }
        }
    }

    // epilogue: write split bf16 attention output (n,s,e)
    float inv0 = 1.0f / l0, inv1 = 1.0f / l1;
    int n = nh >> 3, hh = nh & 7;
    int row0 = qt*128 + warp*16 + lr;
    size_t b0 = ((size_t)n*S_ + row0)*E_ + hh*HD_;
    size_t b1 = b0 + (size_t)8*E_;
    #pragma unroll
    for (int dt = 0; dt < 8; ++dt) {
        int e = dt*8 + lc2;
        float v0 = oacc[dt][0]*inv0, v1 = oacc[dt][1]*inv0;
        float v2 = oacc[dt][2]*inv1, v3 = oacc[dt][3]*inv1;
        *(uint32_t*)(g_attnhi + b0 + e) = pack2(v0, v1);
        *(uint32_t*)(g_attnlo + b0 + e) = pack2lo(v0, v1);
        *(uint32_t*)(g_attnhi + b1 + e) = pack2(v2, v3);
        *(uint32_t*)(g_attnlo + b1 + e) = pack2lo(v2, v3);
    }
}

// ================= weight transpose + split =================
__global__ __launch_bounds__(256) void wsplit_kernel(
    const float* __restrict__ W, __nv_bfloat16* __restrict__ hi,
    __nv_bfloat16* __restrict__ lo, int K, int N)
{
    __shared__ float t[32][33];
    size_t lstr = (size_t)K*N*blockIdx.z;
    const float* Wl = W + lstr;
    __nv_bfloat16* hil = hi + lstr;
    __nv_bfloat16* lol = lo + lstr;
    int kb = blockIdx.y*32, nb = blockIdx.x*32;
    int x = threadIdx.x, y0 = threadIdx.y;
    for (int y = y0; y < 32; y += 8)
        t[y][x] = Wl[(size_t)(kb+y)*N + nb + x];
    __syncthreads();
    for (int y = y0; y < 32; y += 8) {
        float v = t[x][y];
        __nv_bfloat16 h, l2; split2(v, h, l2);
        size_t o = (size_t)(nb+y)*K + kb + x;
        hil[o] = h; lol[o] = l2;
    }
}

// ================= mma.sync GEMM (unchanged from R6) =================
#define GSTAGE_B 40960
#define GARR_B   10240

static __device__ __forceinline__ void mma_load_stage(
    uint32_t sbase, int st,
    const __nv_bfloat16* __restrict__ Ahi, const __nv_bfloat16* __restrict__ Alo,
    const __nv_bfloat16* __restrict__ Bhi, const __nv_bfloat16* __restrict__ Blo,
    int m0, int n0, int k0, int K, int tid)
{
    uint32_t s0 = sbase + st*GSTAGE_B;
    #pragma unroll
    for (int i = 0; i < 2; ++i) {
        int id = tid + i*256;
        int r = id >> 2, c = id & 3;
        uint32_t off = (uint32_t)(r*80 + c*16);
        size_t ga = (size_t)(m0 + r)*K + k0 + c*8;
        size_t gb = (size_t)(n0 + r)*K + k0 + c*8;
        cp16(s0 +            off, Ahi + ga);
        cp16(s0 +   GARR_B + off, Alo + ga);
        cp16(s0 + 2*GARR_B + off, Bhi + gb);
        cp16(s0 + 3*GARR_B + off, Blo + gb);
    }
    CP_COMMIT();
}

template<int RELU, int RESID, int SPLITOUT>
__global__ __launch_bounds__(256) void gemm_mma(
    const __nv_bfloat16* __restrict__ Ahi, const __nv_bfloat16* __restrict__ Alo,
    const __nv_bfloat16* __restrict__ Bhi, const __nv_bfloat16* __restrict__ Blo,
    const float* __restrict__ bias, const float* __restrict__ Rres,
    float* __restrict__ Cf, __nv_bfloat16* __restrict__ Chi, __nv_bfloat16* __restrict__ Clo,
    int Nn, int K)
{
    extern __shared__ __nv_bfloat16 sm[];
    uint32_t sbase = smem_u32(sm);
    int tid = threadIdx.x;
    int warp = tid >> 5, lane = tid & 31;
    int m0 = blockIdx.y * 128, n0 = blockIdx.x * 128;
    int wm0 = (warp & 3) * 32, wn0 = (warp >> 2) * 64;
    int lr = lane >> 2, lc2 = (lane & 3) * 2;

    float acc[2][8][4];
    #pragma unroll
    for (int a = 0; a < 2; ++a)
        #pragma unroll
        for (int b = 0; b < 8; ++b)
            #pragma unroll
            for (int c = 0; c < 4; ++c) acc[a][b][c] = 0.0f;

    int NKB = K >> 5;

    mma_load_stage(sbase, 0, Ahi, Alo, Bhi, Blo, m0, n0, 0,  K, tid);
    mma_load_stage(sbase, 1, Ahi, Alo, Bhi, Blo, m0, n0, 32, K, tid);

    for (int kb = 0; kb < NKB; ++kb) {
        int st = kb & 1;
        if (kb == NKB-1) { CP_WAIT0(); } else { CP_WAIT1(); }
        __syncthreads();

        const __nv_bfloat16* sA  = sm + st*(GSTAGE_B/2);
        const __nv_bfloat16* sAl = sA + GARR_B/2;
        const __nv_bfloat16* sB  = sA + 2*(GARR_B/2);
        const __nv_bfloat16* sBl = sA + 3*(GARR_B/2);

        #pragma unroll
        for (int ks = 0; ks < 2; ++ks) {
            int kk = ks*16 + lc2;
            uint32_t ahi[2][4], alo[2][4];
            #pragma unroll
            for (int mt = 0; mt < 2; ++mt) {
                int r = wm0 + mt*16 + lr;
                ahi[mt][0] = *(const uint32_t*)(sA  + r*40 + kk);
                ahi[mt][1] = *(const uint32_t*)(sA  + (r+8)*40 + kk);
                ahi[mt][2] = *(const uint32_t*)(sA  + r*40 + kk + 8);
                ahi[mt][3] = *(const uint32_t*)(sA  + (r+8)*40 + kk + 8);
                alo[mt][0] = *(const uint32_t*)(sAl + r*40 + kk);
                alo[mt][1] = *(const uint32_t*)(sAl + (r+8)*40 + kk);
                alo[mt][2] = *(const uint32_t*)(sAl + r*40 + kk + 8);
                alo[mt][3] = *(const uint32_t*)(sAl + (r+8)*40 + kk + 8);
            }
            #pragma unroll
            for (int nt = 0; nt < 8; ++nt) {
                int n = wn0 + nt*8 + lr;
                uint32_t bh0 = *(const uint32_t*)(sB  + n*40 + kk);
                uint32_t bh1 = *(const uint32_t*)(sB  + n*40 + kk + 8);
                uint32_t bl0 = *(const uint32_t*)(sBl + n*40 + kk);
                uint32_t bl1 = *(const uint32_t*)(sBl + n*40 + kk + 8);
                #pragma unroll
                for (int mt = 0; mt < 2; ++mt) {
                    mma16816(acc[mt][nt], ahi[mt], bh0, bh1);
                    mma16816(acc[mt][nt], alo[mt], bh0, bh1);
                    mma16816(acc[mt][nt], ahi[mt], bl0, bl1);
                }
            }
        }
        __syncthreads();
        if (kb + 2 < NKB)
            mma_load_stage(sbase, st, Ahi, Alo, Bhi, Blo, m0, n0, (kb+2)*32, K, tid);
    }

    #pragma unroll
    for (int mt = 0; mt < 2; ++mt) {
        #pragma unroll
        for (int half = 0; half < 2; ++half) {
            int m = m0 + wm0 + mt*16 + half*8 + lr;
            #pragma unroll
            for (int nt = 0; nt < 8; ++nt) {
                int c0 = n0 + wn0 + nt*8 + lc2;
                float2 bi = *(const float2*)(bias + c0);
                float v0 = acc[mt][nt][half*2+0] + bi.x;
                float v1 = acc[mt][nt][half*2+1] + bi.y;
                if (RESID) {
                    float2 rr = *(const float2*)(Rres + (size_t)m*Nn + c0);
                    v0 += rr.x; v1 += rr.y;
                }
                if (RELU) { v0 = fmaxf(v0, 0.f); v1 = fmaxf(v1, 0.f); }
                if (SPLITOUT) {
                    *(uint32_t*)(Chi + (size_t)m*Nn + c0) = pack2(v0, v1);
                    *(uint32_t*)(Clo + (size_t)m*Nn + c0) = pack2lo(v0, v1);
                } else {
                    *(float2*)(Cf + (size_t)m*Nn + c0) = make_float2(v0, v1);
                }
            }
        }
    }
}

// ================= small SIMT GEMM (final conv, N=64) =================
template<int FINAL>
__global__ __launch_bounds__(256) void gemm_kernel(
    const float* __restrict__ A, const float* __restrict__ B,
    const float* __restrict__ bias, float* __restrict__ C,
    int M, int Nn, int K)
{
    __shared__ float As[16][65];
    __shared__ float Bs[16][64];
    int m0 = blockIdx.y * 64, n0 = blockIdx.x * 64;
    int tid = threadIdx.x;
    int tx = tid & 15, ty = tid >> 4;

    int ar = tid >> 2;
    int ac = (tid & 3) * 4;
    int br = tid >> 4;
    int bc = (tid & 15) * 4;
    const float* Ap = A + (size_t)(m0 + ar)*K + ac;
    const float* Bp = B + (size_t)br*Nn + n0 + bc;

    float acc[4][4] = {};
    for (int k0 = 0; k0 < K; k0 += 16) {
        float4 a4 = *(const float4*)(Ap + k0);
        float4 b4 = *(const float4*)(Bp + (size_t)k0*Nn);
        As[ac+0][ar]=a4.x; As[ac+1][ar]=a4.y; As[ac+2][ar]=a4.z; As[ac+3][ar]=a4.w;
        *(float4*)&Bs[br][bc] = b4;
        __syncthreads();
        #pragma unroll
        for (int kk = 0; kk < 16; ++kk) {
            float a[4], b[4];
            #pragma unroll
            for (int i = 0; i < 4; ++i) a[i] = As[kk][ty + 16*i];
            #pragma unroll
            for (int j = 0; j < 4; ++j) b[j] = Bs[kk][tx + 16*j];
            #pragma unroll
            for (int i = 0; i < 4; ++i)
                #pragma unroll
                for (int j = 0; j < 4; ++j)
                    acc[i][j] = fmaf(a[i], b[j], acc[i][j]);
        }
        __syncthreads();
    }
    #pragma unroll
    for (int i = 0; i < 4; ++i) {
        int mrow = m0 + ty + 16*i;
        #pragma unroll
        for (int j = 0; j < 4; ++j) {
            int nn = n0 + tx + 16*j;
            float v = acc[i][j] + bias[nn];
            if (FINAL) {
                C[((size_t)(mrow >> 10)*O_ + nn)*S_ + (mrow & (S_-1))] = v;
            } else {
                C[(size_t)mrow*Nn + nn] = v;
            }
        }
    }
}

// ================= layernorm (optional split output) =================
template<int SPLIT>
__global__ __launch_bounds__(128) void ln_kernel(
    const float* __restrict__ in, float* __restrict__ out,
    const float* __restrict__ g, const float* __restrict__ b,
    __nv_bfloat16* __restrict__ ohi, __nv_bfloat16* __restrict__ olo)
{
    int row = blockIdx.x;
    int t = threadIdx.x;
    const float* p = in + (size_t)row*E_;
    float v[4], s = 0.0f, sq = 0.0f;
    #pragma unroll
    for (int q = 0; q < 4; ++q) {
        v[q] = p[t + 128*q];
        s += v[q]; sq += v[q]*v[q];
    }
    #pragma unroll
    for (int off = 16; off; off >>= 1) {
        s  += __shfl_xor_sync(0xffffffffu, s,  off);
        sq += __shfl_xor_sync(0xffffffffu, sq, off);
    }
    __shared__ float red[2][4];
    int w = t >> 5;
    if ((t & 31) == 0) { red[0][w] = s; red[1][w] = sq; }
    __syncthreads();
    s  = red[0][0] + red[0][1] + red[0][2] + red[0][3];
    sq = red[1][0] + red[1][1] + red[1][2] + red[1][3];
    float mean = s * (1.0f/E_);
    float var = sq * (1.0f/E_) - mean*mean;
    float inv = rsqrtf(var + 1e-5f);
    float* q_ = out + (size_t)row*E_;
    #pragma unroll
    for (int q = 0; q < 4; ++q) {
        int e = t + 128*q;
        float val = (v[q] - mean)*inv*g[e] + b[e];
        q_[e] = val;
        if (SPLIT) {
            __nv_bfloat16 hi, lo; split2(val, hi, lo);
            size_t o = (size_t)row*E_ + e;
            ohi[o] = hi; olo[o] = lo;
        }
    }
}

// ================= launch =================
#define GEMM_MMA_SMEM (2*GSTAGE_B)

extern "C" void kernel_launch(void* const* d_in, const int* in_sizes, int n_in,
                              void* d_out, int out_size)
{
    const float* x       = (const float*)d_in[0];
    const float* W_first = (const float*)d_in[1];
    const float* b_first = (const float*)d_in[2];
    const float* pos_emb = (const float*)d_in[3];
    const float* Wq      = (const float*)d_in[4];
    const float* bq      = (const float*)d_in[5];
    const float* Wk      = (const float*)d_in[6];
    const float* bk      = (const float*)d_in[7];
    const float* Wv      = (const float*)d_in[8];
    const float* bv      = (const float*)d_in[9];
    const float* Wo      = (const float*)d_in[10];
    const float* bo      = (const float*)d_in[11];
    const float* g1      = (const float*)d_in[12];
    const float* be1     = (const float*)d_in[13];
    const float* Wf1     = (const float*)d_in[14];
    const float* bf1     = (const float*)d_in[15];
    const float* Wf2     = (const float*)d_in[16];
    const float* bf2     = (const float*)d_in[17];
    const float* g2      = (const float*)d_in[18];
    const float* be2     = (const float*)d_in[19];
    const float* Wfin    = (const float*)d_in[20];
    const float* bfin    = (const float*)d_in[21];
    (void)in_sizes; (void)n_in; (void)out_size;

    cudaFuncSetAttribute(gemm_mma<0,1,0>, cudaFuncAttributeMaxDynamicSharedMemorySize, GEMM_MMA_SMEM);
    cudaFuncSetAttribute(gemm_mma<1,0,1>, cudaFuncAttributeMaxDynamicSharedMemorySize, GEMM_MMA_SMEM);

    float *h_p, *buf_p, *hx_p;
    cudaGetSymbolAddress((void**)&h_p,   g_h);
    cudaGetSymbolAddress((void**)&buf_p, g_buf);
    cudaGetSymbolAddress((void**)&hx_p,  g_hx);
    __nv_bfloat16 *attnhi, *attnlo, *hxhi, *hxlo, *ffhi, *fflo;
    __nv_bfloat16 *wothi, *wotlo, *wf1thi, *wf1tlo, *wf2thi, *wf2tlo;
    cudaGetSymbolAddress((void**)&attnhi, g_attnhi);
    cudaGetSymbolAddress((void**)&attnlo, g_attnlo);
    cudaGetSymbolAddress((void**)&hxhi,   g_hxhi);
    cudaGetSymbolAddress((void**)&hxlo,   g_hxlo);
    cudaGetSymbolAddress((void**)&ffhi,   g_ffhi);
    cudaGetSymbolAddress((void**)&fflo,   g_fflo);
    cudaGetSymbolAddress((void**)&wothi,  g_wothi);
    cudaGetSymbolAddress((void**)&wotlo,  g_wotlo);
    cudaGetSymbolAddress((void**)&wf1thi, g_wf1thi);
    cudaGetSymbolAddress((void**)&wf1tlo, g_wf1tlo);
    cudaGetSymbolAddress((void**)&wf2thi, g_wf2thi);
    cudaGetSymbolAddress((void**)&wf2tlo, g_wf2tlo);

    // weight prep: transpose + bf16 split (all layers)
    wsplit_kernel<<<dim3(E_/32,  E_/32,  L_), dim3(32,8)>>>(Wo,  wothi,  wotlo,  E_,  E_);
    wsplit_kernel<<<dim3(FF_/32, E_/32,  L_), dim3(32,8)>>>(Wf1, wf1thi, wf1tlo, E_,  FF_);
    wsplit_kernel<<<dim3(E_/32,  FF_/32, L_), dim3(32,8)>>>(Wf2, wf2thi, wf2tlo, FF_, E_);

    xt_kernel<<<dim3(S_/32, F_/32, N_), dim3(32,8)>>>(x);
    embed_kernel<<<NS_, 512>>>(W_first, b_first, pos_emb);

    for (int i = 0; i < L_; ++i) {
        qkv_kernel<<<NS_/4, 512>>>(Wq + i*HD_*HD_, bq + i*HD_,
                                   Wk + i*HD_*HD_, bk + i*HD_,
                                   Wv + i*HD_*HD_, bv + i*HD_);
        attn_kernel<<<N_*H_*8, 256>>>();

        gemm_mma<0,1,0><<<dim3(E_/128, NS_/128), 256, GEMM_MMA_SMEM>>>(
            attnhi, attnlo,
            wothi + (size_t)i*E_*E_, wotlo + (size_t)i*E_*E_,
            bo + i*E_, h_p, buf_p, (__nv_bfloat16*)0, (__nv_bfloat16*)0, E_, E_);
        ln_kernel<1><<<NS_, 128>>>(buf_p, hx_p, g1 + i*E_, be1 + i*E_, hxhi, hxlo);

        gemm_mma<1,0,1><<<dim3(FF_/128, NS_/128), 256, GEMM_MMA_SMEM>>>(
            hxhi, hxlo,
            wf1thi + (size_t)i*(size_t)E_*FF_, wf1tlo + (size_t)i*(size_t)E_*FF_,
            bf1 + i*FF_, (const float*)0, (float*)0, ffhi, fflo, FF_, E_);

        gemm_mma<0,1,0><<<dim3(E_/128, NS_/128), 256, GEMM_MMA_SMEM>>>(
            ffhi, fflo,
            wf2thi + (size_t)i*(size_t)FF_*E_, wf2tlo + (size_t)i*(size_t)FF_*E_,
            bf2 + i*E_, hx_p, buf_p, (__nv_bfloat16*)0, (__nv_bfloat16*)0, E_, FF_);
        ln_kernel<0><<<NS_, 128>>>(buf_p, h_p, g2 + i*E_, be2 + i*E_,
                                   (__nv_bfloat16*)0, (__nv_bfloat16*)0);
    }

    gemm_kernel<1><<<dim3(O_/64, NS_/64), 256>>>(
        h_p, Wfin, bfin, (float*)d_out, NS_, O_, E_);
}

// round 8
// speedup vs baseline: 3.0612x; 1.0251x over previous
#include <cuda_runtime.h>
#include <cuda_bf16.h>
#include <math.h>
#include <stdint.h>

#define N_ 8
#define S_ 1024
#define F_ 64
#define E_ 512
#define H_ 8
#define HD_ 64
#define O_ 64
#define L_ 6
#define FF_ 2048
#define NS_ (N_*S_)

// ---------------- scratch (no allocations allowed) ----------------
__device__ float g_h[NS_*E_];       // running hidden state (n,s,e)
__device__ float g_buf[NS_*E_];     // pre-LN sum
__device__ float g_hx[NS_*E_];      // post-LN1 (fp32 residual for FF2)
__device__ float g_xt[NS_*F_];      // transposed input (n,s,f)

// bf16 split q/k/v in (n,h,s,d)
__device__ __nv_bfloat16 g_qhi[NS_*E_], g_qlo[NS_*E_];
__device__ __nv_bfloat16 g_khi[NS_*E_], g_klo[NS_*E_];
__device__ __nv_bfloat16 g_vhi[NS_*E_], g_vlo[NS_*E_];

// bf16 split activations
__device__ __nv_bfloat16 g_attnhi[NS_*E_], g_attnlo[NS_*E_];
__device__ __nv_bfloat16 g_hxhi[NS_*E_],   g_hxlo[NS_*E_];
__device__ __nv_bfloat16 g_ffhi[NS_*FF_],  g_fflo[NS_*FF_];

// bf16 split transposed weights  Wt[n][k]
__device__ __nv_bfloat16 g_wothi[L_*E_*E_],   g_wotlo[L_*E_*E_];
__device__ __nv_bfloat16 g_wf1thi[L_*E_*FF_], g_wf1tlo[L_*E_*FF_];
__device__ __nv_bfloat16 g_wf2thi[L_*FF_*E_], g_wf2tlo[L_*FF_*E_];

// ================= helpers =================
static __device__ __forceinline__ uint32_t smem_u32(const void* p){
    uint32_t a;
    asm("{ .reg .u64 t; cvta.to.shared.u64 t, %1; cvt.u32.u64 %0, t; }" : "=r"(a) : "l"(p));
    return a;
}
static __device__ __forceinline__ void cp16(uint32_t dst, const void* src){
    asm volatile("cp.async.cg.shared.global [%0], [%1], 16;" :: "r"(dst), "l"(src));
}
#define CP_COMMIT() asm volatile("cp.async.commit_group;" ::: "memory")
#define CP_WAIT2()  asm volatile("cp.async.wait_group 2;" ::: "memory")

#define LDSM4(r, a) \
    asm volatile("ldmatrix.sync.aligned.m8n8.x4.shared.b16 {%0,%1,%2,%3}, [%4];" \
        : "=r"((r)[0]), "=r"((r)[1]), "=r"((r)[2]), "=r"((r)[3]) : "r"(a))

static __device__ __forceinline__ void mma16816(
    float* d, const uint32_t* a, uint32_t b0, uint32_t b1)
{
    asm volatile("mma.sync.aligned.m16n8k16.row.col.f32.bf16.bf16.f32 "
        "{%0,%1,%2,%3}, {%4,%5,%6,%7}, {%8,%9}, {%0,%1,%2,%3};"
        : "+f"(d[0]), "+f"(d[1]), "+f"(d[2]), "+f"(d[3])
        : "r"(a[0]), "r"(a[1]), "r"(a[2]), "r"(a[3]), "r"(b0), "r"(b1));
}

static __device__ __forceinline__ void split2(float v, __nv_bfloat16& hi, __nv_bfloat16& lo){
    hi = __float2bfloat16(v);
    lo = __float2bfloat16(v - __bfloat162float(hi));
}
static __device__ __forceinline__ uint32_t pack2(float a, float b){
    __nv_bfloat162 t(__float2bfloat16(a), __float2bfloat16(b));
    return *(uint32_t*)&t;
}
static __device__ __forceinline__ uint32_t pack2lo(float a, float b){
    float ah = __bfloat162float(__float2bfloat16(a));
    float bh = __bfloat162float(__float2bfloat16(b));
    __nv_bfloat162 t(__float2bfloat16(a - ah), __float2bfloat16(b - bh));
    return *(uint32_t*)&t;
}

// fast exp on fma/alu pipes (no MUFU)
static __device__ __forceinline__ float fexp(float x){
    x = fmaxf(x, -87.0f);
    float t = x * 1.4426950408889634f;
    float z = t + 12582912.0f;
    int   i = __float_as_int(z) - 0x4B400000;
    float f = t - (z - 12582912.0f);
    float xf = f * 0.6931471805599453f;
    float p = fmaf(xf, 0.0083333333f, 0.0416666667f);
    p = fmaf(xf, p, 0.1666666667f);
    p = fmaf(xf, p, 0.5f);
    p = fmaf(xf, p, 1.0f);
    p = fmaf(xf, p, 1.0f);
    return p * __int_as_float((i + 127) << 23);
}

// ================= x transpose: x[n][f][s] -> xt[n][s][f] =================
__global__ __launch_bounds__(256) void xt_kernel(const float* __restrict__ x)
{
    __shared__ float t[32][33];
    int n = blockIdx.z;
    int s0 = blockIdx.x * 32, f0 = blockIdx.y * 32;
    int tx = threadIdx.x, ty = threadIdx.y;
    for (int y = ty; y < 32; y += 8)
        t[y][tx] = x[(size_t)n*F_*S_ + (size_t)(f0 + y)*S_ + s0 + tx];
    __syncthreads();
    for (int y = ty; y < 32; y += 8)
        g_xt[((size_t)n*S_ + s0 + y)*F_ + f0 + tx] = t[tx][y];
}

// ================= kernel 1: embed =================
__global__ __launch_bounds__(512) void embed_kernel(
    const float* __restrict__ W,
    const float* __restrict__ b, const float* __restrict__ pos)
{
    int ns = blockIdx.x;
    int s = ns & (S_-1);
    int e = threadIdx.x;
    __shared__ float xs[F_];
    if (e < F_) xs[e] = g_xt[(size_t)ns*F_ + e];
    __syncthreads();
    float acc = b[e];
    #pragma unroll 16
    for (int f = 0; f < F_; ++f)
        acc = fmaf(xs[f], W[f*E_ + e], acc);
    acc = fmaxf(acc, 0.0f) + pos[s*E_ + e];
    g_h[(size_t)ns*E_ + e] = acc;
}

// ================= kernel 2: QKV projection -> split bf16 (n,h,s,d) =================
__global__ __launch_bounds__(512) void qkv_kernel(
    const float* __restrict__ Wq, const float* __restrict__ bq,
    const float* __restrict__ Wk, const float* __restrict__ bk,
    const float* __restrict__ Wv, const float* __restrict__ bv)
{
    int ns0 = blockIdx.x * 4;
    int t = threadIdx.x;
    int hh = t >> 6, dp = t & 63;
    __shared__ float hs[4][E_];
    #pragma unroll
    for (int r = 0; r < 4; ++r)
        hs[r][t] = g_h[(size_t)(ns0 + r)*E_ + t];
    __syncthreads();
    float aq[4], ak[4], av[4];
    float bqv = bq[dp], bkv = bk[dp], bvv = bv[dp];
    #pragma unroll
    for (int r = 0; r < 4; ++r) { aq[r]=bqv; ak[r]=bkv; av[r]=bvv; }
    #pragma unroll 4
    for (int d = 0; d < HD_; ++d) {
        float wq = Wq[d*HD_+dp], wk = Wk[d*HD_+dp], wv = Wv[d*HD_+dp];
        #pragma unroll
        for (int r = 0; r < 4; ++r) {
            float hv = hs[r][hh*HD_ + d];
            aq[r] = fmaf(hv, wq, aq[r]);
            ak[r] = fmaf(hv, wk, ak[r]);
            av[r] = fmaf(hv, wv, av[r]);
        }
    }
    #pragma unroll
    for (int r = 0; r < 4; ++r) {
        int ns = ns0 + r;
        int n = ns >> 10, s = ns & (S_-1);
        size_t o = ((size_t)(n*H_ + hh)*S_ + s)*HD_ + dp;
        __nv_bfloat16 hi, lo;
        split2(aq[r], hi, lo); g_qhi[o] = hi; g_qlo[o] = lo;
        split2(ak[r], hi, lo); g_khi[o] = hi; g_klo[o] = lo;
        split2(av[r], hi, lo); g_vhi[o] = hi; g_vlo[o] = lo;
    }
}

// ================= kernel 3: flash attention on tensor cores (ldmatrix frags) =================
#define KPAD 72
__global__ __launch_bounds__(256) void attn_kernel()
{
    __shared__ __nv_bfloat16 sKhi[64*KPAD], sKlo[64*KPAD];
    __shared__ __nv_bfloat16 sVthi[64*KPAD], sVtlo[64*KPAD];

    int bid = blockIdx.x;
    int qt = bid & 7;
    int nh = bid >> 3;
    int tid = threadIdx.x;
    int warp = tid >> 5, lane = tid & 31;
    int lr = lane >> 2, lc2 = (lane & 3) * 2;
    const float isc = 0.044194173824159216f;   // 1/sqrt(E)

    uint32_t sKhi_u = smem_u32(sKhi), sKlo_u = smem_u32(sKlo);
    uint32_t sVthi_u = smem_u32(sVthi), sVtlo_u = smem_u32(sVtlo);
    // ldmatrix B-style address components
    int brow = (lane & 7) + ((lane >> 4) << 3);
    int bcol = ((lane >> 3) & 1) * 8;

    size_t qkv_base = (size_t)nh * S_ * HD_;
    int qrow0 = qt*128 + warp*16;

    // Q fragments (hi/lo), loaded once from global
    uint32_t qh[4][4], ql[4][4];
    #pragma unroll
    for (int ks = 0; ks < 4; ++ks) {
        int d = ks*16 + lc2;
        size_t r0 = qkv_base + (size_t)(qrow0 + lr)*HD_;
        size_t r1 = qkv_base + (size_t)(qrow0 + lr + 8)*HD_;
        qh[ks][0] = *(const uint32_t*)(g_qhi + r0 + d);
        qh[ks][1] = *(const uint32_t*)(g_qhi + r1 + d);
        qh[ks][2] = *(const uint32_t*)(g_qhi + r0 + d + 8);
        qh[ks][3] = *(const uint32_t*)(g_qhi + r1 + d + 8);
        ql[ks][0] = *(const uint32_t*)(g_qlo + r0 + d);
        ql[ks][1] = *(const uint32_t*)(g_qlo + r1 + d);
        ql[ks][2] = *(const uint32_t*)(g_qlo + r0 + d + 8);
        ql[ks][3] = *(const uint32_t*)(g_qlo + r1 + d + 8);
    }

    float oacc[8][4];
    #pragma unroll
    for (int dt = 0; dt < 8; ++dt)
        #pragma unroll
        for (int j = 0; j < 4; ++j) oacc[dt][j] = 0.0f;
    float m0 = -1e30f, m1 = -1e30f, l0 = 0.0f, l1 = 0.0f;

    for (int kt = 0; kt < 16; ++kt) {
        __syncthreads();
        {
            #pragma unroll
            for (int i = 0; i < 2; ++i) {
                int id = tid + 256*i;
                int r = id >> 3, c = id & 7;
                size_t g = qkv_base + (size_t)(kt*64 + r)*HD_ + c*8;
                *(float4*)&sKhi[r*KPAD + c*8] = *(const float4*)(g_khi + g);
                *(float4*)&sKlo[r*KPAD + c*8] = *(const float4*)(g_klo + g);
            }
        }
        {
            int k = tid >> 2, dg = (tid & 3) * 16;
            size_t g = qkv_base + (size_t)(kt*64 + k)*HD_ + dg;
            #pragma unroll
            for (int j = 0; j < 8; ++j) {
                uint32_t vh = *(const uint32_t*)(g_vhi + g + 2*j);
                uint32_t vl = *(const uint32_t*)(g_vlo + g + 2*j);
                __nv_bfloat162 h2 = *(__nv_bfloat162*)&vh;
                __nv_bfloat162 l2 = *(__nv_bfloat162*)&vl;
                sVthi[(dg + 2*j)*KPAD + k]     = h2.x;
                sVthi[(dg + 2*j + 1)*KPAD + k] = h2.y;
                sVtlo[(dg + 2*j)*KPAD + k]     = l2.x;
                sVtlo[(dg + 2*j + 1)*KPAD + k] = l2.y;
            }
        }
        __syncthreads();

        // S = Q K^T  (16 x 64 per warp, fp32 accum) via ldmatrix frags
        float sacc[8][4];
        #pragma unroll
        for (int nt = 0; nt < 8; ++nt)
            #pragma unroll
            for (int j = 0; j < 4; ++j) sacc[nt][j] = 0.0f;
        #pragma unroll
        for (int ks = 0; ks < 4; ++ks) {
            #pragma unroll
            for (int ntp = 0; ntp < 4; ++ntp) {
                uint32_t off = (uint32_t)((ntp*16 + brow)*KPAD + ks*16 + bcol) * 2;
                uint32_t kh[4], kl[4];
                LDSM4(kh, sKhi_u + off);
                LDSM4(kl, sKlo_u + off);
                mma16816(sacc[2*ntp],   qh[ks], kh[0], kh[1]);
                mma16816(sacc[2*ntp],   ql[ks], kh[0], kh[1]);
                mma16816(sacc[2*ntp],   qh[ks], kl[0], kl[1]);
                mma16816(sacc[2*ntp+1], qh[ks], kh[2], kh[3]);
                mma16816(sacc[2*ntp+1], ql[ks], kh[2], kh[3]);
                mma16816(sacc[2*ntp+1], qh[ks], kl[2], kl[3]);
            }
        }

        // online softmax
        #pragma unroll
        for (int nt = 0; nt < 8; ++nt)
            #pragma unroll
            for (int j = 0; j < 4; ++j) sacc[nt][j] *= isc;

        float mx0 = -1e30f, mx1 = -1e30f;
        #pragma unroll
        for (int nt = 0; nt < 8; ++nt) {
            mx0 = fmaxf(mx0, fmaxf(sacc[nt][0], sacc[nt][1]));
            mx1 = fmaxf(mx1, fmaxf(sacc[nt][2], sacc[nt][3]));
        }
        mx0 = fmaxf(mx0, __shfl_xor_sync(0xffffffffu, mx0, 1));
        mx0 = fmaxf(mx0, __shfl_xor_sync(0xffffffffu, mx0, 2));
        mx1 = fmaxf(mx1, __shfl_xor_sync(0xffffffffu, mx1, 1));
        mx1 = fmaxf(mx1, __shfl_xor_sync(0xffffffffu, mx1, 2));
        float mn0 = fmaxf(m0, mx0), mn1 = fmaxf(m1, mx1);
        float al0 = fexp(m0 - mn0), al1 = fexp(m1 - mn1);
        m0 = mn0; m1 = mn1;

        uint32_t pah[4][4], pal[4][4];
        float ls0 = 0.0f, ls1 = 0.0f;
        #pragma unroll
        for (int nt = 0; nt < 8; ++nt) {
            float p0 = fexp(sacc[nt][0] - mn0);
            float p1 = fexp(sacc[nt][1] - mn0);
            float p2 = fexp(sacc[nt][2] - mn1);
            float p3 = fexp(sacc[nt][3] - mn1);
            ls0 += p0 + p1; ls1 += p2 + p3;
            int ks = nt >> 1, hf = (nt & 1) * 2;
            pah[ks][hf+0] = pack2(p0, p1);
            pah[ks][hf+1] = pack2(p2, p3);
            pal[ks][hf+0] = pack2lo(p0, p1);
            pal[ks][hf+1] = pack2lo(p2, p3);
        }
        ls0 += __shfl_xor_sync(0xffffffffu, ls0, 1);
        ls0 += __shfl_xor_sync(0xffffffffu, ls0, 2);
        ls1 += __shfl_xor_sync(0xffffffffu, ls1, 1);
        ls1 += __shfl_xor_sync(0xffffffffu, ls1, 2);
        l0 = l0*al0 + ls0; l1 = l1*al1 + ls1;
        #pragma unroll
        for (int dt = 0; dt < 8; ++dt) {
            oacc[dt][0] *= al0; oacc[dt][1] *= al0;
            oacc[dt][2] *= al1; oacc[dt][3] *= al1;
        }

        // O += P V via ldmatrix frags
        #pragma unroll
        for (int ks = 0; ks < 4; ++ks) {
            #pragma unroll
            for (int dtp = 0; dtp < 4; ++dtp) {
                uint32_t off = (uint32_t)((dtp*16 + brow)*KPAD + ks*16 + bcol) * 2;
                uint32_t vh[4], vl[4];
                LDSM4(vh, sVthi_u + off);
                LDSM4(vl, sVtlo_u + off);
                mma16816(oacc[2*dtp],   pah[ks], vh[0], vh[1]);
                mma16816(oacc[2*dtp],   pal[ks], vh[0], vh[1]);
                mma16816(oacc[2*dtp],   pah[ks], vl[0], vl[1]);
                mma16816(oacc[2*dtp+1], pah[ks], vh[2], vh[3]);
                mma16816(oacc[2*dtp+1], pal[ks], vh[2], vh[3]);
                mma16816(oacc[2*dtp+1], pah[ks], vl[2], vl[3]);
            }
        }
    }

    // epilogue: write split bf16 attention output (n,s,e)
    float inv0 = 1.0f / l0, inv1 = 1.0f / l1;
    int n = nh >> 3, hh = nh & 7;
    int row0 = qt*128 + warp*16 + lr;
    size_t b0 = ((size_t)n*S_ + row0)*E_ + hh*HD_;
    size_t b1 = b0 + (size_t)8*E_;
    #pragma unroll
    for (int dt = 0; dt < 8; ++dt) {
        int e = dt*8 + lc2;
        float v0 = oacc[dt][0]*inv0, v1 = oacc[dt][1]*inv0;
        float v2 = oacc[dt][2]*inv1, v3 = oacc[dt][3]*inv1;
        *(uint32_t*)(g_attnhi + b0 + e) = pack2(v0, v1);
        *(uint32_t*)(g_attnlo + b0 + e) = pack2lo(v0, v1);
        *(uint32_t*)(g_attnhi + b1 + e) = pack2(v2, v3);
        *(uint32_t*)(g_attnlo + b1 + e) = pack2lo(v2, v3);
    }
}

// ================= weight transpose + split =================
__global__ __launch_bounds__(256) void wsplit_kernel(
    const float* __restrict__ W, __nv_bfloat16* __restrict__ hi,
    __nv_bfloat16* __restrict__ lo, int K, int N)
{
    __shared__ float t[32][33];
    size_t lstr = (size_t)K*N*blockIdx.z;
    const float* Wl = W + lstr;
    __nv_bfloat16* hil = hi + lstr;
    __nv_bfloat16* lol = lo + lstr;
    int kb = blockIdx.y*32, nb = blockIdx.x*32;
    int x = threadIdx.x, y0 = threadIdx.y;
    for (int y = y0; y < 32; y += 8)
        t[y][x] = Wl[(size_t)(kb+y)*N + nb + x];
    __syncthreads();
    for (int y = y0; y < 32; y += 8) {
        float v = t[x][y];
        __nv_bfloat16 h, l2; split2(v, h, l2);
        size_t o = (size_t)(nb+y)*K + kb + x;
        hil[o] = h; lol[o] = l2;
    }
}

// ================= mma.sync GEMM v2: 4-stage BK=16 pipeline, ldmatrix frags =================
// C[M,Nn] = A[M,K] * Bt[Nn,K]^T; A,B pre-split bf16 (hi/lo), fp32 accum.
// SMEM stage: 4 arrays [128 rows][16 cols] bf16, pitch 24 elems (48 B, conflict-free ldmatrix).
#define PT    24
#define ARR_B 6144       /* 128 * 48 bytes */
#define STG_B (4*ARR_B)  /* 24576 */
#define NSTG  4
#define GEMM_MMA_SMEM (NSTG*STG_B)  /* 98304 */

static __device__ __forceinline__ void mma_load_stage16(
    uint32_t sbase, int st,
    const __nv_bfloat16* __restrict__ Ahi, const __nv_bfloat16* __restrict__ Alo,
    const __nv_bfloat16* __restrict__ Bhi, const __nv_bfloat16* __restrict__ Blo,
    int m0, int n0, int k0, int K, int tid)
{
    uint32_t s0 = sbase + st*STG_B;
    int r = tid >> 1, c = tid & 1;
    uint32_t off = (uint32_t)(r*48 + c*16);
    size_t ga = (size_t)(m0 + r)*K + k0 + c*8;
    size_t gb = (size_t)(n0 + r)*K + k0 + c*8;
    cp16(s0 +           off, Ahi + ga);
    cp16(s0 +   ARR_B + off, Alo + ga);
    cp16(s0 + 2*ARR_B + off, Bhi + gb);
    cp16(s0 + 3*ARR_B + off, Blo + gb);
    CP_COMMIT();
}

template<int RELU, int RESID, int SPLITOUT>
__global__ __launch_bounds__(256, 2) void gemm_mma(
    const __nv_bfloat16* __restrict__ Ahi, const __nv_bfloat16* __restrict__ Alo,
    const __nv_bfloat16* __restrict__ Bhi, const __nv_bfloat16* __restrict__ Blo,
    const float* __restrict__ bias, const float* __restrict__ Rres,
    float* __restrict__ Cf, __nv_bfloat16* __restrict__ Chi, __nv_bfloat16* __restrict__ Clo,
    int Nn, int K)
{
    extern __shared__ __nv_bfloat16 sm[];
    uint32_t sbase = smem_u32(sm);
    int tid = threadIdx.x;
    int warp = tid >> 5, lane = tid & 31;
    int m0 = blockIdx.y * 128, n0 = blockIdx.x * 128;
    int wm0 = (warp & 3) * 32, wn0 = (warp >> 2) * 64;
    int lr = lane >> 2, lc2 = (lane & 3) * 2;

    // ldmatrix address components
    int arow = lane & 15, acol = (lane >> 4) * 8;            // A-style (16 rows x 2 k-halves)
    int brow = (lane & 7) + ((lane >> 4) << 3);              // B-style (2 n-octets x 2 k-halves)
    int bcol = ((lane >> 3) & 1) * 8;

    float acc[2][8][4];
    #pragma unroll
    for (int a = 0; a < 2; ++a)
        #pragma unroll
        for (int b = 0; b < 8; ++b)
            #pragma unroll
            for (int c = 0; c < 4; ++c) acc[a][b][c] = 0.0f;

    int NKB = K >> 4;   // BK=16

    mma_load_stage16(sbase, 0, Ahi, Alo, Bhi, Blo, m0, n0, 0,  K, tid);
    mma_load_stage16(sbase, 1, Ahi, Alo, Bhi, Blo, m0, n0, 16, K, tid);
    mma_load_stage16(sbase, 2, Ahi, Alo, Bhi, Blo, m0, n0, 32, K, tid);

    for (int kb = 0; kb < NKB; ++kb) {
        int st = kb & 3;
        CP_WAIT2();
        __syncthreads();

        uint32_t su = sbase + st*STG_B;
        // A fragments
        uint32_t ahi[2][4], alo[2][4];
        #pragma unroll
        for (int mt = 0; mt < 2; ++mt) {
            uint32_t ad = su + (uint32_t)((wm0 + mt*16 + arow)*48 + acol*2);
            LDSM4(ahi[mt], ad);
            LDSM4(alo[mt], ad + ARR_B);
        }
        // B fragments (per nt-pair, short liveness) + MMAs
        #pragma unroll
        for (int ntp = 0; ntp < 4; ++ntp) {
            uint32_t bd = su + 2*ARR_B + (uint32_t)((wn0 + ntp*16 + brow)*48 + bcol*2);
            uint32_t bh[4], bl[4];
            LDSM4(bh, bd);
            LDSM4(bl, bd + ARR_B);
            #pragma unroll
            for (int mt = 0; mt < 2; ++mt) {
                mma16816(acc[mt][2*ntp],   ahi[mt], bh[0], bh[1]);
                mma16816(acc[mt][2*ntp],   alo[mt], bh[0], bh[1]);
                mma16816(acc[mt][2*ntp],   ahi[mt], bl[0], bl[1]);
                mma16816(acc[mt][2*ntp+1], ahi[mt], bh[2], bh[3]);
                mma16816(acc[mt][2*ntp+1], alo[mt], bh[2], bh[3]);
                mma16816(acc[mt][2*ntp+1], ahi[mt], bl[2], bl[3]);
            }
        }
        // prefetch: stage (kb+3)%4 == stage consumed at kb-1, drained by this iter's barrier
        if (kb + 3 < NKB)
            mma_load_stage16(sbase, (kb+3) & 3, Ahi, Alo, Bhi, Blo, m0, n0, (kb+3)*16, K, tid);
    }

    #pragma unroll
    for (int mt = 0; mt < 2; ++mt) {
        #pragma unroll
        for (int half = 0; half < 2; ++half) {
            int m = m0 + wm0 + mt*16 + half*8 + lr;
            #pragma unroll
            for (int nt = 0; nt < 8; ++nt) {
                int c0 = n0 + wn0 + nt*8 + lc2;
                float2 bi = *(const float2*)(bias + c0);
                float v0 = acc[mt][nt][half*2+0] + bi.x;
                float v1 = acc[mt][nt][half*2+1] + bi.y;
                if (RESID) {
                    float2 rr = *(const float2*)(Rres + (size_t)m*Nn + c0);
                    v0 += rr.x; v1 += rr.y;
                }
                if (RELU) { v0 = fmaxf(v0, 0.f); v1 = fmaxf(v1, 0.f); }
                if (SPLITOUT) {
                    *(uint32_t*)(Chi + (size_t)m*Nn + c0) = pack2(v0, v1);
                    *(uint32_t*)(Clo + (size_t)m*Nn + c0) = pack2lo(v0, v1);
                } else {
                    *(float2*)(Cf + (size_t)m*Nn + c0) = make_float2(v0, v1);
                }
            }
        }
    }
}

// ================= small SIMT GEMM (final conv, N=64) =================
template<int FINAL>
__global__ __launch_bounds__(256) void gemm_kernel(
    const float* __restrict__ A, const float* __restrict__ B,
    const float* __restrict__ bias, float* __restrict__ C,
    int M, int Nn, int K)
{
    __shared__ float As[16][65];
    __shared__ float Bs[16][64];
    int m0 = blockIdx.y * 64, n0 = blockIdx.x * 64;
    int tid = threadIdx.x;
    int tx = tid & 15, ty = tid >> 4;

    int ar = tid >> 2;
    int ac = (tid & 3) * 4;
    int br = tid >> 4;
    int bc = (tid & 15) * 4;
    const float* Ap = A + (size_t)(m0 + ar)*K + ac;
    const float* Bp = B + (size_t)br*Nn + n0 + bc;

    float acc[4][4] = {};
    for (int k0 = 0; k0 < K; k0 += 16) {
        float4 a4 = *(const float4*)(Ap + k0);
        float4 b4 = *(const float4*)(Bp + (size_t)k0*Nn);
        As[ac+0][ar]=a4.x; As[ac+1][ar]=a4.y; As[ac+2][ar]=a4.z; As[ac+3][ar]=a4.w;
        *(float4*)&Bs[br][bc] = b4;
        __syncthreads();
        #pragma unroll
        for (int kk = 0; kk < 16; ++kk) {
            float a[4], b[4];
            #pragma unroll
            for (int i = 0; i < 4; ++i) a[i] = As[kk][ty + 16*i];
            #pragma unroll
            for (int j = 0; j < 4; ++j) b[j] = Bs[kk][tx + 16*j];
            #pragma unroll
            for (int i = 0; i < 4; ++i)
                #pragma unroll
                for (int j = 0; j < 4; ++j)
                    acc[i][j] = fmaf(a[i], b[j], acc[i][j]);
        }
        __syncthreads();
    }
    #pragma unroll
    for (int i = 0; i < 4; ++i) {
        int mrow = m0 + ty + 16*i;
        #pragma unroll
        for (int j = 0; j < 4; ++j) {
            int nn = n0 + tx + 16*j;
            float v = acc[i][j] + bias[nn];
            if (FINAL) {
                C[((size_t)(mrow >> 10)*O_ + nn)*S_ + (mrow & (S_-1))] = v;
            } else {
                C[(size_t)mrow*Nn + nn] = v;
            }
        }
    }
}

// ================= layernorm (optional split output) =================
template<int SPLIT>
__global__ __launch_bounds__(128) void ln_kernel(
    const float* __restrict__ in, float* __restrict__ out,
    const float* __restrict__ g, const float* __restrict__ b,
    __nv_bfloat16* __restrict__ ohi, __nv_bfloat16* __restrict__ olo)
{
    int row = blockIdx.x;
    int t = threadIdx.x;
    const float* p = in + (size_t)row*E_;
    float v[4], s = 0.0f, sq = 0.0f;
    #pragma unroll
    for (int q = 0; q < 4; ++q) {
        v[q] = p[t + 128*q];
        s += v[q]; sq += v[q]*v[q];
    }
    #pragma unroll
    for (int off = 16; off; off >>= 1) {
        s  += __shfl_xor_sync(0xffffffffu, s,  off);
        sq += __shfl_xor_sync(0xffffffffu, sq, off);
    }
    __shared__ float red[2][4];
    int w = t >> 5;
    if ((t & 31) == 0) { red[0][w] = s; red[1][w] = sq; }
    __syncthreads();
    s  = red[0][0] + red[0][1] + red[0][2] + red[0][3];
    sq = red[1][0] + red[1][1] + red[1][2] + red[1][3];
    float mean = s * (1.0f/E_);
    float var = sq * (1.0f/E_) - mean*mean;
    float inv = rsqrtf(var + 1e-5f);
    float* q_ = out + (size_t)row*E_;
    #pragma unroll
    for (int q = 0; q < 4; ++q) {
        int e = t + 128*q;
        float val = (v[q] - mean)*inv*g[e] + b[e];
        q_[e] = val;
        if (SPLIT) {
            __nv_bfloat16 hi, lo; split2(val, hi, lo);
            size_t o = (size_t)row*E_ + e;
            ohi[o] = hi; olo[o] = lo;
        }
    }
}

// ================= launch =================
extern "C" void kernel_launch(void* const* d_in, const int* in_sizes, int n_in,
                              void* d_out, int out_size)
{
    const float* x       = (const float*)d_in[0];
    const float* W_first = (const float*)d_in[1];
    const float* b_first = (const float*)d_in[2];
    const float* pos_emb = (const float*)d_in[3];
    const float* Wq      = (const float*)d_in[4];
    const float* bq      = (const float*)d_in[5];
    const float* Wk      = (const float*)d_in[6];
    const float* bk      = (const float*)d_in[7];
    const float* Wv      = (const float*)d_in[8];
    const float* bv      = (const float*)d_in[9];
    const float* Wo      = (const float*)d_in[10];
    const float* bo      = (const float*)d_in[11];
    const float* g1      = (const float*)d_in[12];
    const float* be1     = (const float*)d_in[13];
    const float* Wf1     = (const float*)d_in[14];
    const float* bf1     = (const float*)d_in[15];
    const float* Wf2     = (const float*)d_in[16];
    const float* bf2     = (const float*)d_in[17];
    const float* g2      = (const float*)d_in[18];
    const float* be2     = (const float*)d_in[19];
    const float* Wfin    = (const float*)d_in[20];
    const float* bfin    = (const float*)d_in[21];
    (void)in_sizes; (void)n_in; (void)out_size;

    cudaFuncSetAttribute(gemm_mma<0,1,0>, cudaFuncAttributeMaxDynamicSharedMemorySize, GEMM_MMA_SMEM);
    cudaFuncSetAttribute(gemm_mma<1,0,1>, cudaFuncAttributeMaxDynamicSharedMemorySize, GEMM_MMA_SMEM);

    float *h_p, *buf_p, *hx_p;
    cudaGetSymbolAddress((void**)&h_p,   g_h);
    cudaGetSymbolAddress((void**)&buf_p, g_buf);
    cudaGetSymbolAddress((void**)&hx_p,  g_hx);
    __nv_bfloat16 *attnhi, *attnlo, *hxhi, *hxlo, *ffhi, *fflo;
    __nv_bfloat16 *wothi, *wotlo, *wf1thi, *wf1tlo, *wf2thi, *wf2tlo;
    cudaGetSymbolAddress((void**)&attnhi, g_attnhi);
    cudaGetSymbolAddress((void**)&attnlo, g_attnlo);
    cudaGetSymbolAddress((void**)&hxhi,   g_hxhi);
    cudaGetSymbolAddress((void**)&hxlo,   g_hxlo);
    cudaGetSymbolAddress((void**)&ffhi,   g_ffhi);
    cudaGetSymbolAddress((void**)&fflo,   g_fflo);
    cudaGetSymbolAddress((void**)&wothi,  g_wothi);
    cudaGetSymbolAddress((void**)&wotlo,  g_wotlo);
    cudaGetSymbolAddress((void**)&wf1thi, g_wf1thi);
    cudaGetSymbolAddress((void**)&wf1tlo, g_wf1tlo);
    cudaGetSymbolAddress((void**)&wf2thi, g_wf2thi);
    cudaGetSymbolAddress((void**)&wf2tlo, g_wf2tlo);

    // weight prep: transpose + bf16 split (all layers)
    wsplit_kernel<<<dim3(E_/32,  E_/32,  L_), dim3(32,8)>>>(Wo,  wothi,  wotlo,  E_,  E_);
    wsplit_kernel<<<dim3(FF_/32, E_/32,  L_), dim3(32,8)>>>(Wf1, wf1thi, wf1tlo, E_,  FF_);
    wsplit_kernel<<<dim3(E_/32,  FF_/32, L_), dim3(32,8)>>>(Wf2, wf2thi, wf2tlo, FF_, E_);

    xt_kernel<<<dim3(S_/32, F_/32, N_), dim3(32,8)>>>(x);
    embed_kernel<<<NS_, 512>>>(W_first, b_first, pos_emb);

    for (int i = 0; i < L_; ++i) {
        qkv_kernel<<<NS_/4, 512>>>(Wq + i*HD_*HD_, bq + i*HD_,
                                   Wk + i*HD_*HD_, bk + i*HD_,
                                   Wv + i*HD_*HD_, bv + i*HD_);
        attn_kernel<<<N_*H_*8, 256>>>();

        gemm_mma<0,1,0><<<dim3(E_/128, NS_/128), 256, GEMM_MMA_SMEM>>>(
            attnhi, attnlo,
            wothi + (size_t)i*E_*E_, wotlo + (size_t)i*E_*E_,
            bo + i*E_, h_p, buf_p, (__nv_bfloat16*)0, (__nv_bfloat16*)0, E_, E_);
        ln_kernel<1><<<NS_, 128>>>(buf_p, hx_p, g1 + i*E_, be1 + i*E_, hxhi, hxlo);

        gemm_mma<1,0,1><<<dim3(FF_/128, NS_/128), 256, GEMM_MMA_SMEM>>>(
            hxhi, hxlo,
            wf1thi + (size_t)i*(size_t)E_*FF_, wf1tlo + (size_t)i*(size_t)E_*FF_,
            bf1 + i*FF_, (const float*)0, (float*)0, ffhi, fflo, FF_, E_);

        gemm_mma<0,1,0><<<dim3(E_/128, NS_/128), 256, GEMM_MMA_SMEM>>>(
            ffhi, fflo,
            wf2thi + (size_t)i*(size_t)FF_*E_, wf2tlo + (size_t)i*(size_t)FF_*E_,
            bf2 + i*E_, hx_p, buf_p, (__nv_bfloat16*)0, (__nv_bfloat16*)0, E_, FF_);
        ln_kernel<0><<<NS_, 128>>>(buf_p, h_p, g2 + i*E_, be2 + i*E_,
                                   (__nv_bfloat16*)0, (__nv_bfloat16*)0);
    }

    gemm_kernel<1><<<dim3(O_/64, NS_/64), 256>>>(
        h_p, Wfin, bfin, (float*)d_out, NS_, O_, E_);
}

// round 10
// speedup vs baseline: 6.3692x; 2.0806x over previous
#include <cuda_runtime.h>
#include <cuda_fp16.h>
#include <math.h>
#include <stdint.h>

#define N_ 8
#define S_ 1024
#define F_ 64
#define E_ 512
#define H_ 8
#define HD_ 64
#define O_ 64
#define L_ 6
#define FF_ 2048
#define NS_ (N_*S_)

// ---------------- scratch (no allocations allowed) ----------------
__device__ float g_h[NS_*E_];       // running hidden state (n,s,e)
__device__ float g_buf[NS_*E_];     // pre-LN sum
__device__ float g_hx[NS_*E_];      // post-LN1 (fp32 residual for FF2)
__device__ float g_xt[NS_*F_];      // transposed input (n,s,f)

// fp16 q/k/v in (n,h,s,d)
__device__ __half g_qf[NS_*E_], g_kf[NS_*E_], g_vf[NS_*E_];

// fp16 activations
__device__ __half g_attnf[NS_*E_];
__device__ __half g_hxf[NS_*E_];
__device__ __half g_fff[NS_*FF_];

// fp16 transposed weights  Wt[n][k]
__device__ __half g_wotf[L_*E_*E_];
__device__ __half g_wf1tf[L_*E_*FF_];
__device__ __half g_wf2tf[L_*FF_*E_];

// ================= helpers =================
static __device__ __forceinline__ uint32_t smem_u32(const void* p){
    uint32_t a;
    asm("{ .reg .u64 t; cvta.to.shared.u64 t, %1; cvt.u32.u64 %0, t; }" : "=r"(a) : "l"(p));
    return a;
}
static __device__ __forceinline__ void cp16(uint32_t dst, const void* src){
    asm volatile("cp.async.cg.shared.global [%0], [%1], 16;" :: "r"(dst), "l"(src));
}
#define CP_COMMIT() asm volatile("cp.async.commit_group;" ::: "memory")
#define CP_WAIT2()  asm volatile("cp.async.wait_group 2;" ::: "memory")

#define LDSM4(r, a) \
    asm volatile("ldmatrix.sync.aligned.m8n8.x4.shared.b16 {%0,%1,%2,%3}, [%4];" \
        : "=r"((r)[0]), "=r"((r)[1]), "=r"((r)[2]), "=r"((r)[3]) : "r"(a))
#define LDSM4T(r, a) \
    asm volatile("ldmatrix.sync.aligned.m8n8.x4.trans.shared.b16 {%0,%1,%2,%3}, [%4];" \
        : "=r"((r)[0]), "=r"((r)[1]), "=r"((r)[2]), "=r"((r)[3]) : "r"(a))

static __device__ __forceinline__ void mma16816(
    float* d, const uint32_t* a, uint32_t b0, uint32_t b1)
{
    asm volatile("mma.sync.aligned.m16n8k16.row.col.f32.f16.f16.f32 "
        "{%0,%1,%2,%3}, {%4,%5,%6,%7}, {%8,%9}, {%0,%1,%2,%3};"
        : "+f"(d[0]), "+f"(d[1]), "+f"(d[2]), "+f"(d[3])
        : "r"(a[0]), "r"(a[1]), "r"(a[2]), "r"(a[3]), "r"(b0), "r"(b1));
}

static __device__ __forceinline__ uint32_t pack2h(float a, float b){
    __half2 t = __floats2half2_rn(a, b);
    return *(uint32_t*)&t;
}

// fast exp on fma/alu pipes (no MUFU)
static __device__ __forceinline__ float fexp(float x){
    x = fmaxf(x, -87.0f);
    float t = x * 1.4426950408889634f;
    float z = t + 12582912.0f;
    int   i = __float_as_int(z) - 0x4B400000;
    float f = t - (z - 12582912.0f);
    float xf = f * 0.6931471805599453f;
    float p = fmaf(xf, 0.0083333333f, 0.0416666667f);
    p = fmaf(xf, p, 0.1666666667f);
    p = fmaf(xf, p, 0.5f);
    p = fmaf(xf, p, 1.0f);
    p = fmaf(xf, p, 1.0f);
    return p * __int_as_float((i + 127) << 23);
}

// ================= x transpose: x[n][f][s] -> xt[n][s][f] =================
__global__ __launch_bounds__(256) void xt_kernel(const float* __restrict__ x)
{
    __shared__ float t[32][33];
    int n = blockIdx.z;
    int s0 = blockIdx.x * 32, f0 = blockIdx.y * 32;
    int tx = threadIdx.x, ty = threadIdx.y;
    for (int y = ty; y < 32; y += 8)
        t[y][tx] = x[(size_t)n*F_*S_ + (size_t)(f0 + y)*S_ + s0 + tx];
    __syncthreads();
    for (int y = ty; y < 32; y += 8)
        g_xt[((size_t)n*S_ + s0 + y)*F_ + f0 + tx] = t[tx][y];
}

// ================= kernel 1: embed =================
__global__ __launch_bounds__(512) void embed_kernel(
    const float* __restrict__ W,
    const float* __restrict__ b, const float* __restrict__ pos)
{
    int ns = blockIdx.x;
    int s = ns & (S_-1);
    int e = threadIdx.x;
    __shared__ float xs[F_];
    if (e < F_) xs[e] = g_xt[(size_t)ns*F_ + e];
    __syncthreads();
    float acc = b[e];
    #pragma unroll 16
    for (int f = 0; f < F_; ++f)
        acc = fmaf(xs[f], W[f*E_ + e], acc);
    acc = fmaxf(acc, 0.0f) + pos[s*E_ + e];
    g_h[(size_t)ns*E_ + e] = acc;
}

// ================= kernel 2: QKV projection -> fp16 (n,h,s,d) =================
__global__ __launch_bounds__(512) void qkv_kernel(
    const float* __restrict__ Wq, const float* __restrict__ bq,
    const float* __restrict__ Wk, const float* __restrict__ bk,
    const float* __restrict__ Wv, const float* __restrict__ bv)
{
    int ns0 = blockIdx.x * 4;
    int t = threadIdx.x;
    int hh = t >> 6, dp = t & 63;
    __shared__ float hs[4][E_];
    #pragma unroll
    for (int r = 0; r < 4; ++r)
        hs[r][t] = g_h[(size_t)(ns0 + r)*E_ + t];
    __syncthreads();
    float aq[4], ak[4], av[4];
    float bqv = bq[dp], bkv = bk[dp], bvv = bv[dp];
    #pragma unroll
    for (int r = 0; r < 4; ++r) { aq[r]=bqv; ak[r]=bkv; av[r]=bvv; }
    #pragma unroll 4
    for (int d = 0; d < HD_; ++d) {
        float wq = Wq[d*HD_+dp], wk = Wk[d*HD_+dp], wv = Wv[d*HD_+dp];
        #pragma unroll
        for (int r = 0; r < 4; ++r) {
            float hv = hs[r][hh*HD_ + d];
            aq[r] = fmaf(hv, wq, aq[r]);
            ak[r] = fmaf(hv, wk, ak[r]);
            av[r] = fmaf(hv, wv, av[r]);
        }
    }
    #pragma unroll
    for (int r = 0; r < 4; ++r) {
        int ns = ns0 + r;
        int n = ns >> 10, s = ns & (S_-1);
        size_t o = ((size_t)(n*H_ + hh)*S_ + s)*HD_ + dp;
        g_qf[o] = __float2half_rn(aq[r]);
        g_kf[o] = __float2half_rn(ak[r]);
        g_vf[o] = __float2half_rn(av[r]);
    }
}

// ================= kernel 3: flash attention on tensor cores (fp16 single) =================
#define KPAD 72
__global__ __launch_bounds__(256) void attn_kernel()
{
    __shared__ __half sKf[64*KPAD];
    __shared__ __half sVf[64*KPAD];   // [k][d], B-frags via ldmatrix.trans

    int bid = blockIdx.x;
    int qt = bid & 7;
    int nh = bid >> 3;
    int tid = threadIdx.x;
    int warp = tid >> 5, lane = tid & 31;
    int lr = lane >> 2, lc2 = (lane & 3) * 2;
    const float isc = 0.044194173824159216f;   // 1/sqrt(E)

    uint32_t sKf_u = smem_u32(sKf), sVf_u = smem_u32(sVf);
    // non-trans B addressing (K tiles)
    int brow = (lane & 7) + ((lane >> 4) << 3);
    int bcol = ((lane >> 3) & 1) * 8;
    // trans B addressing (V tiles): matrix mi = lane>>3
    int vrow = ((lane >> 3) & 1) * 8 + (lane & 7);
    int vcol = (lane >> 4) * 8;

    size_t qkv_base = (size_t)nh * S_ * HD_;
    int qrow0 = qt*128 + warp*16;

    // Q fragments, loaded once from global
    uint32_t qf[4][4];
    #pragma unroll
    for (int ks = 0; ks < 4; ++ks) {
        int d = ks*16 + lc2;
        size_t r0 = qkv_base + (size_t)(qrow0 + lr)*HD_;
        size_t r1 = qkv_base + (size_t)(qrow0 + lr + 8)*HD_;
        qf[ks][0] = *(const uint32_t*)(g_qf + r0 + d);
        qf[ks][1] = *(const uint32_t*)(g_qf + r1 + d);
        qf[ks][2] = *(const uint32_t*)(g_qf + r0 + d + 8);
        qf[ks][3] = *(const uint32_t*)(g_qf + r1 + d + 8);
    }

    float oacc[8][4];
    #pragma unroll
    for (int dt = 0; dt < 8; ++dt)
        #pragma unroll
        for (int j = 0; j < 4; ++j) oacc[dt][j] = 0.0f;
    float m0 = -1e30f, m1 = -1e30f, l0 = 0.0f, l1 = 0.0f;

    for (int kt = 0; kt < 16; ++kt) {
        __syncthreads();
        // load K and V tiles: 64 rows x 64 fp16 = 8 chunks/row, coalesced float4
        #pragma unroll
        for (int i = 0; i < 2; ++i) {
            int id = tid + 256*i;
            int r = id >> 3, c = id & 7;
            size_t g = qkv_base + (size_t)(kt*64 + r)*HD_ + c*8;
            *(float4*)&sKf[r*KPAD + c*8] = *(const float4*)(g_kf + g);
            *(float4*)&sVf[r*KPAD + c*8] = *(const float4*)(g_vf + g);
        }
        __syncthreads();

        // S = Q K^T  (16 x 64 per warp, fp32 accum)
        float sacc[8][4];
        #pragma unroll
        for (int nt = 0; nt < 8; ++nt)
            #pragma unroll
            for (int j = 0; j < 4; ++j) sacc[nt][j] = 0.0f;
        #pragma unroll
        for (int ks = 0; ks < 4; ++ks) {
            #pragma unroll
            for (int ntp = 0; ntp < 4; ++ntp) {
                uint32_t off = (uint32_t)((ntp*16 + brow)*KPAD + ks*16 + bcol) * 2;
                uint32_t kh[4];
                LDSM4(kh, sKf_u + off);
                mma16816(sacc[2*ntp],   qf[ks], kh[0], kh[1]);
                mma16816(sacc[2*ntp+1], qf[ks], kh[2], kh[3]);
            }
        }

        // online softmax
        #pragma unroll
        for (int nt = 0; nt < 8; ++nt)
            #pragma unroll
            for (int j = 0; j < 4; ++j) sacc[nt][j] *= isc;

        float mx0 = -1e30f, mx1 = -1e30f;
        #pragma unroll
        for (int nt = 0; nt < 8; ++nt) {
            mx0 = fmaxf(mx0, fmaxf(sacc[nt][0], sacc[nt][1]));
            mx1 = fmaxf(mx1, fmaxf(sacc[nt][2], sacc[nt][3]));
        }
        mx0 = fmaxf(mx0, __shfl_xor_sync(0xffffffffu, mx0, 1));
        mx0 = fmaxf(mx0, __shfl_xor_sync(0xffffffffu, mx0, 2));
        mx1 = fmaxf(mx1, __shfl_xor_sync(0xffffffffu, mx1, 1));
        mx1 = fmaxf(mx1, __shfl_xor_sync(0xffffffffu, mx1, 2));
        float mn0 = fmaxf(m0, mx0), mn1 = fmaxf(m1, mx1);
        float al0 = fexp(m0 - mn0), al1 = fexp(m1 - mn1);
        m0 = mn0; m1 = mn1;

        uint32_t pah[4][4];
        float ls0 = 0.0f, ls1 = 0.0f;
        #pragma unroll
        for (int nt = 0; nt < 8; ++nt) {
            float p0 = fexp(sacc[nt][0] - mn0);
            float p1 = fexp(sacc[nt][1] - mn0);
            float p2 = fexp(sacc[nt][2] - mn1);
            float p3 = fexp(sacc[nt][3] - mn1);
            ls0 += p0 + p1; ls1 += p2 + p3;
            int ks = nt >> 1, hf = (nt & 1) * 2;
            pah[ks][hf+0] = pack2h(p0, p1);
            pah[ks][hf+1] = pack2h(p2, p3);
        }
        ls0 += __shfl_xor_sync(0xffffffffu, ls0, 1);
        ls0 += __shfl_xor_sync(0xffffffffu, ls0, 2);
        ls1 += __shfl_xor_sync(0xffffffffu, ls1, 1);
        ls1 += __shfl_xor_sync(0xffffffffu, ls1, 2);
        l0 = l0*al0 + ls0; l1 = l1*al1 + ls1;
        #pragma unroll
        for (int dt = 0; dt < 8; ++dt) {
            oacc[dt][0] *= al0; oacc[dt][1] *= al0;
            oacc[dt][2] *= al1; oacc[dt][3] *= al1;
        }

        // O += P V: B-frags from row-major V via ldmatrix.trans
        #pragma unroll
        for (int ks = 0; ks < 4; ++ks) {
            #pragma unroll
            for (int dtp = 0; dtp < 4; ++dtp) {
                uint32_t off = (uint32_t)((ks*16 + vrow)*KPAD + dtp*16 + vcol) * 2;
                uint32_t vh[4];
                LDSM4T(vh, sVf_u + off);
                mma16816(oacc[2*dtp],   pah[ks], vh[0], vh[1]);
                mma16816(oacc[2*dtp+1], pah[ks], vh[2], vh[3]);
            }
        }
    }

    // epilogue: write fp16 attention output (n,s,e)
    float inv0 = 1.0f / l0, inv1 = 1.0f / l1;
    int n = nh >> 3, hh = nh & 7;
    int row0 = qt*128 + warp*16 + lr;
    size_t b0 = ((size_t)n*S_ + row0)*E_ + hh*HD_;
    size_t b1 = b0 + (size_t)8*E_;
    #pragma unroll
    for (int dt = 0; dt < 8; ++dt) {
        int e = dt*8 + lc2;
        *(uint32_t*)(g_attnf + b0 + e) = pack2h(oacc[dt][0]*inv0, oacc[dt][1]*inv0);
        *(uint32_t*)(g_attnf + b1 + e) = pack2h(oacc[dt][2]*inv1, oacc[dt][3]*inv1);
    }
}

// ================= weight transpose + fp16 convert =================
// in: W [K][N] fp32 (layer z stride K*N) -> out [N][K] fp16
__global__ __launch_bounds__(256) void wconv_kernel(
    const float* __restrict__ W, __half* __restrict__ out, int K, int N)
{
    __shared__ float t[32][33];
    size_t lstr = (size_t)K*N*blockIdx.z;
    const float* Wl = W + lstr;
    __half* ol = out + lstr;
    int kb = blockIdx.y*32, nb = blockIdx.x*32;
    int x = threadIdx.x, y0 = threadIdx.y;
    for (int y = y0; y < 32; y += 8)
        t[y][x] = Wl[(size_t)(kb+y)*N + nb + x];
    __syncthreads();
    for (int y = y0; y < 32; y += 8)
        ol[(size_t)(nb+y)*K + kb + x] = __float2half_rn(t[x][y]);
}

// ================= mma.sync GEMM: fp16 single, 4-stage BK=16, ldmatrix =================
// C[M,Nn] = A[M,K] * Bt[Nn,K]^T; fp32 accum.
// SMEM stage: 2 arrays [128 rows][16 cols] fp16, pitch 24 elems (48 B).
#define ARR_B 6144       /* 128 * 48 bytes */
#define STG_B (2*ARR_B)  /* 12288 */
#define NSTG  4
#define GEMM_MMA_SMEM (NSTG*STG_B)  /* 49152 */

static __device__ __forceinline__ void mma_load_stage16(
    uint32_t sbase, int st,
    const __half* __restrict__ Af, const __half* __restrict__ Bf,
    int m0, int n0, int k0, int K, int tid)
{
    uint32_t s0 = sbase + st*STG_B;
    int r = tid >> 1, c = tid & 1;
    uint32_t off = (uint32_t)(r*48 + c*16);
    cp16(s0 +         off, Af + (size_t)(m0 + r)*K + k0 + c*8);
    cp16(s0 + ARR_B + off, Bf + (size_t)(n0 + r)*K + k0 + c*8);
    CP_COMMIT();
}

template<int RELU, int RESID, int HOUT>
__global__ __launch_bounds__(256, 2) void gemm_mma(
    const __half* __restrict__ Af, const __half* __restrict__ Bf,
    const float* __restrict__ bias, const float* __restrict__ Rres,
    float* __restrict__ Cf, __half* __restrict__ Ch,
    int Nn, int K)
{
    extern __shared__ __half sm[];
    uint32_t sbase = smem_u32(sm);
    int tid = threadIdx.x;
    int warp = tid >> 5, lane = tid & 31;
    int m0 = blockIdx.y * 128, n0 = blockIdx.x * 128;
    int wm0 = (warp & 3) * 32, wn0 = (warp >> 2) * 64;
    int lr = lane >> 2, lc2 = (lane & 3) * 2;

    int arow = lane & 15, acol = (lane >> 4) * 8;
    int brow = (lane & 7) + ((lane >> 4) << 3);
    int bcol = ((lane >> 3) & 1) * 8;

    float acc[2][8][4];
    #pragma unroll
    for (int a = 0; a < 2; ++a)
        #pragma unroll
        for (int b = 0; b < 8; ++b)
            #pragma unroll
            for (int c = 0; c < 4; ++c) acc[a][b][c] = 0.0f;

    int NKB = K >> 4;

    mma_load_stage16(sbase, 0, Af, Bf, m0, n0, 0,  K, tid);
    mma_load_stage16(sbase, 1, Af, Bf, m0, n0, 16, K, tid);
    mma_load_stage16(sbase, 2, Af, Bf, m0, n0, 32, K, tid);

    for (int kb = 0; kb < NKB; ++kb) {
        int st = kb & 3;
        CP_WAIT2();
        __syncthreads();

        uint32_t su = sbase + st*STG_B;
        uint32_t af[2][4];
        #pragma unroll
        for (int mt = 0; mt < 2; ++mt) {
            uint32_t ad = su + (uint32_t)((wm0 + mt*16 + arow)*48 + acol*2);
            LDSM4(af[mt], ad);
        }
        #pragma unroll
        for (int ntp = 0; ntp < 4; ++ntp) {
            uint32_t bd = su + ARR_B + (uint32_t)((wn0 + ntp*16 + brow)*48 + bcol*2);
            uint32_t bfr[4];
            LDSM4(bfr, bd);
            #pragma unroll
            for (int mt = 0; mt < 2; ++mt) {
                mma16816(acc[mt][2*ntp],   af[mt], bfr[0], bfr[1]);
                mma16816(acc[mt][2*ntp+1], af[mt], bfr[2], bfr[3]);
            }
        }
        if (kb + 3 < NKB)
            mma_load_stage16(sbase, (kb+3) & 3, Af, Bf, m0, n0, (kb+3)*16, K, tid);
    }

    #pragma unroll
    for (int mt = 0; mt < 2; ++mt) {
        #pragma unroll
        for (int half = 0; half < 2; ++half) {
            int m = m0 + wm0 + mt*16 + half*8 + lr;
            #pragma unroll
            for (int nt = 0; nt < 8; ++nt) {
                int c0 = n0 + wn0 + nt*8 + lc2;
                float2 bi = *(const float2*)(bias + c0);
                float v0 = acc[mt][nt][half*2+0] + bi.x;
                float v1 = acc[mt][nt][half*2+1] + bi.y;
                if (RESID) {
                    float2 rr = *(const float2*)(Rres + (size_t)m*Nn + c0);
                    v0 += rr.x; v1 += rr.y;
                }
                if (RELU) { v0 = fmaxf(v0, 0.f); v1 = fmaxf(v1, 0.f); }
                if (HOUT) {
                    *(uint32_t*)(Ch + (size_t)m*Nn + c0) = pack2h(v0, v1);
                } else {
                    *(float2*)(Cf + (size_t)m*Nn + c0) = make_float2(v0, v1);
                }
            }
        }
    }
}

// ================= small SIMT GEMM (final conv, N=64) =================
template<int FINAL>
__global__ __launch_bounds__(256) void gemm_kernel(
    const float* __restrict__ A, const float* __restrict__ B,
    const float* __restrict__ bias, float* __restrict__ C,
    int M, int Nn, int K)
{
    __shared__ float As[16][65];
    __shared__ float Bs[16][64];
    int m0 = blockIdx.y * 64, n0 = blockIdx.x * 64;
    int tid = threadIdx.x;
    int tx = tid & 15, ty = tid >> 4;

    int ar = tid >> 2;
    int ac = (tid & 3) * 4;
    int br = tid >> 4;
    int bc = (tid & 15) * 4;
    const float* Ap = A + (size_t)(m0 + ar)*K + ac;
    const float* Bp = B + (size_t)br*Nn + n0 + bc;

    float acc[4][4] = {};
    for (int k0 = 0; k0 < K; k0 += 16) {
        float4 a4 = *(const float4*)(Ap + k0);
        float4 b4 = *(const float4*)(Bp + (size_t)k0*Nn);
        As[ac+0][ar]=a4.x; As[ac+1][ar]=a4.y; As[ac+2][ar]=a4.z; As[ac+3][ar]=a4.w;
        *(float4*)&Bs[br][bc] = b4;
        __syncthreads();
        #pragma unroll
        for (int kk = 0; kk < 16; ++kk) {
            float a[4], b[4];
            #pragma unroll
            for (int i = 0; i < 4; ++i) a[i] = As[kk][ty + 16*i];
            #pragma unroll
            for (int j = 0; j < 4; ++j) b[j] = Bs[kk][tx + 16*j];
            #pragma unroll
            for (int i = 0; i < 4; ++i)
                #pragma unroll
                for (int j = 0; j < 4; ++j)
                    acc[i][j] = fmaf(a[i], b[j], acc[i][j]);
        }
        __syncthreads();
    }
    #pragma unroll
    for (int i = 0; i < 4; ++i) {
        int mrow = m0 + ty + 16*i;
        #pragma unroll
        for (int j = 0; j < 4; ++j) {
            int nn = n0 + tx + 16*j;
            float v = acc[i][j] + bias[nn];
            if (FINAL) {
                C[((size_t)(mrow >> 10)*O_ + nn)*S_ + (mrow & (S_-1))] = v;
            } else {
                C[(size_t)mrow*Nn + nn] = v;
            }
        }
    }
}

// ================= layernorm (optional fp16 output) =================
template<int HOUT>
__global__ __launch_bounds__(128) void ln_kernel(
    const float* __restrict__ in, float* __restrict__ out,
    const float* __restrict__ g, const float* __restrict__ b,
    __half* __restrict__ oh)
{
    int row = blockIdx.x;
    int t = threadIdx.x;
    const float* p = in + (size_t)row*E_;
    float v[4], s = 0.0f, sq = 0.0f;
    #pragma unroll
    for (int q = 0; q < 4; ++q) {
        v[q] = p[t + 128*q];
        s += v[q]; sq += v[q]*v[q];
    }
    #pragma unroll
    for (int off = 16; off; off >>= 1) {
        s  += __shfl_xor_sync(0xffffffffu, s,  off);
        sq += __shfl_xor_sync(0xffffffffu, sq, off);
    }
    __shared__ float red[2][4];
    int w = t >> 5;
    if ((t & 31) == 0) { red[0][w] = s; red[1][w] = sq; }
    __syncthreads();
    s  = red[0][0] + red[0][1] + red[0][2] + red[0][3];
    sq = red[1][0] + red[1][1] + red[1][2] + red[1][3];
    float mean = s * (1.0f/E_);
    float var = sq * (1.0f/E_) - mean*mean;
    float inv = rsqrtf(var + 1e-5f);
    float* q_ = out + (size_t)row*E_;
    #pragma unroll
    for (int q = 0; q < 4; ++q) {
        int e = t + 128*q;
        float val = (v[q] - mean)*inv*g[e] + b[e];
        q_[e] = val;
        if (HOUT) oh[(size_t)row*E_ + e] = __float2half_rn(val);
    }
}

// ================= launch =================
extern "C" void kernel_launch(void* const* d_in, const int* in_sizes, int n_in,
                              void* d_out, int out_size)
{
    const float* x       = (const float*)d_in[0];
    const float* W_first = (const float*)d_in[1];
    const float* b_first = (const float*)d_in[2];
    const float* pos_emb = (const float*)d_in[3];
    const float* Wq      = (const float*)d_in[4];
    const float* bq      = (const float*)d_in[5];
    const float* Wk      = (const float*)d_in[6];
    const float* bk      = (const float*)d_in[7];
    const float* Wv      = (const float*)d_in[8];
    const float* bv      = (const float*)d_in[9];
    const float* Wo      = (const float*)d_in[10];
    const float* bo      = (const float*)d_in[11];
    const float* g1      = (const float*)d_in[12];
    const float* be1     = (const float*)d_in[13];
    const float* Wf1     = (const float*)d_in[14];
    const float* bf1     = (const float*)d_in[15];
    const float* Wf2     = (const float*)d_in[16];
    const float* bf2     = (const float*)d_in[17];
    const float* g2      = (const float*)d_in[18];
    const float* be2     = (const float*)d_in[19];
    const float* Wfin    = (const float*)d_in[20];
    const float* bfin    = (const float*)d_in[21];
    (void)in_sizes; (void)n_in; (void)out_size;

    cudaFuncSetAttribute(gemm_mma<0,1,0>, cudaFuncAttributeMaxDynamicSharedMemorySize, GEMM_MMA_SMEM);
    cudaFuncSetAttribute(gemm_mma<1,0,1>, cudaFuncAttributeMaxDynamicSharedMemorySize, GEMM_MMA_SMEM);

    float *h_p, *buf_p, *hx_p;
    cudaGetSymbolAddress((void**)&h_p,   g_h);
    cudaGetSymbolAddress((void**)&buf_p, g_buf);
    cudaGetSymbolAddress((void**)&hx_p,  g_hx);
    __half *attnf, *hxf, *fff, *wotf, *wf1tf, *wf2tf;
    cudaGetSymbolAddress((void**)&attnf, g_attnf);
    cudaGetSymbolAddress((void**)&hxf,   g_hxf);
    cudaGetSymbolAddress((void**)&fff,   g_fff);
    cudaGetSymbolAddress((void**)&wotf,  g_wotf);
    cudaGetSymbolAddress((void**)&wf1tf, g_wf1tf);
    cudaGetSymbolAddress((void**)&wf2tf, g_wf2tf);

    // weight prep: transpose + fp16 convert (all layers)
    wconv_kernel<<<dim3(E_/32,  E_/32,  L_), dim3(32,8)>>>(Wo,  wotf,  E_,  E_);
    wconv_kernel<<<dim3(FF_/32, E_/32,  L_), dim3(32,8)>>>(Wf1, wf1tf, E_,  FF_);
    wconv_kernel<<<dim3(E_/32,  FF_/32, L_), dim3(32,8)>>>(Wf2, wf2tf, FF_, E_);

    xt_kernel<<<dim3(S_/32, F_/32, N_), dim3(32,8)>>>(x);
    embed_kernel<<<NS_, 512>>>(W_first, b_first, pos_emb);

    for (int i = 0; i < L_; ++i) {
        qkv_kernel<<<NS_/4, 512>>>(Wq + i*HD_*HD_, bq + i*HD_,
                                   Wk + i*HD_*HD_, bk + i*HD_,
                                   Wv + i*HD_*HD_, bv + i*HD_);
        attn_kernel<<<N_*H_*8, 256>>>();

        gemm_mma<0,1,0><<<dim3(E_/128, NS_/128), 256, GEMM_MMA_SMEM>>>(
            attnf, wotf + (size_t)i*E_*E_,
            bo + i*E_, h_p, buf_p, (__half*)0, E_, E_);
        ln_kernel<1><<<NS_, 128>>>(buf_p, hx_p, g1 + i*E_, be1 + i*E_, hxf);

        gemm_mma<1,0,1><<<dim3(FF_/128, NS_/128), 256, GEMM_MMA_SMEM>>>(
            hxf, wf1tf + (size_t)i*(size_t)E_*FF_,
            bf1 + i*FF_, (const float*)0, (float*)0, fff, FF_, E_);

        gemm_mma<0,1,0><<<dim3(E_/128, NS_/128), 256, GEMM_MMA_SMEM>>>(
            fff, wf2tf + (size_t)i*(size_t)FF_*E_,
            bf2 + i*E_, hx_p, buf_p, (__half*)0, E_, FF_);
        ln_kernel<0><<<NS_, 128>>>(buf_p, h_p, g2 + i*E_, be2 + i*E_, (__half*)0);
    }

    gemm_kernel<1><<<dim3(O_/64, NS_/64), 256>>>(
        h_p, Wfin, bfin, (float*)d_out, NS_, O_, E_);
}

// round 11
// speedup vs baseline: 7.2900x; 1.1446x over previous
#include <cuda_runtime.h>
#include <cuda_fp16.h>
#include <math.h>
#include <stdint.h>

#define N_ 8
#define S_ 1024
#define F_ 64
#define E_ 512
#define H_ 8
#define HD_ 64
#define O_ 64
#define L_ 6
#define FF_ 2048
#define NS_ (N_*S_)

// ---------------- scratch (no allocations allowed) ----------------
__device__ float g_h[NS_*E_];       // running hidden state (n,s,e) fp32 (residual)
__device__ float g_buf[NS_*E_];     // pre-LN sum
__device__ float g_hx[NS_*E_];      // post-LN1 (fp32 residual for FF2)
__device__ float g_xt[NS_*F_];      // transposed input (n,s,f)

__device__ __half g_hf[NS_*E_];     // fp16 copy of hidden state (qkv input)

// fp16 q/k/v in (n,h,s,d)
__device__ __half g_qf[NS_*E_], g_kf[NS_*E_], g_vf[NS_*E_];

// fp16 activations
__device__ __half g_attnf[NS_*E_];
__device__ __half g_hxf[NS_*E_];
__device__ __half g_fff[NS_*FF_];

// fp16 transposed weights
__device__ __half g_wotf[L_*E_*E_];
__device__ __half g_wf1tf[L_*E_*FF_];
__device__ __half g_wf2tf[L_*FF_*E_];
__device__ __half g_wqtf[L_*HD_*HD_], g_wktf[L_*HD_*HD_], g_wvtf[L_*HD_*HD_];

// ================= helpers =================
static __device__ __forceinline__ uint32_t smem_u32(const void* p){
    uint32_t a;
    asm("{ .reg .u64 t; cvta.to.shared.u64 t, %1; cvt.u32.u64 %0, t; }" : "=r"(a) : "l"(p));
    return a;
}
static __device__ __forceinline__ void cp16(uint32_t dst, const void* src){
    asm volatile("cp.async.cg.shared.global [%0], [%1], 16;" :: "r"(dst), "l"(src));
}
#define CP_COMMIT() asm volatile("cp.async.commit_group;" ::: "memory")
#define CP_WAIT0()  asm volatile("cp.async.wait_group 0;" ::: "memory")
#define CP_WAIT2()  asm volatile("cp.async.wait_group 2;" ::: "memory")

#define LDSM4(r, a) \
    asm volatile("ldmatrix.sync.aligned.m8n8.x4.shared.b16 {%0,%1,%2,%3}, [%4];" \
        : "=r"((r)[0]), "=r"((r)[1]), "=r"((r)[2]), "=r"((r)[3]) : "r"(a))
#define LDSM4T(r, a) \
    asm volatile("ldmatrix.sync.aligned.m8n8.x4.trans.shared.b16 {%0,%1,%2,%3}, [%4];" \
        : "=r"((r)[0]), "=r"((r)[1]), "=r"((r)[2]), "=r"((r)[3]) : "r"(a))

static __device__ __forceinline__ void mma16816(
    float* d, const uint32_t* a, uint32_t b0, uint32_t b1)
{
    asm volatile("mma.sync.aligned.m16n8k16.row.col.f32.f16.f16.f32 "
        "{%0,%1,%2,%3}, {%4,%5,%6,%7}, {%8,%9}, {%0,%1,%2,%3};"
        : "+f"(d[0]), "+f"(d[1]), "+f"(d[2]), "+f"(d[3])
        : "r"(a[0]), "r"(a[1]), "r"(a[2]), "r"(a[3]), "r"(b0), "r"(b1));
}

static __device__ __forceinline__ uint32_t pack2h(float a, float b){
    __half2 t = __floats2half2_rn(a, b);
    return *(uint32_t*)&t;
}

// fast exp on fma/alu pipes (no MUFU)
static __device__ __forceinline__ float fexp(float x){
    x = fmaxf(x, -87.0f);
    float t = x * 1.4426950408889634f;
    float z = t + 12582912.0f;
    int   i = __float_as_int(z) - 0x4B400000;
    float f = t - (z - 12582912.0f);
    float xf = f * 0.6931471805599453f;
    float p = fmaf(xf, 0.0083333333f, 0.0416666667f);
    p = fmaf(xf, p, 0.1666666667f);
    p = fmaf(xf, p, 0.5f);
    p = fmaf(xf, p, 1.0f);
    p = fmaf(xf, p, 1.0f);
    return p * __int_as_float((i + 127) << 23);
}

// ================= x transpose: x[n][f][s] -> xt[n][s][f] =================
__global__ __launch_bounds__(256) void xt_kernel(const float* __restrict__ x)
{
    __shared__ float t[32][33];
    int n = blockIdx.z;
    int s0 = blockIdx.x * 32, f0 = blockIdx.y * 32;
    int tx = threadIdx.x, ty = threadIdx.y;
    for (int y = ty; y < 32; y += 8)
        t[y][tx] = x[(size_t)n*F_*S_ + (size_t)(f0 + y)*S_ + s0 + tx];
    __syncthreads();
    for (int y = ty; y < 32; y += 8)
        g_xt[((size_t)n*S_ + s0 + y)*F_ + f0 + tx] = t[tx][y];
}

// ================= kernel 1: embed (writes fp32 + fp16) =================
__global__ __launch_bounds__(512) void embed_kernel(
    const float* __restrict__ W,
    const float* __restrict__ b, const float* __restrict__ pos)
{
    int ns = blockIdx.x;
    int s = ns & (S_-1);
    int e = threadIdx.x;
    __shared__ float xs[F_];
    if (e < F_) xs[e] = g_xt[(size_t)ns*F_ + e];
    __syncthreads();
    float acc = b[e];
    #pragma unroll 16
    for (int f = 0; f < F_; ++f)
        acc = fmaf(xs[f], W[f*E_ + e], acc);
    acc = fmaxf(acc, 0.0f) + pos[s*E_ + e];
    g_h[(size_t)ns*E_ + e] = acc;
    g_hf[(size_t)ns*E_ + e] = __float2half_rn(acc);
}

// ================= kernel 2: QKV projection on tensor cores =================
// block = (mtile, nh): A = hf[n, s0:s0+128, h*64:+64] (128x64), B = Wt (64x64) x3.
#define QPT 72
__global__ __launch_bounds__(256) void qkv_mma(
    const __half* __restrict__ Wqt, const __half* __restrict__ Wkt,
    const __half* __restrict__ Wvt,
    const float* __restrict__ bq, const float* __restrict__ bk,
    const float* __restrict__ bv)
{
    __shared__ __half sA[128*QPT];
    __shared__ __half sW[3*64*QPT];

    int s0 = blockIdx.x * 128;
    int nh = blockIdx.y;
    int n = nh >> 3, hh = nh & 7;
    int tid = threadIdx.x;
    int warp = tid >> 5, lane = tid & 31;
    int lr = lane >> 2, lc2 = (lane & 3) * 2;
    int arow = lane & 15, acol = (lane >> 4) * 8;
    int brow = (lane & 7) + ((lane >> 4) << 3);
    int bcol = ((lane >> 3) & 1) * 8;

    // load A tile (128 x 64 fp16), coalesced 16B chunks
    #pragma unroll
    for (int i = 0; i < 4; ++i) {
        int id = tid + 256*i;                 // 0..1023
        int r = id >> 3, c = id & 7;
        *(float4*)&sA[r*QPT + c*8] =
            *(const float4*)(g_hf + ((size_t)n*S_ + s0 + r)*E_ + hh*HD_ + c*8);
    }
    // load 3 weight tiles (64 x 64 each)
    #pragma unroll
    for (int i = 0; i < 6; ++i) {
        int id = tid + 256*i;                 // 0..1535
        int mat = id >> 9, rr = (id >> 3) & 63, c = id & 7;
        const __half* src = (mat == 0) ? Wqt : (mat == 1) ? Wkt : Wvt;
        *(float4*)&sW[mat*64*QPT + rr*QPT + c*8] = *(const float4*)(src + rr*HD_ + c*8);
    }
    __syncthreads();

    uint32_t sA_u = smem_u32(sA), sW_u = smem_u32(sW);
    #pragma unroll
    for (int mat = 0; mat < 3; ++mat) {
        float acc[8][4];
        #pragma unroll
        for (int nt = 0; nt < 8; ++nt)
            #pragma unroll
            for (int j = 0; j < 4; ++j) acc[nt][j] = 0.0f;
        #pragma unroll
        for (int ks = 0; ks < 4; ++ks) {
            uint32_t af[4];
            LDSM4(af, sA_u + (uint32_t)((warp*16 + arow)*QPT + ks*16 + acol)*2);
            #pragma unroll
            for (int ntp = 0; ntp < 4; ++ntp) {
                uint32_t bfr[4];
                LDSM4(bfr, sW_u + (uint32_t)(mat*64*QPT + (ntp*16 + brow)*QPT + ks*16 + bcol)*2);
                mma16816(acc[2*ntp],   af, bfr[0], bfr[1]);
                mma16816(acc[2*ntp+1], af, bfr[2], bfr[3]);
            }
        }
        const float* bias = (mat == 0) ? bq : (mat == 1) ? bk : bv;
        __half* dst = (mat == 0) ? g_qf : (mat == 1) ? g_kf : g_vf;
        size_t rb0 = ((size_t)nh*S_ + s0 + warp*16 + lr)*HD_;
        size_t rb1 = rb0 + 8*HD_;
        #pragma unroll
        for (int nt = 0; nt < 8; ++nt) {
            int c0 = nt*8 + lc2;
            float2 bi = *(const float2*)(bias + c0);
            *(uint32_t*)(dst + rb0 + c0) = pack2h(acc[nt][0] + bi.x, acc[nt][1] + bi.y);
            *(uint32_t*)(dst + rb1 + c0) = pack2h(acc[nt][2] + bi.x, acc[nt][3] + bi.y);
        }
    }
}

// ================= kernel 3: flash attention, cp.async double-buffered K/V =================
#define KPAD 72
#define ATT_STG (2*64*KPAD)            /* halfs per stage (K + V) */
#define ATT_SMEM (2*ATT_STG*2)         /* bytes: 2 stages */

static __device__ __forceinline__ void attn_load_kv(
    uint32_t sbase, int st, size_t qkv_base, int kt, int tid)
{
    uint32_t s0 = sbase + (uint32_t)st*ATT_STG*2;
    #pragma unroll
    for (int i = 0; i < 2; ++i) {
        int id = tid + 256*i;
        int r = id >> 3, c = id & 7;
        size_t g = qkv_base + (size_t)(kt*64 + r)*HD_ + c*8;
        cp16(s0 +               r*(KPAD*2) + c*16, g_kf + g);
        cp16(s0 + 64*KPAD*2 +   r*(KPAD*2) + c*16, g_vf + g);
    }
    CP_COMMIT();
}

__global__ __launch_bounds__(256) void attn_kernel()
{
    extern __shared__ __half smA[];
    uint32_t sbase = smem_u32(smA);

    int bid = blockIdx.x;
    int qt = bid & 7;
    int nh = bid >> 3;
    int tid = threadIdx.x;
    int warp = tid >> 5, lane = tid & 31;
    int lr = lane >> 2, lc2 = (lane & 3) * 2;
    const float isc = 0.044194173824159216f;   // 1/sqrt(E)

    int brow = (lane & 7) + ((lane >> 4) << 3);
    int bcol = ((lane >> 3) & 1) * 8;
    int vrow = ((lane >> 3) & 1) * 8 + (lane & 7);
    int vcol = (lane >> 4) * 8;

    size_t qkv_base = (size_t)nh * S_ * HD_;
    int qrow0 = qt*128 + warp*16;

    uint32_t qf[4][4];
    #pragma unroll
    for (int ks = 0; ks < 4; ++ks) {
        int d = ks*16 + lc2;
        size_t r0 = qkv_base + (size_t)(qrow0 + lr)*HD_;
        size_t r1 = qkv_base + (size_t)(qrow0 + lr + 8)*HD_;
        qf[ks][0] = *(const uint32_t*)(g_qf + r0 + d);
        qf[ks][1] = *(const uint32_t*)(g_qf + r1 + d);
        qf[ks][2] = *(const uint32_t*)(g_qf + r0 + d + 8);
        qf[ks][3] = *(const uint32_t*)(g_qf + r1 + d + 8);
    }

    float oacc[8][4];
    #pragma unroll
    for (int dt = 0; dt < 8; ++dt)
        #pragma unroll
        for (int j = 0; j < 4; ++j) oacc[dt][j] = 0.0f;
    float m0 = -1e30f, m1 = -1e30f, l0 = 0.0f, l1 = 0.0f;

    attn_load_kv(sbase, 0, qkv_base, 0, tid);

    for (int kt = 0; kt < 16; ++kt) {
        CP_WAIT0();
        __syncthreads();          // all warps done with the stage being overwritten next
        if (kt + 1 < 16)
            attn_load_kv(sbase, (kt+1) & 1, qkv_base, kt+1, tid);

        uint32_t sK_u = sbase + (uint32_t)(kt & 1)*ATT_STG*2;
        uint32_t sV_u = sK_u + 64*KPAD*2;

        // S = Q K^T
        float sacc[8][4];
        #pragma unroll
        for (int nt = 0; nt < 8; ++nt)
            #pragma unroll
            for (int j = 0; j < 4; ++j) sacc[nt][j] = 0.0f;
        #pragma unroll
        for (int ks = 0; ks < 4; ++ks) {
            #pragma unroll
            for (int ntp = 0; ntp < 4; ++ntp) {
                uint32_t off = (uint32_t)((ntp*16 + brow)*KPAD + ks*16 + bcol) * 2;
                uint32_t kh[4];
                LDSM4(kh, sK_u + off);
                mma16816(sacc[2*ntp],   qf[ks], kh[0], kh[1]);
                mma16816(sacc[2*ntp+1], qf[ks], kh[2], kh[3]);
            }
        }

        // online softmax
        #pragma unroll
        for (int nt = 0; nt < 8; ++nt)
            #pragma unroll
            for (int j = 0; j < 4; ++j) sacc[nt][j] *= isc;

        float mx0 = -1e30f, mx1 = -1e30f;
        #pragma unroll
        for (int nt = 0; nt < 8; ++nt) {
            mx0 = fmaxf(mx0, fmaxf(sacc[nt][0], sacc[nt][1]));
            mx1 = fmaxf(mx1, fmaxf(sacc[nt][2], sacc[nt][3]));
        }
        mx0 = fmaxf(mx0, __shfl_xor_sync(0xffffffffu, mx0, 1));
        mx0 = fmaxf(mx0, __shfl_xor_sync(0xffffffffu, mx0, 2));
        mx1 = fmaxf(mx1, __shfl_xor_sync(0xffffffffu, mx1, 1));
        mx1 = fmaxf(mx1, __shfl_xor_sync(0xffffffffu, mx1, 2));
        float mn0 = fmaxf(m0, mx0), mn1 = fmaxf(m1, mx1);
        float al0 = fexp(m0 - mn0), al1 = fexp(m1 - mn1);
        m0 = mn0; m1 = mn1;

        uint32_t pah[4][4];
        float ls0 = 0.0f, ls1 = 0.0f;
        #pragma unroll
        for (int nt = 0; nt < 8; ++nt) {
            float p0 = fexp(sacc[nt][0] - mn0);
            float p1 = fexp(sacc[nt][1] - mn0);
            float p2 = fexp(sacc[nt][2] - mn1);
            float p3 = fexp(sacc[nt][3] - mn1);
            ls0 += p0 + p1; ls1 += p2 + p3;
            int ks = nt >> 1, hf = (nt & 1) * 2;
            pah[ks][hf+0] = pack2h(p0, p1);
            pah[ks][hf+1] = pack2h(p2, p3);
        }
        ls0 += __shfl_xor_sync(0xffffffffu, ls0, 1);
        ls0 += __shfl_xor_sync(0xffffffffu, ls0, 2);
        ls1 += __shfl_xor_sync(0xffffffffu, ls1, 1);
        ls1 += __shfl_xor_sync(0xffffffffu, ls1, 2);
        l0 = l0*al0 + ls0; l1 = l1*al1 + ls1;
        #pragma unroll
        for (int dt = 0; dt < 8; ++dt) {
            oacc[dt][0] *= al0; oacc[dt][1] *= al0;
            oacc[dt][2] *= al1; oacc[dt][3] *= al1;
        }

        // O += P V
        #pragma unroll
        for (int ks = 0; ks < 4; ++ks) {
            #pragma unroll
            for (int dtp = 0; dtp < 4; ++dtp) {
                uint32_t off = (uint32_t)((ks*16 + vrow)*KPAD + dtp*16 + vcol) * 2;
                uint32_t vh[4];
                LDSM4T(vh, sV_u + off);
                mma16816(oacc[2*dtp],   pah[ks], vh[0], vh[1]);
                mma16816(oacc[2*dtp+1], pah[ks], vh[2], vh[3]);
            }
        }
    }

    // epilogue: write fp16 attention output (n,s,e)
    float inv0 = 1.0f / l0, inv1 = 1.0f / l1;
    int n = nh >> 3, hh = nh & 7;
    int row0 = qt*128 + warp*16 + lr;
    size_t b0 = ((size_t)n*S_ + row0)*E_ + hh*HD_;
    size_t b1 = b0 + (size_t)8*E_;
    #pragma unroll
    for (int dt = 0; dt < 8; ++dt) {
        int e = dt*8 + lc2;
        *(uint32_t*)(g_attnf + b0 + e) = pack2h(oacc[dt][0]*inv0, oacc[dt][1]*inv0);
        *(uint32_t*)(g_attnf + b1 + e) = pack2h(oacc[dt][2]*inv1, oacc[dt][3]*inv1);
    }
}

// ================= weight transpose + fp16 convert =================
__global__ __launch_bounds__(256) void wconv_kernel(
    const float* __restrict__ W, __half* __restrict__ out, int K, int N)
{
    __shared__ float t[32][33];
    size_t lstr = (size_t)K*N*blockIdx.z;
    const float* Wl = W + lstr;
    __half* ol = out + lstr;
    int kb = blockIdx.y*32, nb = blockIdx.x*32;
    int x = threadIdx.x, y0 = threadIdx.y;
    for (int y = y0; y < 32; y += 8)
        t[y][x] = Wl[(size_t)(kb+y)*N + nb + x];
    __syncthreads();
    for (int y = y0; y < 32; y += 8)
        ol[(size_t)(nb+y)*K + kb + x] = __float2half_rn(t[x][y]);
}

// ================= mma.sync GEMM: fp16, 4-stage BK=16, ldmatrix =================
#define ARR_B 6144
#define STG_B (2*ARR_B)
#define NSTG  4
#define GEMM_MMA_SMEM (NSTG*STG_B)

static __device__ __forceinline__ void mma_load_stage16(
    uint32_t sbase, int st,
    const __half* __restrict__ Af, const __half* __restrict__ Bf,
    int m0, int n0, int k0, int K, int tid)
{
    uint32_t s0 = sbase + st*STG_B;
    int r = tid >> 1, c = tid & 1;
    uint32_t off = (uint32_t)(r*48 + c*16);
    cp16(s0 +         off, Af + (size_t)(m0 + r)*K + k0 + c*8);
    cp16(s0 + ARR_B + off, Bf + (size_t)(n0 + r)*K + k0 + c*8);
    CP_COMMIT();
}

template<int RELU, int RESID, int HOUT>
__global__ __launch_bounds__(256, 2) void gemm_mma(
    const __half* __restrict__ Af, const __half* __restrict__ Bf,
    const float* __restrict__ bias, const float* __restrict__ Rres,
    float* __restrict__ Cf, __half* __restrict__ Ch,
    int Nn, int K)
{
    extern __shared__ __half sm[];
    uint32_t sbase = smem_u32(sm);
    int tid = threadIdx.x;
    int warp = tid >> 5, lane = tid & 31;
    int m0 = blockIdx.y * 128, n0 = blockIdx.x * 128;
    int wm0 = (warp & 3) * 32, wn0 = (warp >> 2) * 64;
    int lr = lane >> 2, lc2 = (lane & 3) * 2;

    int arow = lane & 15, acol = (lane >> 4) * 8;
    int brow = (lane & 7) + ((lane >> 4) << 3);
    int bcol = ((lane >> 3) & 1) * 8;

    float acc[2][8][4];
    #pragma unroll
    for (int a = 0; a < 2; ++a)
        #pragma unroll
        for (int b = 0; b < 8; ++b)
            #pragma unroll
            for (int c = 0; c < 4; ++c) acc[a][b][c] = 0.0f;

    int NKB = K >> 4;

    mma_load_stage16(sbase, 0, Af, Bf, m0, n0, 0,  K, tid);
    mma_load_stage16(sbase, 1, Af, Bf, m0, n0, 16, K, tid);
    mma_load_stage16(sbase, 2, Af, Bf, m0, n0, 32, K, tid);

    for (int kb = 0; kb < NKB; ++kb) {
        int st = kb & 3;
        CP_WAIT2();
        __syncthreads();

        uint32_t su = sbase + st*STG_B;
        uint32_t af[2][4];
        #pragma unroll
        for (int mt = 0; mt < 2; ++mt) {
            uint32_t ad = su + (uint32_t)((wm0 + mt*16 + arow)*48 + acol*2);
            LDSM4(af[mt], ad);
        }
        #pragma unroll
        for (int ntp = 0; ntp < 4; ++ntp) {
            uint32_t bd = su + ARR_B + (uint32_t)((wn0 + ntp*16 + brow)*48 + bcol*2);
            uint32_t bfr[4];
            LDSM4(bfr, bd);
            #pragma unroll
            for (int mt = 0; mt < 2; ++mt) {
                mma16816(acc[mt][2*ntp],   af[mt], bfr[0], bfr[1]);
                mma16816(acc[mt][2*ntp+1], af[mt], bfr[2], bfr[3]);
            }
        }
        if (kb + 3 < NKB)
            mma_load_stage16(sbase, (kb+3) & 3, Af, Bf, m0, n0, (kb+3)*16, K, tid);
    }

    #pragma unroll
    for (int mt = 0; mt < 2; ++mt) {
        #pragma unroll
        for (int half = 0; half < 2; ++half) {
            int m = m0 + wm0 + mt*16 + half*8 + lr;
            #pragma unroll
            for (int nt = 0; nt < 8; ++nt) {
                int c0 = n0 + wn0 + nt*8 + lc2;
                float2 bi = *(const float2*)(bias + c0);
                float v0 = acc[mt][nt][half*2+0] + bi.x;
                float v1 = acc[mt][nt][half*2+1] + bi.y;
                if (RESID) {
                    float2 rr = *(const float2*)(Rres + (size_t)m*Nn + c0);
                    v0 += rr.x; v1 += rr.y;
                }
                if (RELU) { v0 = fmaxf(v0, 0.f); v1 = fmaxf(v1, 0.f); }
                if (HOUT) {
                    *(uint32_t*)(Ch + (size_t)m*Nn + c0) = pack2h(v0, v1);
                } else {
                    *(float2*)(Cf + (size_t)m*Nn + c0) = make_float2(v0, v1);
                }
            }
        }
    }
}

// ================= small SIMT GEMM (final conv, N=64) =================
template<int FINAL>
__global__ __launch_bounds__(256) void gemm_kernel(
    const float* __restrict__ A, const float* __restrict__ B,
    const float* __restrict__ bias, float* __restrict__ C,
    int M, int Nn, int K)
{
    __shared__ float As[16][65];
    __shared__ float Bs[16][64];
    int m0 = blockIdx.y * 64, n0 = blockIdx.x * 64;
    int tid = threadIdx.x;
    int tx = tid & 15, ty = tid >> 4;

    int ar = tid >> 2;
    int ac = (tid & 3) * 4;
    int br = tid >> 4;
    int bc = (tid & 15) * 4;
    const float* Ap = A + (size_t)(m0 + ar)*K + ac;
    const float* Bp = B + (size_t)br*Nn + n0 + bc;

    float acc[4][4] = {};
    for (int k0 = 0; k0 < K; k0 += 16) {
        float4 a4 = *(const float4*)(Ap + k0);
        float4 b4 = *(const float4*)(Bp + (size_t)k0*Nn);
        As[ac+0][ar]=a4.x; As[ac+1][ar]=a4.y; As[ac+2][ar]=a4.z; As[ac+3][ar]=a4.w;
        *(float4*)&Bs[br][bc] = b4;
        __syncthreads();
        #pragma unroll
        for (int kk = 0; kk < 16; ++kk) {
            float a[4], b[4];
            #pragma unroll
            for (int i = 0; i < 4; ++i) a[i] = As[kk][ty + 16*i];
            #pragma unroll
            for (int j = 0; j < 4; ++j) b[j] = Bs[kk][tx + 16*j];
            #pragma unroll
            for (int i = 0; i < 4; ++i)
                #pragma unroll
                for (int j = 0; j < 4; ++j)
                    acc[i][j] = fmaf(a[i], b[j], acc[i][j]);
        }
        __syncthreads();
    }
    #pragma unroll
    for (int i = 0; i < 4; ++i) {
        int mrow = m0 + ty + 16*i;
        #pragma unroll
        for (int j = 0; j < 4; ++j) {
            int nn = n0 + tx + 16*j;
            float v = acc[i][j] + bias[nn];
            if (FINAL) {
                C[((size_t)(mrow >> 10)*O_ + nn)*S_ + (mrow & (S_-1))] = v;
            } else {
                C[(size_t)mrow*Nn + nn] = v;
            }
        }
    }
}

// ================= layernorm (optional fp16 output) =================
template<int HOUT>
__global__ __launch_bounds__(128) void ln_kernel(
    const float* __restrict__ in, float* __restrict__ out,
    const float* __restrict__ g, const float* __restrict__ b,
    __half* __restrict__ oh)
{
    int row = blockIdx.x;
    int t = threadIdx.x;
    const float* p = in + (size_t)row*E_;
    float v[4], s = 0.0f, sq = 0.0f;
    #pragma unroll
    for (int q = 0; q < 4; ++q) {
        v[q] = p[t + 128*q];
        s += v[q]; sq += v[q]*v[q];
    }
    #pragma unroll
    for (int off = 16; off; off >>= 1) {
        s  += __shfl_xor_sync(0xffffffffu, s,  off);
        sq += __shfl_xor_sync(0xffffffffu, sq, off);
    }
    __shared__ float red[2][4];
    int w = t >> 5;
    if ((t & 31) == 0) { red[0][w] = s; red[1][w] = sq; }
    __syncthreads();
    s  = red[0][0] + red[0][1] + red[0][2] + red[0][3];
    sq = red[1][0] + red[1][1] + red[1][2] + red[1][3];
    float mean = s * (1.0f/E_);
    float var = sq * (1.0f/E_) - mean*mean;
    float inv = rsqrtf(var + 1e-5f);
    float* q_ = out + (size_t)row*E_;
    #pragma unroll
    for (int q = 0; q < 4; ++q) {
        int e = t + 128*q;
        float val = (v[q] - mean)*inv*g[e] + b[e];
        q_[e] = val;
        if (HOUT) oh[(size_t)row*E_ + e] = __float2half_rn(val);
    }
}

// ================= launch =================
extern "C" void kernel_launch(void* const* d_in, const int* in_sizes, int n_in,
                              void* d_out, int out_size)
{
    const float* x       = (const float*)d_in[0];
    const float* W_first = (const float*)d_in[1];
    const float* b_first = (const float*)d_in[2];
    const float* pos_emb = (const float*)d_in[3];
    const float* Wq      = (const float*)d_in[4];
    const float* bq      = (const float*)d_in[5];
    const float* Wk      = (const float*)d_in[6];
    const float* bk      = (const float*)d_in[7];
    const float* Wv      = (const float*)d_in[8];
    const float* bv      = (const float*)d_in[9];
    const float* Wo      = (const float*)d_in[10];
    const float* bo      = (const float*)d_in[11];
    const float* g1      = (const float*)d_in[12];
    const float* be1     = (const float*)d_in[13];
    const float* Wf1     = (const float*)d_in[14];
    const float* bf1     = (const float*)d_in[15];
    const float* Wf2     = (const float*)d_in[16];
    const float* bf2     = (const float*)d_in[17];
    const float* g2      = (const float*)d_in[18];
    const float* be2     = (const float*)d_in[19];
    const float* Wfin    = (const float*)d_in[20];
    const float* bfin    = (const float*)d_in[21];
    (void)in_sizes; (void)n_in; (void)out_size;

    cudaFuncSetAttribute(gemm_mma<0,1,0>, cudaFuncAttributeMaxDynamicSharedMemorySize, GEMM_MMA_SMEM);
    cudaFuncSetAttribute(gemm_mma<1,0,1>, cudaFuncAttributeMaxDynamicSharedMemorySize, GEMM_MMA_SMEM);
    cudaFuncSetAttribute(attn_kernel, cudaFuncAttributeMaxDynamicSharedMemorySize, ATT_SMEM);

    float *h_p, *buf_p, *hx_p;
    cudaGetSymbolAddress((void**)&h_p,   g_h);
    cudaGetSymbolAddress((void**)&buf_p, g_buf);
    cudaGetSymbolAddress((void**)&hx_p,  g_hx);
    __half *hf_p, *attnf, *hxf, *fff, *wotf, *wf1tf, *wf2tf, *wqtf, *wktf, *wvtf;
    cudaGetSymbolAddress((void**)&hf_p,  g_hf);
    cudaGetSymbolAddress((void**)&attnf, g_attnf);
    cudaGetSymbolAddress((void**)&hxf,   g_hxf);
    cudaGetSymbolAddress((void**)&fff,   g_fff);
    cudaGetSymbolAddress((void**)&wotf,  g_wotf);
    cudaGetSymbolAddress((void**)&wf1tf, g_wf1tf);
    cudaGetSymbolAddress((void**)&wf2tf, g_wf2tf);
    cudaGetSymbolAddress((void**)&wqtf,  g_wqtf);
    cudaGetSymbolAddress((void**)&wktf,  g_wktf);
    cudaGetSymbolAddress((void**)&wvtf,  g_wvtf);

    // weight prep: transpose + fp16 convert (all layers)
    wconv_kernel<<<dim3(E_/32,  E_/32,  L_), dim3(32,8)>>>(Wo,  wotf,  E_,  E_);
    wconv_kernel<<<dim3(FF_/32, E_/32,  L_), dim3(32,8)>>>(Wf1, wf1tf, E_,  FF_);
    wconv_kernel<<<dim3(E_/32,  FF_/32, L_), dim3(32,8)>>>(Wf2, wf2tf, FF_, E_);
    wconv_kernel<<<dim3(HD_/32, HD_/32, L_), dim3(32,8)>>>(Wq,  wqtf,  HD_, HD_);
    wconv_kernel<<<dim3(HD_/32, HD_/32, L_), dim3(32,8)>>>(Wk,  wktf,  HD_, HD_);
    wconv_kernel<<<dim3(HD_/32, HD_/32, L_), dim3(32,8)>>>(Wv,  wvtf,  HD_, HD_);

    xt_kernel<<<dim3(S_/32, F_/32, N_), dim3(32,8)>>>(x);
    embed_kernel<<<NS_, 512>>>(W_first, b_first, pos_emb);

    for (int i = 0; i < L_; ++i) {
        qkv_mma<<<dim3(S_/128, N_*H_), 256>>>(
            wqtf + i*HD_*HD_, wktf + i*HD_*HD_, wvtf + i*HD_*HD_,
            bq + i*HD_, bk + i*HD_, bv + i*HD_);
        attn_kernel<<<N_*H_*8, 256, ATT_SMEM>>>();

        gemm_mma<0,1,0><<<dim3(E_/128, NS_/128), 256, GEMM_MMA_SMEM>>>(
            attnf, wotf + (size_t)i*E_*E_,
            bo + i*E_, h_p, buf_p, (__half*)0, E_, E_);
        ln_kernel<1><<<NS_, 128>>>(buf_p, hx_p, g1 + i*E_, be1 + i*E_, hxf);

        gemm_mma<1,0,1><<<dim3(FF_/128, NS_/128), 256, GEMM_MMA_SMEM>>>(
            hxf, wf1tf + (size_t)i*(size_t)E_*FF_,
            bf1 + i*FF_, (const float*)0, (float*)0, fff, FF_, E_);

        gemm_mma<0,1,0><<<dim3(E_/128, NS_/128), 256, GEMM_MMA_SMEM>>>(
            fff, wf2tf + (size_t)i*(size_t)FF_*E_,
            bf2 + i*E_, hx_p, buf_p, (__half*)0, E_, FF_);
        ln_kernel<1><<<NS_, 128>>>(buf_p, h_p, g2 + i*E_, be2 + i*E_, hf_p);
    }

    gemm_kernel<1><<<dim3(O_/64, NS_/64), 256>>>(
        h_p, Wfin, bfin, (float*)d_out, NS_, O_, E_);
}

// round 12
// speedup vs baseline: 7.5716x; 1.0386x over previous
#include <cuda_runtime.h>
#include <cuda_fp16.h>
#include <math.h>
#include <stdint.h>

#define N_ 8
#define S_ 1024
#define F_ 64
#define E_ 512
#define H_ 8
#define HD_ 64
#define O_ 64
#define L_ 6
#define FF_ 2048
#define NS_ (N_*S_)

// ---------------- scratch (no allocations allowed) ----------------
__device__ float g_h[NS_*E_];       // running hidden state (n,s,e) fp32 (residual)
__device__ float g_buf[NS_*E_];     // pre-LN sum
__device__ float g_hx[NS_*E_];      // post-LN1 (fp32 residual for FF2)

__device__ __half g_xtf[NS_*F_];    // transposed input (n,s,f) fp16
__device__ __half g_hf[NS_*E_];     // fp16 copy of hidden state (qkv input)

// fp16 q/k/v in (n,h,s,d)  (q pre-scaled by 1/sqrt(E))
__device__ __half g_qf[NS_*E_], g_kf[NS_*E_], g_vf[NS_*E_];

// fp16 activations
__device__ __half g_attnf[NS_*E_];
__device__ __half g_hxf[NS_*E_];
__device__ __half g_fff[NS_*FF_];

// fp16 transposed weights
__device__ __half g_wotf[L_*E_*E_];
__device__ __half g_wf1tf[L_*E_*FF_];
__device__ __half g_wf2tf[L_*FF_*E_];
__device__ __half g_wqtf[L_*HD_*HD_], g_wktf[L_*HD_*HD_], g_wvtf[L_*HD_*HD_];
__device__ __half g_wftf[E_*F_];    // W_first^T fp16 [E][F]

#define ISC 0.044194173824159216f   /* 1/sqrt(E) */

// ================= helpers =================
static __device__ __forceinline__ uint32_t smem_u32(const void* p){
    uint32_t a;
    asm("{ .reg .u64 t; cvta.to.shared.u64 t, %1; cvt.u32.u64 %0, t; }" : "=r"(a) : "l"(p));
    return a;
}
static __device__ __forceinline__ void cp16(uint32_t dst, const void* src){
    asm volatile("cp.async.cg.shared.global [%0], [%1], 16;" :: "r"(dst), "l"(src));
}
#define CP_COMMIT() asm volatile("cp.async.commit_group;" ::: "memory")
#define CP_WAIT0()  asm volatile("cp.async.wait_group 0;" ::: "memory")
#define CP_WAIT1()  asm volatile("cp.async.wait_group 1;" ::: "memory")
#define CP_WAIT2()  asm volatile("cp.async.wait_group 2;" ::: "memory")

#define LDSM4(r, a) \
    asm volatile("ldmatrix.sync.aligned.m8n8.x4.shared.b16 {%0,%1,%2,%3}, [%4];" \
        : "=r"((r)[0]), "=r"((r)[1]), "=r"((r)[2]), "=r"((r)[3]) : "r"(a))
#define LDSM4T(r, a) \
    asm volatile("ldmatrix.sync.aligned.m8n8.x4.trans.shared.b16 {%0,%1,%2,%3}, [%4];" \
        : "=r"((r)[0]), "=r"((r)[1]), "=r"((r)[2]), "=r"((r)[3]) : "r"(a))

static __device__ __forceinline__ void mma16816(
    float* d, const uint32_t* a, uint32_t b0, uint32_t b1)
{
    asm volatile("mma.sync.aligned.m16n8k16.row.col.f32.f16.f16.f32 "
        "{%0,%1,%2,%3}, {%4,%5,%6,%7}, {%8,%9}, {%0,%1,%2,%3};"
        : "+f"(d[0]), "+f"(d[1]), "+f"(d[2]), "+f"(d[3])
        : "r"(a[0]), "r"(a[1]), "r"(a[2]), "r"(a[3]), "r"(b0), "r"(b1));
}

static __device__ __forceinline__ uint32_t pack2h(float a, float b){
    __half2 t = __floats2half2_rn(a, b);
    return *(uint32_t*)&t;
}

// fast exp on fma/alu pipes (no MUFU)
static __device__ __forceinline__ float fexp(float x){
    x = fmaxf(x, -87.0f);
    float t = x * 1.4426950408889634f;
    float z = t + 12582912.0f;
    int   i = __float_as_int(z) - 0x4B400000;
    float f = t - (z - 12582912.0f);
    float xf = f * 0.6931471805599453f;
    float p = fmaf(xf, 0.0083333333f, 0.0416666667f);
    p = fmaf(xf, p, 0.1666666667f);
    p = fmaf(xf, p, 0.5f);
    p = fmaf(xf, p, 1.0f);
    p = fmaf(xf, p, 1.0f);
    return p * __int_as_float((i + 127) << 23);
}

// ================= x transpose: x[n][f][s] -> xtf[n][s][f] fp16 =================
__global__ __launch_bounds__(256) void xt_kernel(const float* __restrict__ x)
{
    __shared__ float t[32][33];
    int n = blockIdx.z;
    int s0 = blockIdx.x * 32, f0 = blockIdx.y * 32;
    int tx = threadIdx.x, ty = threadIdx.y;
    for (int y = ty; y < 32; y += 8)
        t[y][tx] = x[(size_t)n*F_*S_ + (size_t)(f0 + y)*S_ + s0 + tx];
    __syncthreads();
    for (int y = ty; y < 32; y += 8)
        g_xtf[((size_t)n*S_ + s0 + y)*F_ + f0 + tx] = __float2half_rn(t[tx][y]);
}

// ================= weight transpose + fp16 convert =================
__global__ __launch_bounds__(256) void wconv_kernel(
    const float* __restrict__ W, __half* __restrict__ out, int K, int N)
{
    __shared__ float t[32][33];
    size_t lstr = (size_t)K*N*blockIdx.z;
    const float* Wl = W + lstr;
    __half* ol = out + lstr;
    int kb = blockIdx.y*32, nb = blockIdx.x*32;
    int x = threadIdx.x, y0 = threadIdx.y;
    for (int y = y0; y < 32; y += 8)
        t[y][x] = Wl[(size_t)(kb+y)*N + nb + x];
    __syncthreads();
    for (int y = y0; y < 32; y += 8)
        ol[(size_t)(nb+y)*K + kb + x] = __float2half_rn(t[x][y]);
}

// merged Wq/Wk/Wv prep: z = mat*L + layer
__global__ __launch_bounds__(256) void wconv_qkv_kernel(
    const float* __restrict__ Wq, const float* __restrict__ Wk,
    const float* __restrict__ Wv)
{
    __shared__ float t[32][33];
    int mat = blockIdx.z / L_, layer = blockIdx.z % L_;
    const float* W = (mat == 0) ? Wq : (mat == 1) ? Wk : Wv;
    __half* out = (mat == 0) ? g_wqtf : (mat == 1) ? g_wktf : g_wvtf;
    size_t lstr = (size_t)HD_*HD_*layer;
    const float* Wl = W + lstr;
    __half* ol = out + lstr;
    int kb = blockIdx.y*32, nb = blockIdx.x*32;
    int x = threadIdx.x, y0 = threadIdx.y;
    for (int y = y0; y < 32; y += 8)
        t[y][x] = Wl[(size_t)(kb+y)*HD_ + nb + x];
    __syncthreads();
    for (int y = y0; y < 32; y += 8)
        ol[(size_t)(nb+y)*HD_ + kb + x] = __float2half_rn(t[x][y]);
}

// ================= kernel 2: QKV projection on tensor cores =================
#define QPT 72
__global__ __launch_bounds__(256) void qkv_mma(
    const __half* __restrict__ Wqt, const __half* __restrict__ Wkt,
    const __half* __restrict__ Wvt,
    const float* __restrict__ bq, const float* __restrict__ bk,
    const float* __restrict__ bv)
{
    __shared__ __half sA[128*QPT];
    __shared__ __half sW[3*64*QPT];

    int s0 = blockIdx.x * 128;
    int nh = blockIdx.y;
    int n = nh >> 3, hh = nh & 7;
    int tid = threadIdx.x;
    int warp = tid >> 5, lane = tid & 31;
    int lr = lane >> 2, lc2 = (lane & 3) * 2;
    int arow = lane & 15, acol = (lane >> 4) * 8;
    int brow = (lane & 7) + ((lane >> 4) << 3);
    int bcol = ((lane >> 3) & 1) * 8;

    #pragma unroll
    for (int i = 0; i < 4; ++i) {
        int id = tid + 256*i;
        int r = id >> 3, c = id & 7;
        *(float4*)&sA[r*QPT + c*8] =
            *(const float4*)(g_hf + ((size_t)n*S_ + s0 + r)*E_ + hh*HD_ + c*8);
    }
    #pragma unroll
    for (int i = 0; i < 6; ++i) {
        int id = tid + 256*i;
        int mat = id >> 9, rr = (id >> 3) & 63, c = id & 7;
        const __half* src = (mat == 0) ? Wqt : (mat == 1) ? Wkt : Wvt;
        *(float4*)&sW[mat*64*QPT + rr*QPT + c*8] = *(const float4*)(src + rr*HD_ + c*8);
    }
    __syncthreads();

    uint32_t sA_u = smem_u32(sA), sW_u = smem_u32(sW);
    #pragma unroll
    for (int mat = 0; mat < 3; ++mat) {
        float acc[8][4];
        #pragma unroll
        for (int nt = 0; nt < 8; ++nt)
            #pragma unroll
            for (int j = 0; j < 4; ++j) acc[nt][j] = 0.0f;
        #pragma unroll
        for (int ks = 0; ks < 4; ++ks) {
            uint32_t af[4];
            LDSM4(af, sA_u + (uint32_t)((warp*16 + arow)*QPT + ks*16 + acol)*2);
            #pragma unroll
            for (int ntp = 0; ntp < 4; ++ntp) {
                uint32_t bfr[4];
                LDSM4(bfr, sW_u + (uint32_t)(mat*64*QPT + (ntp*16 + brow)*QPT + ks*16 + bcol)*2);
                mma16816(acc[2*ntp],   af, bfr[0], bfr[1]);
                mma16816(acc[2*ntp+1], af, bfr[2], bfr[3]);
            }
        }
        const float* bias = (mat == 0) ? bq : (mat == 1) ? bk : bv;
        __half* dst = (mat == 0) ? g_qf : (mat == 1) ? g_kf : g_vf;
        float sc = (mat == 0) ? ISC : 1.0f;     // pre-scale q by 1/sqrt(E)
        size_t rb0 = ((size_t)nh*S_ + s0 + warp*16 + lr)*HD_;
        size_t rb1 = rb0 + 8*HD_;
        #pragma unroll
        for (int nt = 0; nt < 8; ++nt) {
            int c0 = nt*8 + lc2;
            float2 bi = *(const float2*)(bias + c0);
            *(uint32_t*)(dst + rb0 + c0) = pack2h((acc[nt][0] + bi.x)*sc, (acc[nt][1] + bi.y)*sc);
            *(uint32_t*)(dst + rb1 + c0) = pack2h((acc[nt][2] + bi.x)*sc, (acc[nt][3] + bi.y)*sc);
        }
    }
}

// ================= kernel 3: flash attention, 3-stage cp.async K/V =================
#define KPAD 72
#define ATT_STG_B (2*64*KPAD*2)        /* bytes per stage (K + V) = 18432 */
#define ATT_SMEM (3*ATT_STG_B)         /* 55296 bytes */

static __device__ __forceinline__ void attn_load_kv(
    uint32_t sbase, int st, size_t qkv_base, int kt, int tid)
{
    uint32_t s0 = sbase + (uint32_t)st*ATT_STG_B;
    #pragma unroll
    for (int i = 0; i < 2; ++i) {
        int id = tid + 256*i;
        int r = id >> 3, c = id & 7;
        size_t g = qkv_base + (size_t)(kt*64 + r)*HD_ + c*8;
        cp16(s0 +              r*(KPAD*2) + c*16, g_kf + g);
        cp16(s0 + 64*KPAD*2 +  r*(KPAD*2) + c*16, g_vf + g);
    }
    CP_COMMIT();
}

__global__ __launch_bounds__(256) void attn_kernel()
{
    extern __shared__ __half smA[];
    uint32_t sbase = smem_u32(smA);

    int bid = blockIdx.x;
    int qt = bid & 7;
    int nh = bid >> 3;
    int tid = threadIdx.x;
    int warp = tid >> 5, lane = tid & 31;
    int lr = lane >> 2, lc2 = (lane & 3) * 2;

    int brow = (lane & 7) + ((lane >> 4) << 3);
    int bcol = ((lane >> 3) & 1) * 8;
    int vrow = ((lane >> 3) & 1) * 8 + (lane & 7);
    int vcol = (lane >> 4) * 8;

    size_t qkv_base = (size_t)nh * S_ * HD_;
    int qrow0 = qt*128 + warp*16;

    uint32_t qf[4][4];
    #pragma unroll
    for (int ks = 0; ks < 4; ++ks) {
        int d = ks*16 + lc2;
        size_t r0 = qkv_base + (size_t)(qrow0 + lr)*HD_;
        size_t r1 = qkv_base + (size_t)(qrow0 + lr + 8)*HD_;
        qf[ks][0] = *(const uint32_t*)(g_qf + r0 + d);
        qf[ks][1] = *(const uint32_t*)(g_qf + r1 + d);
        qf[ks][2] = *(const uint32_t*)(g_qf + r0 + d + 8);
        qf[ks][3] = *(const uint32_t*)(g_qf + r1 + d + 8);
    }

    float oacc[8][4];
    #pragma unroll
    for (int dt = 0; dt < 8; ++dt)
        #pragma unroll
        for (int j = 0; j < 4; ++j) oacc[dt][j] = 0.0f;
    float m0 = -1e30f, m1 = -1e30f, l0 = 0.0f, l1 = 0.0f;

    attn_load_kv(sbase, 0, qkv_base, 0, tid);
    attn_load_kv(sbase, 1, qkv_base, 1, tid);

    for (int kt = 0; kt < 16; ++kt) {
        if (kt == 15) { CP_WAIT0(); } else { CP_WAIT1(); }
        __syncthreads();          // all warps done with the stage being overwritten next
        if (kt + 2 < 16)
            attn_load_kv(sbase, (kt+2) % 3, qkv_base, kt+2, tid);

        uint32_t sK_u = sbase + (uint32_t)(kt % 3)*ATT_STG_B;
        uint32_t sV_u = sK_u + 64*KPAD*2;

        // S = Q K^T  (q pre-scaled)
        float sacc[8][4];
        #pragma unroll
        for (int nt = 0; nt < 8; ++nt)
            #pragma unroll
            for (int j = 0; j < 4; ++j) sacc[nt][j] = 0.0f;
        #pragma unroll
        for (int ks = 0; ks < 4; ++ks) {
            #pragma unroll
            for (int ntp = 0; ntp < 4; ++ntp) {
                uint32_t off = (uint32_t)((ntp*16 + brow)*KPAD + ks*16 + bcol) * 2;
                uint32_t kh[4];
                LDSM4(kh, sK_u + off);
                mma16816(sacc[2*ntp],   qf[ks], kh[0], kh[1]);
                mma16816(sacc[2*ntp+1], qf[ks], kh[2], kh[3]);
            }
        }

        // online softmax
        float mx0 = -1e30f, mx1 = -1e30f;
        #pragma unroll
        for (int nt = 0; nt < 8; ++nt) {
            mx0 = fmaxf(mx0, fmaxf(sacc[nt][0], sacc[nt][1]));
            mx1 = fmaxf(mx1, fmaxf(sacc[nt][2], sacc[nt][3]));
        }
        mx0 = fmaxf(mx0, __shfl_xor_sync(0xffffffffu, mx0, 1));
        mx0 = fmaxf(mx0, __shfl_xor_sync(0xffffffffu, mx0, 2));
        mx1 = fmaxf(mx1, __shfl_xor_sync(0xffffffffu, mx1, 1));
        mx1 = fmaxf(mx1, __shfl_xor_sync(0xffffffffu, mx1, 2));
        float mn0 = fmaxf(m0, mx0), mn1 = fmaxf(m1, mx1);
        float al0 = fexp(m0 - mn0), al1 = fexp(m1 - mn1);
        m0 = mn0; m1 = mn1;

        uint32_t pah[4][4];
        float ls0 = 0.0f, ls1 = 0.0f;
        #pragma unroll
        for (int nt = 0; nt < 8; ++nt) {
            float p0 = fexp(sacc[nt][0] - mn0);
            float p1 = fexp(sacc[nt][1] - mn0);
            float p2 = fexp(sacc[nt][2] - mn1);
            float p3 = fexp(sacc[nt][3] - mn1);
            ls0 += p0 + p1; ls1 += p2 + p3;
            int ks = nt >> 1, hf = (nt & 1) * 2;
            pah[ks][hf+0] = pack2h(p0, p1);
            pah[ks][hf+1] = pack2h(p2, p3);
        }
        ls0 += __shfl_xor_sync(0xffffffffu, ls0, 1);
        ls0 += __shfl_xor_sync(0xffffffffu, ls0, 2);
        ls1 += __shfl_xor_sync(0xffffffffu, ls1, 1);
        ls1 += __shfl_xor_sync(0xffffffffu, ls1, 2);
        l0 = l0*al0 + ls0; l1 = l1*al1 + ls1;
        #pragma unroll
        for (int dt = 0; dt < 8; ++dt) {
            oacc[dt][0] *= al0; oacc[dt][1] *= al0;
            oacc[dt][2] *= al1; oacc[dt][3] *= al1;
        }

        // O += P V
        #pragma unroll
        for (int ks = 0; ks < 4; ++ks) {
            #pragma unroll
            for (int dtp = 0; dtp < 4; ++dtp) {
                uint32_t off = (uint32_t)((ks*16 + vrow)*KPAD + dtp*16 + vcol) * 2;
                uint32_t vh[4];
                LDSM4T(vh, sV_u + off);
                mma16816(oacc[2*dtp],   pah[ks], vh[0], vh[1]);
                mma16816(oacc[2*dtp+1], pah[ks], vh[2], vh[3]);
            }
        }
    }

    float inv0 = 1.0f / l0, inv1 = 1.0f / l1;
    int n = nh >> 3, hh = nh & 7;
    int row0 = qt*128 + warp*16 + lr;
    size_t b0 = ((size_t)n*S_ + row0)*E_ + hh*HD_;
    size_t b1 = b0 + (size_t)8*E_;
    #pragma unroll
    for (int dt = 0; dt < 8; ++dt) {
        int e = dt*8 + lc2;
        *(uint32_t*)(g_attnf + b0 + e) = pack2h(oacc[dt][0]*inv0, oacc[dt][1]*inv0);
        *(uint32_t*)(g_attnf + b1 + e) = pack2h(oacc[dt][2]*inv1, oacc[dt][3]*inv1);
    }
}

// ================= mma.sync GEMM: fp16, 4-stage BK=16, ldmatrix =================
// EMBED: epilogue = relu(acc+bias) + pos_emb (Rres = pos base, row = m & (S-1)),
//        writes BOTH fp32 Cf and fp16 Ch.
#define ARR_B 6144
#define STG_B (2*ARR_B)
#define NSTG  4
#define GEMM_MMA_SMEM (NSTG*STG_B)

static __device__ __forceinline__ void mma_load_stage16(
    uint32_t sbase, int st,
    const __half* __restrict__ Af, const __half* __restrict__ Bf,
    int m0, int n0, int k0, int K, int tid)
{
    uint32_t s0 = sbase + st*STG_B;
    int r = tid >> 1, c = tid & 1;
    uint32_t off = (uint32_t)(r*48 + c*16);
    cp16(s0 +         off, Af + (size_t)(m0 + r)*K + k0 + c*8);
    cp16(s0 + ARR_B + off, Bf + (size_t)(n0 + r)*K + k0 + c*8);
    CP_COMMIT();
}

template<int RELU, int RESID, int HOUT, int EMBED>
__global__ __launch_bounds__(256, 2) void gemm_mma(
    const __half* __restrict__ Af, const __half* __restrict__ Bf,
    const float* __restrict__ bias, const float* __restrict__ Rres,
    float* __restrict__ Cf, __half* __restrict__ Ch,
    int Nn, int K)
{
    extern __shared__ __half sm[];
    uint32_t sbase = smem_u32(sm);
    int tid = threadIdx.x;
    int warp = tid >> 5, lane = tid & 31;
    int m0 = blockIdx.y * 128, n0 = blockIdx.x * 128;
    int wm0 = (warp & 3) * 32, wn0 = (warp >> 2) * 64;
    int lr = lane >> 2, lc2 = (lane & 3) * 2;

    int arow = lane & 15, acol = (lane >> 4) * 8;
    int brow = (lane & 7) + ((lane >> 4) << 3);
    int bcol = ((lane >> 3) & 1) * 8;

    float acc[2][8][4];
    #pragma unroll
    for (int a = 0; a < 2; ++a)
        #pragma unroll
        for (int b = 0; b < 8; ++b)
            #pragma unroll
            for (int c = 0; c < 4; ++c) acc[a][b][c] = 0.0f;

    int NKB = K >> 4;

    mma_load_stage16(sbase, 0, Af, Bf, m0, n0, 0,  K, tid);
    mma_load_stage16(sbase, 1, Af, Bf, m0, n0, 16, K, tid);
    mma_load_stage16(sbase, 2, Af, Bf, m0, n0, 32, K, tid);

    for (int kb = 0; kb < NKB; ++kb) {
        int st = kb & 3;
        if (kb >= NKB-3) { CP_WAIT0(); } else { CP_WAIT2(); }
        __syncthreads();

        uint32_t su = sbase + st*STG_B;
        uint32_t af[2][4];
        #pragma unroll
        for (int mt = 0; mt < 2; ++mt) {
            uint32_t ad = su + (uint32_t)((wm0 + mt*16 + arow)*48 + acol*2);
            LDSM4(af[mt], ad);
        }
        #pragma unroll
        for (int ntp = 0; ntp < 4; ++ntp) {
            uint32_t bd = su + ARR_B + (uint32_t)((wn0 + ntp*16 + brow)*48 + bcol*2);
            uint32_t bfr[4];
            LDSM4(bfr, bd);
            #pragma unroll
            for (int mt = 0; mt < 2; ++mt) {
                mma16816(acc[mt][2*ntp],   af[mt], bfr[0], bfr[1]);
                mma16816(acc[mt][2*ntp+1], af[mt], bfr[2], bfr[3]);
            }
        }
        if (kb + 3 < NKB)
            mma_load_stage16(sbase, (kb+3) & 3, Af, Bf, m0, n0, (kb+3)*16, K, tid);
    }

    #pragma unroll
    for (int mt = 0; mt < 2; ++mt) {
        #pragma unroll
        for (int half = 0; half < 2; ++half) {
            int m = m0 + wm0 + mt*16 + half*8 + lr;
            #pragma unroll
            for (int nt = 0; nt < 8; ++nt) {
                int c0 = n0 + wn0 + nt*8 + lc2;
                float2 bi = *(const float2*)(bias + c0);
                float v0 = acc[mt][nt][half*2+0] + bi.x;
                float v1 = acc[mt][nt][half*2+1] + bi.y;
                if (EMBED) {
                    int s = m & (S_-1);
                    float2 pe = *(const float2*)(Rres + (size_t)s*Nn + c0);
                    v0 = fmaxf(v0, 0.f) + pe.x;
                    v1 = fmaxf(v1, 0.f) + pe.y;
                    *(float2*)(Cf + (size_t)m*Nn + c0) = make_float2(v0, v1);
                    *(uint32_t*)(Ch + (size_t)m*Nn + c0) = pack2h(v0, v1);
                } else {
                    if (RESID) {
                        float2 rr = *(const float2*)(Rres + (size_t)m*Nn + c0);
                        v0 += rr.x; v1 += rr.y;
                    }
                    if (RELU) { v0 = fmaxf(v0, 0.f); v1 = fmaxf(v1, 0.f); }
                    if (HOUT) {
                        *(uint32_t*)(Ch + (size_t)m*Nn + c0) = pack2h(v0, v1);
                    } else {
                        *(float2*)(Cf + (size_t)m*Nn + c0) = make_float2(v0, v1);
                    }
                }
            }
        }
    }
}

// ================= small SIMT GEMM (final conv, N=64) =================
template<int FINAL>
__global__ __launch_bounds__(256) void gemm_kernel(
    const float* __restrict__ A, const float* __restrict__ B,
    const float* __restrict__ bias, float* __restrict__ C,
    int M, int Nn, int K)
{
    __shared__ float As[16][65];
    __shared__ float Bs[16][64];
    int m0 = blockIdx.y * 64, n0 = blockIdx.x * 64;
    int tid = threadIdx.x;
    int tx = tid & 15, ty = tid >> 4;

    int ar = tid >> 2;
    int ac = (tid & 3) * 4;
    int br = tid >> 4;
    int bc = (tid & 15) * 4;
    const float* Ap = A + (size_t)(m0 + ar)*K + ac;
    const float* Bp = B + (size_t)br*Nn + n0 + bc;

    float acc[4][4] = {};
    for (int k0 = 0; k0 < K; k0 += 16) {
        float4 a4 = *(const float4*)(Ap + k0);
        float4 b4 = *(const float4*)(Bp + (size_t)k0*Nn);
        As[ac+0][ar]=a4.x; As[ac+1][ar]=a4.y; As[ac+2][ar]=a4.z; As[ac+3][ar]=a4.w;
        *(float4*)&Bs[br][bc] = b4;
        __syncthreads();
        #pragma unroll
        for (int kk = 0; kk < 16; ++kk) {
            float a[4], b[4];
            #pragma unroll
            for (int i = 0; i < 4; ++i) a[i] = As[kk][ty + 16*i];
            #pragma unroll
            for (int j = 0; j < 4; ++j) b[j] = Bs[kk][tx + 16*j];
            #pragma unroll
            for (int i = 0; i < 4; ++i)
                #pragma unroll
                for (int j = 0; j < 4; ++j)
                    acc[i][j] = fmaf(a[i], b[j], acc[i][j]);
        }
        __syncthreads();
    }
    #pragma unroll
    for (int i = 0; i < 4; ++i) {
        int mrow = m0 + ty + 16*i;
        #pragma unroll
        for (int j = 0; j < 4; ++j) {
            int nn = n0 + tx + 16*j;
            float v = acc[i][j] + bias[nn];
            if (FINAL) {
                C[((size_t)(mrow >> 10)*O_ + nn)*S_ + (mrow & (S_-1))] = v;
            } else {
                C[(size_t)mrow*Nn + nn] = v;
            }
        }
    }
}

// ================= layernorm, float4-vectorized (optional fp16 output) =================
template<int HOUT>
__global__ __launch_bounds__(128) void ln_kernel(
    const float* __restrict__ in, float* __restrict__ out,
    const float* __restrict__ g, const float* __restrict__ b,
    __half* __restrict__ oh)
{
    int row = blockIdx.x;
    int t = threadIdx.x;
    const float* p = in + (size_t)row*E_;
    float4 v4 = *(const float4*)(p + t*4);
    float s  = v4.x + v4.y + v4.z + v4.w;
    float sq = v4.x*v4.x + v4.y*v4.y + v4.z*v4.z + v4.w*v4.w;
    #pragma unroll
    for (int off = 16; off; off >>= 1) {
        s  += __shfl_xor_sync(0xffffffffu, s,  off);
        sq += __shfl_xor_sync(0xffffffffu, sq, off);
    }
    __shared__ float red[2][4];
    int w = t >> 5;
    if ((t & 31) == 0) { red[0][w] = s; red[1][w] = sq; }
    __syncthreads();
    s  = red[0][0] + red[0][1] + red[0][2] + red[0][3];
    sq = red[1][0] + red[1][1] + red[1][2] + red[1][3];
    float mean = s * (1.0f/E_);
    float var = sq * (1.0f/E_) - mean*mean;
    float inv = rsqrtf(var + 1e-5f);
    float4 g4 = *(const float4*)(g + t*4);
    float4 b4 = *(const float4*)(b + t*4);
    float4 o4;
    o4.x = (v4.x - mean)*inv*g4.x + b4.x;
    o4.y = (v4.y - mean)*inv*g4.y + b4.y;
    o4.z = (v4.z - mean)*inv*g4.z + b4.z;
    o4.w = (v4.w - mean)*inv*g4.w + b4.w;
    *(float4*)(out + (size_t)row*E_ + t*4) = o4;
    if (HOUT) {
        uint2 h2;
        h2.x = pack2h(o4.x, o4.y);
        h2.y = pack2h(o4.z, o4.w);
        *(uint2*)(oh + (size_t)row*E_ + t*4) = h2;
    }
}

// ================= launch =================
extern "C" void kernel_launch(void* const* d_in, const int* in_sizes, int n_in,
                              void* d_out, int out_size)
{
    const float* x       = (const float*)d_in[0];
    const float* W_first = (const float*)d_in[1];
    const float* b_first = (const float*)d_in[2];
    const float* pos_emb = (const float*)d_in[3];
    const float* Wq      = (const float*)d_in[4];
    const float* bq      = (const float*)d_in[5];
    const float* Wk      = (const float*)d_in[6];
    const float* bk      = (const float*)d_in[7];
    const float* Wv      = (const float*)d_in[8];
    const float* bv      = (const float*)d_in[9];
    const float* Wo      = (const float*)d_in[10];
    const float* bo      = (const float*)d_in[11];
    const float* g1      = (const float*)d_in[12];
    const float* be1     = (const float*)d_in[13];
    const float* Wf1     = (const float*)d_in[14];
    const float* bf1     = (const float*)d_in[15];
    const float* Wf2     = (const float*)d_in[16];
    const float* bf2     = (const float*)d_in[17];
    const float* g2      = (const float*)d_in[18];
    const float* be2     = (const float*)d_in[19];
    const float* Wfin    = (const float*)d_in[20];
    const float* bfin    = (const float*)d_in[21];
    (void)in_sizes; (void)n_in; (void)out_size;

    cudaFuncSetAttribute(gemm_mma<0,1,0,0>, cudaFuncAttributeMaxDynamicSharedMemorySize, GEMM_MMA_SMEM);
    cudaFuncSetAttribute(gemm_mma<1,0,1,0>, cudaFuncAttributeMaxDynamicSharedMemorySize, GEMM_MMA_SMEM);
    cudaFuncSetAttribute(gemm_mma<0,0,0,1>, cudaFuncAttributeMaxDynamicSharedMemorySize, GEMM_MMA_SMEM);
    cudaFuncSetAttribute(attn_kernel, cudaFuncAttributeMaxDynamicSharedMemorySize, ATT_SMEM);

    float *h_p, *buf_p, *hx_p;
    cudaGetSymbolAddress((void**)&h_p,   g_h);
    cudaGetSymbolAddress((void**)&buf_p, g_buf);
    cudaGetSymbolAddress((void**)&hx_p,  g_hx);
    __half *xtf_p, *hf_p, *attnf, *hxf, *fff;
    __half *wotf, *wf1tf, *wf2tf, *wqtf, *wktf, *wvtf, *wftf;
    cudaGetSymbolAddress((void**)&xtf_p, g_xtf);
    cudaGetSymbolAddress((void**)&hf_p,  g_hf);
    cudaGetSymbolAddress((void**)&attnf, g_attnf);
    cudaGetSymbolAddress((void**)&hxf,   g_hxf);
    cudaGetSymbolAddress((void**)&fff,   g_fff);
    cudaGetSymbolAddress((void**)&wotf,  g_wotf);
    cudaGetSymbolAddress((void**)&wf1tf, g_wf1tf);
    cudaGetSymbolAddress((void**)&wf2tf, g_wf2tf);
    cudaGetSymbolAddress((void**)&wqtf,  g_wqtf);
    cudaGetSymbolAddress((void**)&wktf,  g_wktf);
    cudaGetSymbolAddress((void**)&wvtf,  g_wvtf);
    cudaGetSymbolAddress((void**)&wftf,  g_wftf);

    // weight prep: transpose + fp16 convert
    wconv_kernel<<<dim3(E_/32,  E_/32,  L_), dim3(32,8)>>>(Wo,  wotf,  E_,  E_);
    wconv_kernel<<<dim3(FF_/32, E_/32,  L_), dim3(32,8)>>>(Wf1, wf1tf, E_,  FF_);
    wconv_kernel<<<dim3(E_/32,  FF_/32, L_), dim3(32,8)>>>(Wf2, wf2tf, FF_, E_);
    wconv_qkv_kernel<<<dim3(HD_/32, HD_/32, 3*L_), dim3(32,8)>>>(Wq, Wk, Wv);
    wconv_kernel<<<dim3(E_/32,  F_/32,  1),  dim3(32,8)>>>(W_first, wftf, F_, E_);

    xt_kernel<<<dim3(S_/32, F_/32, N_), dim3(32,8)>>>(x);

    // embed: h = relu(xt @ W_first + b) + pos  (tensor GEMM, K=64)
    gemm_mma<0,0,0,1><<<dim3(E_/128, NS_/128), 256, GEMM_MMA_SMEM>>>(
        xtf_p, wftf, b_first, pos_emb, h_p, hf_p, E_, F_);

    for (int i = 0; i < L_; ++i) {
        qkv_mma<<<dim3(S_/128, N_*H_), 256>>>(
            wqtf + i*HD_*HD_, wktf + i*HD_*HD_, wvtf + i*HD_*HD_,
            bq + i*HD_, bk + i*HD_, bv + i*HD_);
        attn_kernel<<<N_*H_*8, 256, ATT_SMEM>>>();

        gemm_mma<0,1,0,0><<<dim3(E_/128, NS_/128), 256, GEMM_MMA_SMEM>>>(
            attnf, wotf + (size_t)i*E_*E_,
            bo + i*E_, h_p, buf_p, (__half*)0, E_, E_);
        ln_kernel<1><<<NS_, 128>>>(buf_p, hx_p, g1 + i*E_, be1 + i*E_, hxf);

        gemm_mma<1,0,1,0><<<dim3(FF_/128, NS_/128), 256, GEMM_MMA_SMEM>>>(
            hxf, wf1tf + (size_t)i*(size_t)E_*FF_,
            bf1 + i*FF_, (const float*)0, (float*)0, fff, FF_, E_);

        gemm_mma<0,1,0,0><<<dim3(E_/128, NS_/128), 256, GEMM_MMA_SMEM>>>(
            fff, wf2tf + (size_t)i*(size_t)FF_*E_,
            bf2 + i*E_, hx_p, buf_p, (__half*)0, E_, FF_);
        ln_kernel<1><<<NS_, 128>>>(buf_p, h_p, g2 + i*E_, be2 + i*E_, hf_p);
    }

    gemm_kernel<1><<<dim3(O_/64, NS_/64), 256>>>(
        h_p, Wfin, bfin, (float*)d_out, NS_, O_, E_);
}

// round 15
// speedup vs baseline: 8.0561x; 1.0640x over previous
#include <cuda_runtime.h>
#include <cuda_fp16.h>
#include <math.h>
#include <stdint.h>

#define N_ 8
#define S_ 1024
#define F_ 64
#define E_ 512
#define H_ 8
#define HD_ 64
#define O_ 64
#define L_ 6
#define FF_ 2048
#define NS_ (N_*S_)

// ---------------- scratch (no allocations allowed) ----------------
__device__ float g_h[NS_*E_];       // running hidden state (n,s,e) fp32 (residual)
__device__ float g_buf[NS_*E_];     // pre-LN sum
__device__ float g_hx[NS_*E_];      // post-LN1 (fp32 residual for FF2)

__device__ __half g_xtf[NS_*F_];    // transposed input (n,s,f) fp16
__device__ __half g_hf[NS_*E_];     // fp16 copy of hidden state (qkv input)

// fp16 q/k/v in (n,h,s,d)  (q pre-scaled by 1/sqrt(E))
__device__ __half g_qf[NS_*E_], g_kf[NS_*E_], g_vf[NS_*E_];

// fp16 activations
__device__ __half g_attnf[NS_*E_];
__device__ __half g_hxf[NS_*E_];
__device__ __half g_fff[NS_*FF_];

// fp16 transposed weights
__device__ __half g_wotf[L_*E_*E_];
__device__ __half g_wf1tf[L_*E_*FF_];
__device__ __half g_wf2tf[L_*FF_*E_];
__device__ __half g_wqtf[L_*HD_*HD_], g_wktf[L_*HD_*HD_], g_wvtf[L_*HD_*HD_];
__device__ __half g_wftf[E_*F_];    // W_first^T fp16 [E][F]

#define ISC 0.044194173824159216f   /* 1/sqrt(E) */

// ================= helpers =================
static __device__ __forceinline__ uint32_t smem_u32(const void* p){
    uint32_t a;
    asm("{ .reg .u64 t; cvta.to.shared.u64 t, %1; cvt.u32.u64 %0, t; }" : "=r"(a) : "l"(p));
    return a;
}
static __device__ __forceinline__ void cp16(uint32_t dst, const void* src){
    asm volatile("cp.async.cg.shared.global [%0], [%1], 16;" :: "r"(dst), "l"(src));
}
#define CP_COMMIT() asm volatile("cp.async.commit_group;" ::: "memory")
#define CP_WAIT0()  asm volatile("cp.async.wait_group 0;" ::: "memory")
#define CP_WAIT1()  asm volatile("cp.async.wait_group 1;" ::: "memory")
#define CP_WAIT2()  asm volatile("cp.async.wait_group 2;" ::: "memory")

#define LDSM4(r, a) \
    asm volatile("ldmatrix.sync.aligned.m8n8.x4.shared.b16 {%0,%1,%2,%3}, [%4];" \
        : "=r"((r)[0]), "=r"((r)[1]), "=r"((r)[2]), "=r"((r)[3]) : "r"(a))
#define LDSM4T(r, a) \
    asm volatile("ldmatrix.sync.aligned.m8n8.x4.trans.shared.b16 {%0,%1,%2,%3}, [%4];" \
        : "=r"((r)[0]), "=r"((r)[1]), "=r"((r)[2]), "=r"((r)[3]) : "r"(a))

static __device__ __forceinline__ void mma16816(
    float* d, const uint32_t* a, uint32_t b0, uint32_t b1)
{
    asm volatile("mma.sync.aligned.m16n8k16.row.col.f32.f16.f16.f32 "
        "{%0,%1,%2,%3}, {%4,%5,%6,%7}, {%8,%9}, {%0,%1,%2,%3};"
        : "+f"(d[0]), "+f"(d[1]), "+f"(d[2]), "+f"(d[3])
        : "r"(a[0]), "r"(a[1]), "r"(a[2]), "r"(a[3]), "r"(b0), "r"(b1));
}

static __device__ __forceinline__ uint32_t pack2h(float a, float b){
    __half2 t = __floats2half2_rn(a, b);
    return *(uint32_t*)&t;
}

// ================= x transpose: x[n][f][s] -> xtf[n][s][f] fp16 =================
__global__ __launch_bounds__(256) void xt_kernel(const float* __restrict__ x)
{
    __shared__ float t[32][33];
    int n = blockIdx.z;
    int s0 = blockIdx.x * 32, f0 = blockIdx.y * 32;
    int tx = threadIdx.x, ty = threadIdx.y;
    for (int y = ty; y < 32; y += 8)
        t[y][tx] = x[(size_t)n*F_*S_ + (size_t)(f0 + y)*S_ + s0 + tx];
    __syncthreads();
    for (int y = ty; y < 32; y += 8)
        g_xtf[((size_t)n*S_ + s0 + y)*F_ + f0 + tx] = __float2half_rn(t[tx][y]);
}

// ================= weight transpose + fp16 convert =================
__global__ __launch_bounds__(256) void wconv_kernel(
    const float* __restrict__ W, __half* __restrict__ out, int K, int N)
{
    __shared__ float t[32][33];
    size_t lstr = (size_t)K*N*blockIdx.z;
    const float* Wl = W + lstr;
    __half* ol = out + lstr;
    int kb = blockIdx.y*32, nb = blockIdx.x*32;
    int x = threadIdx.x, y0 = threadIdx.y;
    for (int y = y0; y < 32; y += 8)
        t[y][x] = Wl[(size_t)(kb+y)*N + nb + x];
    __syncthreads();
    for (int y = y0; y < 32; y += 8)
        ol[(size_t)(nb+y)*K + kb + x] = __float2half_rn(t[x][y]);
}

// merged Wq/Wk/Wv prep: z = mat*L + layer
__global__ __launch_bounds__(256) void wconv_qkv_kernel(
    const float* __restrict__ Wq, const float* __restrict__ Wk,
    const float* __restrict__ Wv)
{
    __shared__ float t[32][33];
    int mat = blockIdx.z / L_, layer = blockIdx.z % L_;
    const float* W = (mat == 0) ? Wq : (mat == 1) ? Wk : Wv;
    __half* out = (mat == 0) ? g_wqtf : (mat == 1) ? g_wktf : g_wvtf;
    size_t lstr = (size_t)HD_*HD_*layer;
    const float* Wl = W + lstr;
    __half* ol = out + lstr;
    int kb = blockIdx.y*32, nb = blockIdx.x*32;
    int x = threadIdx.x, y0 = threadIdx.y;
    for (int y = y0; y < 32; y += 8)
        t[y][x] = Wl[(size_t)(kb+y)*HD_ + nb + x];
    __syncthreads();
    for (int y = y0; y < 32; y += 8)
        ol[(size_t)(nb+y)*HD_ + kb + x] = __float2half_rn(t[x][y]);
}

// ================= kernel 2: QKV projection on tensor cores =================
#define QPT 72
__global__ __launch_bounds__(256) void qkv_mma(
    const __half* __restrict__ Wqt, const __half* __restrict__ Wkt,
    const __half* __restrict__ Wvt,
    const float* __restrict__ bq, const float* __restrict__ bk,
    const float* __restrict__ bv)
{
    __shared__ __half sA[128*QPT];
    __shared__ __half sW[3*64*QPT];

    int s0 = blockIdx.x * 128;
    int nh = blockIdx.y;
    int n = nh >> 3, hh = nh & 7;
    int tid = threadIdx.x;
    int warp = tid >> 5, lane = tid & 31;
    int lr = lane >> 2, lc2 = (lane & 3) * 2;
    int arow = lane & 15, acol = (lane >> 4) * 8;
    int brow = (lane & 7) + ((lane >> 4) << 3);
    int bcol = ((lane >> 3) & 1) * 8;

    #pragma unroll
    for (int i = 0; i < 4; ++i) {
        int id = tid + 256*i;
        int r = id >> 3, c = id & 7;
        *(float4*)&sA[r*QPT + c*8] =
            *(const float4*)(g_hf + ((size_t)n*S_ + s0 + r)*E_ + hh*HD_ + c*8);
    }
    #pragma unroll
    for (int i = 0; i < 6; ++i) {
        int id = tid + 256*i;
        int mat = id >> 9, rr = (id >> 3) & 63, c = id & 7;
        const __half* src = (mat == 0) ? Wqt : (mat == 1) ? Wkt : Wvt;
        *(float4*)&sW[mat*64*QPT + rr*QPT + c*8] = *(const float4*)(src + rr*HD_ + c*8);
    }
    __syncthreads();

    uint32_t sA_u = smem_u32(sA), sW_u = smem_u32(sW);
    #pragma unroll
    for (int mat = 0; mat < 3; ++mat) {
        float acc[8][4];
        #pragma unroll
        for (int nt = 0; nt < 8; ++nt)
            #pragma unroll
            for (int j = 0; j < 4; ++j) acc[nt][j] = 0.0f;
        #pragma unroll
        for (int ks = 0; ks < 4; ++ks) {
            uint32_t af[4];
            LDSM4(af, sA_u + (uint32_t)((warp*16 + arow)*QPT + ks*16 + acol)*2);
            #pragma unroll
            for (int ntp = 0; ntp < 4; ++ntp) {
                uint32_t bfr[4];
                LDSM4(bfr, sW_u + (uint32_t)(mat*64*QPT + (ntp*16 + brow)*QPT + ks*16 + bcol)*2);
                mma16816(acc[2*ntp],   af, bfr[0], bfr[1]);
                mma16816(acc[2*ntp+1], af, bfr[2], bfr[3]);
            }
        }
        const float* bias = (mat == 0) ? bq : (mat == 1) ? bk : bv;
        __half* dst = (mat == 0) ? g_qf : (mat == 1) ? g_kf : g_vf;
        float sc = (mat == 0) ? ISC : 1.0f;     // pre-scale q by 1/sqrt(E)
        size_t rb0 = ((size_t)nh*S_ + s0 + warp*16 + lr)*HD_;
        size_t rb1 = rb0 + 8*HD_;
        #pragma unroll
        for (int nt = 0; nt < 8; ++nt) {
            int c0 = nt*8 + lc2;
            float2 bi = *(const float2*)(bias + c0);
            *(uint32_t*)(dst + rb0 + c0) = pack2h((acc[nt][0] + bi.x)*sc, (acc[nt][1] + bi.y)*sc);
            *(uint32_t*)(dst + rb1 + c0) = pack2h((acc[nt][2] + bi.x)*sc, (acc[nt][3] + bi.y)*sc);
        }
    }
}

// ================= kernel 3: flash attention, 3-stage cp.async K/V =================
// exp on MUFU (__expf) -- frees the fma pipe for the rest of softmax.
#define KPAD 72
#define ATT_STG_B (2*64*KPAD*2)        /* bytes per stage (K + V) = 18432 */
#define ATT_SMEM (3*ATT_STG_B)         /* 55296 bytes */

static __device__ __forceinline__ void attn_load_kv(
    uint32_t sbase, int st, size_t qkv_base, int kt, int tid)
{
    uint32_t s0 = sbase + (uint32_t)st*ATT_STG_B;
    #pragma unroll
    for (int i = 0; i < 2; ++i) {
        int id = tid + 256*i;
        int r = id >> 3, c = id & 7;
        size_t g = qkv_base + (size_t)(kt*64 + r)*HD_ + c*8;
        cp16(s0 +              r*(KPAD*2) + c*16, g_kf + g);
        cp16(s0 + 64*KPAD*2 +  r*(KPAD*2) + c*16, g_vf + g);
    }
    CP_COMMIT();
}

__global__ __launch_bounds__(256) void attn_kernel()
{
    extern __shared__ __half smA[];
    uint32_t sbase = smem_u32(smA);

    int bid = blockIdx.x;
    int qt = bid & 7;
    int nh = bid >> 3;
    int tid = threadIdx.x;
    int warp = tid >> 5, lane = tid & 31;
    int lr = lane >> 2, lc2 = (lane & 3) * 2;

    int brow = (lane & 7) + ((lane >> 4) << 3);
    int bcol = ((lane >> 3) & 1) * 8;
    int vrow = ((lane >> 3) & 1) * 8 + (lane & 7);
    int vcol = (lane >> 4) * 8;

    size_t qkv_base = (size_t)nh * S_ * HD_;
    int qrow0 = qt*128 + warp*16;

    uint32_t qf[4][4];
    #pragma unroll
    for (int ks = 0; ks < 4; ++ks) {
        int d = ks*16 + lc2;
        size_t r0 = qkv_base + (size_t)(qrow0 + lr)*HD_;
        size_t r1 = qkv_base + (size_t)(qrow0 + lr + 8)*HD_;
        qf[ks][0] = *(const uint32_t*)(g_qf + r0 + d);
        qf[ks][1] = *(const uint32_t*)(g_qf + r1 + d);
        qf[ks][2] = *(const uint32_t*)(g_qf + r0 + d + 8);
        qf[ks][3] = *(const uint32_t*)(g_qf + r1 + d + 8);
    }

    float oacc[8][4];
    #pragma unroll
    for (int dt = 0; dt < 8; ++dt)
        #pragma unroll
        for (int j = 0; j < 4; ++j) oacc[dt][j] = 0.0f;
    float m0 = -1e30f, m1 = -1e30f, l0 = 0.0f, l1 = 0.0f;

    attn_load_kv(sbase, 0, qkv_base, 0, tid);
    attn_load_kv(sbase, 1, qkv_base, 1, tid);

    for (int kt = 0; kt < 16; ++kt) {
        if (kt == 15) { CP_WAIT0(); } else { CP_WAIT1(); }
        __syncthreads();          // all warps done with the stage being overwritten next
        if (kt + 2 < 16)
            attn_load_kv(sbase, (kt+2) % 3, qkv_base, kt+2, tid);

        uint32_t sK_u = sbase + (uint32_t)(kt % 3)*ATT_STG_B;
        uint32_t sV_u = sK_u + 64*KPAD*2;

        // S = Q K^T  (q pre-scaled)
        float sacc[8][4];
        #pragma unroll
        for (int nt = 0; nt < 8; ++nt)
            #pragma unroll
            for (int j = 0; j < 4; ++j) sacc[nt][j] = 0.0f;
        #pragma unroll
        for (int ks = 0; ks < 4; ++ks) {
            #pragma unroll
            for (int ntp = 0; ntp < 4; ++ntp) {
                uint32_t off = (uint32_t)((ntp*16 + brow)*KPAD + ks*16 + bcol) * 2;
                uint32_t kh[4];
                LDSM4(kh, sK_u + off);
                mma16816(sacc[2*ntp],   qf[ks], kh[0], kh[1]);
                mma16816(sacc[2*ntp+1], qf[ks], kh[2], kh[3]);
            }
        }

        // online softmax (exp on MUFU)
        float mx0 = -1e30f, mx1 = -1e30f;
        #pragma unroll
        for (int nt = 0; nt < 8; ++nt) {
            mx0 = fmaxf(mx0, fmaxf(sacc[nt][0], sacc[nt][1]));
            mx1 = fmaxf(mx1, fmaxf(sacc[nt][2], sacc[nt][3]));
        }
        mx0 = fmaxf(mx0, __shfl_xor_sync(0xffffffffu, mx0, 1));
        mx0 = fmaxf(mx0, __shfl_xor_sync(0xffffffffu, mx0, 2));
        mx1 = fmaxf(mx1, __shfl_xor_sync(0xffffffffu, mx1, 1));
        mx1 = fmaxf(mx1, __shfl_xor_sync(0xffffffffu, mx1, 2));
        float mn0 = fmaxf(m0, mx0), mn1 = fmaxf(m1, mx1);
        float al0 = __expf(m0 - mn0), al1 = __expf(m1 - mn1);
        m0 = mn0; m1 = mn1;

        uint32_t pah[4][4];
        float ls0 = 0.0f, ls1 = 0.0f;
        #pragma unroll
        for (int nt = 0; nt < 8; ++nt) {
            float p0 = __expf(sacc[nt][0] - mn0);
            float p1 = __expf(sacc[nt][1] - mn0);
            float p2 = __expf(sacc[nt][2] - mn1);
            float p3 = __expf(sacc[nt][3] - mn1);
            ls0 += p0 + p1; ls1 += p2 + p3;
            int ks = nt >> 1, hf = (nt & 1) * 2;
            pah[ks][hf+0] = pack2h(p0, p1);
            pah[ks][hf+1] = pack2h(p2, p3);
        }
        ls0 += __shfl_xor_sync(0xffffffffu, ls0, 1);
        ls0 += __shfl_xor_sync(0xffffffffu, ls0, 2);
        ls1 += __shfl_xor_sync(0xffffffffu, ls1, 1);
        ls1 += __shfl_xor_sync(0xffffffffu, ls1, 2);
        l0 = l0*al0 + ls0; l1 = l1*al1 + ls1;
        #pragma unroll
        for (int dt = 0; dt < 8; ++dt) {
            oacc[dt][0] *= al0; oacc[dt][1] *= al0;
            oacc[dt][2] *= al1; oacc[dt][3] *= al1;
        }

        // O += P V
        #pragma unroll
        for (int ks = 0; ks < 4; ++ks) {
            #pragma unroll
            for (int dtp = 0; dtp < 4; ++dtp) {
                uint32_t off = (uint32_t)((ks*16 + vrow)*KPAD + dtp*16 + vcol) * 2;
                uint32_t vh[4];
                LDSM4T(vh, sV_u + off);
                mma16816(oacc[2*dtp],   pah[ks], vh[0], vh[1]);
                mma16816(oacc[2*dtp+1], pah[ks], vh[2], vh[3]);
            }
        }
    }

    float inv0 = 1.0f / l0, inv1 = 1.0f / l1;
    int n = nh >> 3, hh = nh & 7;
    int row0 = qt*128 + warp*16 + lr;
    size_t b0 = ((size_t)n*S_ + row0)*E_ + hh*HD_;
    size_t b1 = b0 + (size_t)8*E_;
    #pragma unroll
    for (int dt = 0; dt < 8; ++dt) {
        int e = dt*8 + lc2;
        *(uint32_t*)(g_attnf + b0 + e) = pack2h(oacc[dt][0]*inv0, oacc[dt][1]*inv0);
        *(uint32_t*)(g_attnf + b1 + e) = pack2h(oacc[dt][2]*inv1, oacc[dt][3]*inv1);
    }
}

// ================= mma.sync GEMM: fp16, 4-stage BK=16, ldmatrix =================
// EMBED: epilogue = relu(acc+bias) + pos_emb (Rres = pos base, row = m & (S-1)),
//        writes BOTH fp32 Cf and fp16 Ch.
#define ARR_B 6144
#define STG_B (2*ARR_B)
#define NSTG  4
#define GEMM_MMA_SMEM (NSTG*STG_B)

static __device__ __forceinline__ void mma_load_stage16(
    uint32_t sbase, int st,
    const __half* __restrict__ Af, const __half* __restrict__ Bf,
    int m0, int n0, int k0, int K, int tid)
{
    uint32_t s0 = sbase + st*STG_B;
    int r = tid >> 1, c = tid & 1;
    uint32_t off = (uint32_t)(r*48 + c*16);
    cp16(s0 +         off, Af + (size_t)(m0 + r)*K + k0 + c*8);
    cp16(s0 + ARR_B + off, Bf + (size_t)(n0 + r)*K + k0 + c*8);
    CP_COMMIT();
}

template<int RELU, int RESID, int HOUT, int EMBED>
__global__ __launch_bounds__(256, 2) void gemm_mma(
    const __half* __restrict__ Af, const __half* __restrict__ Bf,
    const float* __restrict__ bias, const float* __restrict__ Rres,
    float* __restrict__ Cf, __half* __restrict__ Ch,
    int Nn, int K)
{
    extern __shared__ __half sm[];
    uint32_t sbase = smem_u32(sm);
    int tid = threadIdx.x;
    int warp = tid >> 5, lane = tid & 31;
    int m0 = blockIdx.y * 128, n0 = blockIdx.x * 128;
    int wm0 = (warp & 3) * 32, wn0 = (warp >> 2) * 64;
    int lr = lane >> 2, lc2 = (lane & 3) * 2;

    int arow = lane & 15, acol = (lane >> 4) * 8;
    int brow = (lane & 7) + ((lane >> 4) << 3);
    int bcol = ((lane >> 3) & 1) * 8;

    float acc[2][8][4];
    #pragma unroll
    for (int a = 0; a < 2; ++a)
        #pragma unroll
        for (int b = 0; b < 8; ++b)
            #pragma unroll
            for (int c = 0; c < 4; ++c) acc[a][b][c] = 0.0f;

    int NKB = K >> 4;

    mma_load_stage16(sbase, 0, Af, Bf, m0, n0, 0,  K, tid);
    mma_load_stage16(sbase, 1, Af, Bf, m0, n0, 16, K, tid);
    mma_load_stage16(sbase, 2, Af, Bf, m0, n0, 32, K, tid);

    for (int kb = 0; kb < NKB; ++kb) {
        int st = kb & 3;
        if (kb >= NKB-3) { CP_WAIT0(); } else { CP_WAIT2(); }
        __syncthreads();

        uint32_t su = sbase + st*STG_B;
        uint32_t af[2][4];
        #pragma unroll
        for (int mt = 0; mt < 2; ++mt) {
            uint32_t ad = su + (uint32_t)((wm0 + mt*16 + arow)*48 + acol*2);
            LDSM4(af[mt], ad);
        }
        #pragma unroll
        for (int ntp = 0; ntp < 4; ++ntp) {
            uint32_t bd = su + ARR_B + (uint32_t)((wn0 + ntp*16 + brow)*48 + bcol*2);
            uint32_t bfr[4];
            LDSM4(bfr, bd);
            #pragma unroll
            for (int mt = 0; mt < 2; ++mt) {
                mma16816(acc[mt][2*ntp],   af[mt], bfr[0], bfr[1]);
                mma16816(acc[mt][2*ntp+1], af[mt], bfr[2], bfr[3]);
            }
        }
        if (kb + 3 < NKB)
            mma_load_stage16(sbase, (kb+3) & 3, Af, Bf, m0, n0, (kb+3)*16, K, tid);
    }

    #pragma unroll
    for (int mt = 0; mt < 2; ++mt) {
        #pragma unroll
        for (int half = 0; half < 2; ++half) {
            int m = m0 + wm0 + mt*16 + half*8 + lr;
            #pragma unroll
            for (int nt = 0; nt < 8; ++nt) {
                int c0 = n0 + wn0 + nt*8 + lc2;
                float2 bi = *(const float2*)(bias + c0);
                float v0 = acc[mt][nt][half*2+0] + bi.x;
                float v1 = acc[mt][nt][half*2+1] + bi.y;
                if (EMBED) {
                    int s = m & (S_-1);
                    float2 pe = *(const float2*)(Rres + (size_t)s*Nn + c0);
                    v0 = fmaxf(v0, 0.f) + pe.x;
                    v1 = fmaxf(v1, 0.f) + pe.y;
                    *(float2*)(Cf + (size_t)m*Nn + c0) = make_float2(v0, v1);
                    *(uint32_t*)(Ch + (size_t)m*Nn + c0) = pack2h(v0, v1);
                } else {
                    if (RESID) {
                        float2 rr = *(const float2*)(Rres + (size_t)m*Nn + c0);
                        v0 += rr.x; v1 += rr.y;
                    }
                    if (RELU) { v0 = fmaxf(v0, 0.f); v1 = fmaxf(v1, 0.f); }
                    if (HOUT) {
                        *(uint32_t*)(Ch + (size_t)m*Nn + c0) = pack2h(v0, v1);
                    } else {
                        *(float2*)(Cf + (size_t)m*Nn + c0) = make_float2(v0, v1);
                    }
                }
            }
        }
    }
}

// ================= small SIMT GEMM (final conv, N=64) =================
template<int FINAL>
__global__ __launch_bounds__(256) void gemm_kernel(
    const float* __restrict__ A, const float* __restrict__ B,
    const float* __restrict__ bias, float* __restrict__ C,
    int M, int Nn, int K)
{
    __shared__ float As[16][65];
    __shared__ float Bs[16][64];
    int m0 = blockIdx.y * 64, n0 = blockIdx.x * 64;
    int tid = threadIdx.x;
    int tx = tid & 15, ty = tid >> 4;

    int ar = tid >> 2;
    int ac = (tid & 3) * 4;
    int br = tid >> 4;
    int bc = (tid & 15) * 4;
    const float* Ap = A + (size_t)(m0 + ar)*K + ac;
    const float* Bp = B + (size_t)br*Nn + n0 + bc;

    float acc[4][4] = {};
    for (int k0 = 0; k0 < K; k0 += 16) {
        float4 a4 = *(const float4*)(Ap + k0);
        float4 b4 = *(const float4*)(Bp + (size_t)k0*Nn);
        As[ac+0][ar]=a4.x; As[ac+1][ar]=a4.y; As[ac+2][ar]=a4.z; As[ac+3][ar]=a4.w;
        *(float4*)&Bs[br][bc] = b4;
        __syncthreads();
        #pragma unroll
        for (int kk = 0; kk < 16; ++kk) {
            float a[4], b[4];
            #pragma unroll
            for (int i = 0; i < 4; ++i) a[i] = As[kk][ty + 16*i];
            #pragma unroll
            for (int j = 0; j < 4; ++j) b[j] = Bs[kk][tx + 16*j];
            #pragma unroll
            for (int i = 0; i < 4; ++i)
                #pragma unroll
                for (int j = 0; j < 4; ++j)
                    acc[i][j] = fmaf(a[i], b[j], acc[i][j]);
        }
        __syncthreads();
    }
    #pragma unroll
    for (int i = 0; i < 4; ++i) {
        int mrow = m0 + ty + 16*i;
        #pragma unroll
        for (int j = 0; j < 4; ++j) {
            int nn = n0 + tx + 16*j;
            float v = acc[i][j] + bias[nn];
            if (FINAL) {
                C[((size_t)(mrow >> 10)*O_ + nn)*S_ + (mrow & (S_-1))] = v;
            } else {
                C[(size_t)mrow*Nn + nn] = v;
            }
        }
    }
}

// ================= layernorm, float4-vectorized (optional fp16 output) =================
template<int HOUT>
__global__ __launch_bounds__(128) void ln_kernel(
    const float* __restrict__ in, float* __restrict__ out,
    const float* __restrict__ g, const float* __restrict__ b,
    __half* __restrict__ oh)
{
    int row = blockIdx.x;
    int t = threadIdx.x;
    const float* p = in + (size_t)row*E_;
    float4 v4 = *(const float4*)(p + t*4);
    float s  = v4.x + v4.y + v4.z + v4.w;
    float sq = v4.x*v4.x + v4.y*v4.y + v4.z*v4.z + v4.w*v4.w;
    #pragma unroll
    for (int off = 16; off; off >>= 1) {
        s  += __shfl_xor_sync(0xffffffffu, s,  off);
        sq += __shfl_xor_sync(0xffffffffu, sq, off);
    }
    __shared__ float red[2][4];
    int w = t >> 5;
    if ((t & 31) == 0) { red[0][w] = s; red[1][w] = sq; }
    __syncthreads();
    s  = red[0][0] + red[0][1] + red[0][2] + red[0][3];
    sq = red[1][0] + red[1][1] + red[1][2] + red[1][3];
    float mean = s * (1.0f/E_);
    float var = sq * (1.0f/E_) - mean*mean;
    float inv = rsqrtf(var + 1e-5f);
    float4 g4 = *(const float4*)(g + t*4);
    float4 b4 = *(const float4*)(b + t*4);
    float4 o4;
    o4.x = (v4.x - mean)*inv*g4.x + b4.x;
    o4.y = (v4.y - mean)*inv*g4.y + b4.y;
    o4.z = (v4.z - mean)*inv*g4.z + b4.z;
    o4.w = (v4.w - mean)*inv*g4.w + b4.w;
    *(float4*)(out + (size_t)row*E_ + t*4) = o4;
    if (HOUT) {
        uint2 h2;
        h2.x = pack2h(o4.x, o4.y);
        h2.y = pack2h(o4.z, o4.w);
        *(uint2*)(oh + (size_t)row*E_ + t*4) = h2;
    }
}

// ================= launch =================
extern "C" void kernel_launch(void* const* d_in, const int* in_sizes, int n_in,
                              void* d_out, int out_size)
{
    const float* x       = (const float*)d_in[0];
    const float* W_first = (const float*)d_in[1];
    const float* b_first = (const float*)d_in[2];
    const float* pos_emb = (const float*)d_in[3];
    const float* Wq      = (const float*)d_in[4];
    const float* bq      = (const float*)d_in[5];
    const float* Wk      = (const float*)d_in[6];
    const float* bk      = (const float*)d_in[7];
    const float* Wv      = (const float*)d_in[8];
    const float* bv      = (const float*)d_in[9];
    const float* Wo      = (const float*)d_in[10];
    const float* bo      = (const float*)d_in[11];
    const float* g1      = (const float*)d_in[12];
    const float* be1     = (const float*)d_in[13];
    const float* Wf1     = (const float*)d_in[14];
    const float* bf1     = (const float*)d_in[15];
    const float* Wf2     = (const float*)d_in[16];
    const float* bf2     = (const float*)d_in[17];
    const float* g2      = (const float*)d_in[18];
    const float* be2     = (const float*)d_in[19];
    const float* Wfin    = (const float*)d_in[20];
    const float* bfin    = (const float*)d_in[21];
    (void)in_sizes; (void)n_in; (void)out_size;

    cudaFuncSetAttribute(gemm_mma<0,1,0,0>, cudaFuncAttributeMaxDynamicSharedMemorySize, GEMM_MMA_SMEM);
    cudaFuncSetAttribute(gemm_mma<1,0,1,0>, cudaFuncAttributeMaxDynamicSharedMemorySize, GEMM_MMA_SMEM);
    cudaFuncSetAttribute(gemm_mma<0,0,0,1>, cudaFuncAttributeMaxDynamicSharedMemorySize, GEMM_MMA_SMEM);
    cudaFuncSetAttribute(attn_kernel, cudaFuncAttributeMaxDynamicSharedMemorySize, ATT_SMEM);

    float *h_p, *buf_p, *hx_p;
    cudaGetSymbolAddress((void**)&h_p,   g_h);
    cudaGetSymbolAddress((void**)&buf_p, g_buf);
    cudaGetSymbolAddress((void**)&hx_p,  g_hx);
    __half *xtf_p, *hf_p, *attnf, *hxf, *fff;
    __half *wotf, *wf1tf, *wf2tf, *wqtf, *wktf, *wvtf, *wftf;
    cudaGetSymbolAddress((void**)&xtf_p, g_xtf);
    cudaGetSymbolAddress((void**)&hf_p,  g_hf);
    cudaGetSymbolAddress((void**)&attnf, g_attnf);
    cudaGetSymbolAddress((void**)&hxf,   g_hxf);
    cudaGetSymbolAddress((void**)&fff,   g_fff);
    cudaGetSymbolAddress((void**)&wotf,  g_wotf);
    cudaGetSymbolAddress((void**)&wf1tf, g_wf1tf);
    cudaGetSymbolAddress((void**)&wf2tf, g_wf2tf);
    cudaGetSymbolAddress((void**)&wqtf,  g_wqtf);
    cudaGetSymbolAddress((void**)&wktf,  g_wktf);
    cudaGetSymbolAddress((void**)&wvtf,  g_wvtf);
    cudaGetSymbolAddress((void**)&wftf,  g_wftf);

    // weight prep: transpose + fp16 convert
    wconv_kernel<<<dim3(E_/32,  E_/32,  L_), dim3(32,8)>>>(Wo,  wotf,  E_,  E_);
    wconv_kernel<<<dim3(FF_/32, E_/32,  L_), dim3(32,8)>>>(Wf1, wf1tf, E_,  FF_);
    wconv_kernel<<<dim3(E_/32,  FF_/32, L_), dim3(32,8)>>>(Wf2, wf2tf, FF_, E_);
    wconv_qkv_kernel<<<dim3(HD_/32, HD_/32, 3*L_), dim3(32,8)>>>(Wq, Wk, Wv);
    wconv_kernel<<<dim3(E_/32,  F_/32,  1),  dim3(32,8)>>>(W_first, wftf, F_, E_);

    xt_kernel<<<dim3(S_/32, F_/32, N_), dim3(32,8)>>>(x);

    // embed: h = relu(xt @ W_first + b) + pos  (tensor GEMM, K=64)
    gemm_mma<0,0,0,1><<<dim3(E_/128, NS_/128), 256, GEMM_MMA_SMEM>>>(
        xtf_p, wftf, b_first, pos_emb, h_p, hf_p, E_, F_);

    for (int i = 0; i < L_; ++i) {
        qkv_mma<<<dim3(S_/128, N_*H_), 256>>>(
            wqtf + i*HD_*HD_, wktf + i*HD_*HD_, wvtf + i*HD_*HD_,
            bq + i*HD_, bk + i*HD_, bv + i*HD_);
        attn_kernel<<<N_*H_*8, 256, ATT_SMEM>>>();

        gemm_mma<0,1,0,0><<<dim3(E_/128, NS_/128), 256, GEMM_MMA_SMEM>>>(
            attnf, wotf + (size_t)i*E_*E_,
            bo + i*E_, h_p, buf_p, (__half*)0, E_, E_);
        ln_kernel<1><<<NS_, 128>>>(buf_p, hx_p, g1 + i*E_, be1 + i*E_, hxf);

        gemm_mma<1,0,1,0><<<dim3(FF_/128, NS_/128), 256, GEMM_MMA_SMEM>>>(
            hxf, wf1tf + (size_t)i*(size_t)E_*FF_,
            bf1 + i*FF_, (const float*)0, (float*)0, fff, FF_, E_);

        gemm_mma<0,1,0,0><<<dim3(E_/128, NS_/128), 256, GEMM_MMA_SMEM>>>(
            fff, wf2tf + (size_t)i*(size_t)FF_*E_,
            bf2 + i*E_, hx_p, buf_p, (__half*)0, E_, FF_);
        ln_kernel<1><<<NS_, 128>>>(buf_p, h_p, g2 + i*E_, be2 + i*E_, hf_p);
    }

    gemm_kernel<1><<<dim3(O_/64, NS_/64), 256>>>(
        h_p, Wfin, bfin, (float*)d_out, NS_, O_, E_);
}

// round 16
// speedup vs baseline: 8.2716x; 1.0268x over previous
#include <cuda_runtime.h>
#include <cuda_fp16.h>
#include <math.h>
#include <stdint.h>

#define N_ 8
#define S_ 1024
#define F_ 64
#define E_ 512
#define H_ 8
#define HD_ 64
#define O_ 64
#define L_ 6
#define FF_ 2048
#define NS_ (N_*S_)

// ---------------- scratch (no allocations allowed) ----------------
__device__ float g_h[NS_*E_];       // running hidden state (n,s,e) fp32 (residual)
__device__ float g_buf[NS_*E_];     // pre-LN sum
__device__ float g_hx[NS_*E_];      // post-LN1 (fp32 residual for FF2)

__device__ __half g_xtf[NS_*F_];    // transposed input (n,s,f) fp16
__device__ __half g_hf[NS_*E_];     // fp16 copy of hidden state

// fp16 q/k/v in (n,h,s,d)  (q pre-scaled by 1/sqrt(E))
__device__ __half g_qf[NS_*E_], g_kf[NS_*E_], g_vf[NS_*E_];

// fp16 activations
__device__ __half g_attnf[NS_*E_];
__device__ __half g_hxf[NS_*E_];
__device__ __half g_fff[NS_*FF_];

// fp16 transposed weights
__device__ __half g_wotf[L_*E_*E_];
__device__ __half g_wf1tf[L_*E_*FF_];
__device__ __half g_wf2tf[L_*FF_*E_];
__device__ __half g_wqtf[L_*HD_*HD_], g_wktf[L_*HD_*HD_], g_wvtf[L_*HD_*HD_];
__device__ __half g_wftf[E_*F_];    // W_first^T fp16 [E][F]
__device__ __half g_wfintf[O_*E_];  // Wfin^T fp16 [O][E]

#define ISC 0.044194173824159216f   /* 1/sqrt(E) */

// ================= helpers =================
static __device__ __forceinline__ uint32_t smem_u32(const void* p){
    uint32_t a;
    asm("{ .reg .u64 t; cvta.to.shared.u64 t, %1; cvt.u32.u64 %0, t; }" : "=r"(a) : "l"(p));
    return a;
}
static __device__ __forceinline__ void cp16(uint32_t dst, const void* src){
    asm volatile("cp.async.cg.shared.global [%0], [%1], 16;" :: "r"(dst), "l"(src));
}
#define CP_COMMIT() asm volatile("cp.async.commit_group;" ::: "memory")
#define CP_WAIT0()  asm volatile("cp.async.wait_group 0;" ::: "memory")
#define CP_WAIT1()  asm volatile("cp.async.wait_group 1;" ::: "memory")
#define CP_WAIT2()  asm volatile("cp.async.wait_group 2;" ::: "memory")

#define LDSM4(r, a) \
    asm volatile("ldmatrix.sync.aligned.m8n8.x4.shared.b16 {%0,%1,%2,%3}, [%4];" \
        : "=r"((r)[0]), "=r"((r)[1]), "=r"((r)[2]), "=r"((r)[3]) : "r"(a))
#define LDSM4T(r, a) \
    asm volatile("ldmatrix.sync.aligned.m8n8.x4.trans.shared.b16 {%0,%1,%2,%3}, [%4];" \
        : "=r"((r)[0]), "=r"((r)[1]), "=r"((r)[2]), "=r"((r)[3]) : "r"(a))

static __device__ __forceinline__ void mma16816(
    float* d, const uint32_t* a, uint32_t b0, uint32_t b1)
{
    asm volatile("mma.sync.aligned.m16n8k16.row.col.f32.f16.f16.f32 "
        "{%0,%1,%2,%3}, {%4,%5,%6,%7}, {%8,%9}, {%0,%1,%2,%3};"
        : "+f"(d[0]), "+f"(d[1]), "+f"(d[2]), "+f"(d[3])
        : "r"(a[0]), "r"(a[1]), "r"(a[2]), "r"(a[3]), "r"(b0), "r"(b1));
}

static __device__ __forceinline__ uint32_t pack2h(float a, float b){
    __half2 t = __floats2half2_rn(a, b);
    return *(uint32_t*)&t;
}

// ================= x transpose: x[n][f][s] -> xtf[n][s][f] fp16 =================
__global__ __launch_bounds__(256) void xt_kernel(const float* __restrict__ x)
{
    __shared__ float t[32][33];
    int n = blockIdx.z;
    int s0 = blockIdx.x * 32, f0 = blockIdx.y * 32;
    int tx = threadIdx.x, ty = threadIdx.y;
    for (int y = ty; y < 32; y += 8)
        t[y][tx] = x[(size_t)n*F_*S_ + (size_t)(f0 + y)*S_ + s0 + tx];
    __syncthreads();
    for (int y = ty; y < 32; y += 8)
        g_xtf[((size_t)n*S_ + s0 + y)*F_ + f0 + tx] = __float2half_rn(t[tx][y]);
}

// ================= merged weight prep: ALL weights, one launch =================
// flat tile id over: Wo(1536) Wf1(6144) Wf2(6144) Wq(24) Wk(24) Wv(24) Wfirst(32) Wfin(32)
#define WPREP_BLOCKS (1536+6144+6144+24+24+24+32+32)
__global__ __launch_bounds__(256) void wprep_kernel(
    const float* __restrict__ Wo,  const float* __restrict__ Wf1,
    const float* __restrict__ Wf2, const float* __restrict__ Wq,
    const float* __restrict__ Wk,  const float* __restrict__ Wv,
    const float* __restrict__ Wfirst, const float* __restrict__ Wfin)
{
    __shared__ float t[32][33];
    int id = blockIdx.x;
    const float* W; __half* out; int K, N;
    if (id < 1536)              { W=Wo;     out=g_wotf;   K=E_;  N=E_;  }
    else if ((id-=1536) < 6144) { W=Wf1;    out=g_wf1tf;  K=E_;  N=FF_; }
    else if ((id-=6144) < 6144) { W=Wf2;    out=g_wf2tf;  K=FF_; N=E_;  }
    else if ((id-=6144) < 24)   { W=Wq;     out=g_wqtf;   K=HD_; N=HD_; }
    else if ((id-=24) < 24)     { W=Wk;     out=g_wktf;   K=HD_; N=HD_; }
    else if ((id-=24) < 24)     { W=Wv;     out=g_wvtf;   K=HD_; N=HD_; }
    else if ((id-=24) < 32)     { W=Wfirst; out=g_wftf;   K=F_;  N=E_;  }
    else         { id -= 32;      W=Wfin;   out=g_wfintf; K=E_;  N=O_;  }

    int ntiles = N >> 5, ktiles = K >> 5;
    int tpl = ntiles * ktiles;
    int layer = id / tpl, rem = id % tpl;
    int nb = (rem % ntiles) * 32, kb = (rem / ntiles) * 32;
    size_t lstr = (size_t)K*N*layer;
    const float* Wl = W + lstr;
    __half* ol = out + lstr;

    int x = threadIdx.x & 31, y0 = threadIdx.x >> 5;
    for (int y = y0; y < 32; y += 8)
        t[y][x] = Wl[(size_t)(kb+y)*N + nb + x];
    __syncthreads();
    for (int y = y0; y < 32; y += 8)
        ol[(size_t)(nb+y)*K + kb + x] = __float2half_rn(t[x][y]);
}

// ================= QKV projection on tensor cores =================
#define QPT 72
__global__ __launch_bounds__(256) void qkv_mma(
    const __half* __restrict__ Wqt, const __half* __restrict__ Wkt,
    const __half* __restrict__ Wvt,
    const float* __restrict__ bq, const float* __restrict__ bk,
    const float* __restrict__ bv)
{
    __shared__ __half sA[128*QPT];
    __shared__ __half sW[3*64*QPT];

    int s0 = blockIdx.x * 128;
    int nh = blockIdx.y;
    int n = nh >> 3, hh = nh & 7;
    int tid = threadIdx.x;
    int warp = tid >> 5, lane = tid & 31;
    int lr = lane >> 2, lc2 = (lane & 3) * 2;
    int arow = lane & 15, acol = (lane >> 4) * 8;
    int brow = (lane & 7) + ((lane >> 4) << 3);
    int bcol = ((lane >> 3) & 1) * 8;

    #pragma unroll
    for (int i = 0; i < 4; ++i) {
        int id = tid + 256*i;
        int r = id >> 3, c = id & 7;
        *(float4*)&sA[r*QPT + c*8] =
            *(const float4*)(g_hf + ((size_t)n*S_ + s0 + r)*E_ + hh*HD_ + c*8);
    }
    #pragma unroll
    for (int i = 0; i < 6; ++i) {
        int id = tid + 256*i;
        int mat = id >> 9, rr = (id >> 3) & 63, c = id & 7;
        const __half* src = (mat == 0) ? Wqt : (mat == 1) ? Wkt : Wvt;
        *(float4*)&sW[mat*64*QPT + rr*QPT + c*8] = *(const float4*)(src + rr*HD_ + c*8);
    }
    __syncthreads();

    uint32_t sA_u = smem_u32(sA), sW_u = smem_u32(sW);
    #pragma unroll
    for (int mat = 0; mat < 3; ++mat) {
        float acc[8][4];
        #pragma unroll
        for (int nt = 0; nt < 8; ++nt)
            #pragma unroll
            for (int j = 0; j < 4; ++j) acc[nt][j] = 0.0f;
        #pragma unroll
        for (int ks = 0; ks < 4; ++ks) {
            uint32_t af[4];
            LDSM4(af, sA_u + (uint32_t)((warp*16 + arow)*QPT + ks*16 + acol)*2);
            #pragma unroll
            for (int ntp = 0; ntp < 4; ++ntp) {
                uint32_t bfr[4];
                LDSM4(bfr, sW_u + (uint32_t)(mat*64*QPT + (ntp*16 + brow)*QPT + ks*16 + bcol)*2);
                mma16816(acc[2*ntp],   af, bfr[0], bfr[1]);
                mma16816(acc[2*ntp+1], af, bfr[2], bfr[3]);
            }
        }
        const float* bias = (mat == 0) ? bq : (mat == 1) ? bk : bv;
        __half* dst = (mat == 0) ? g_qf : (mat == 1) ? g_kf : g_vf;
        float sc = (mat == 0) ? ISC : 1.0f;
        size_t rb0 = ((size_t)nh*S_ + s0 + warp*16 + lr)*HD_;
        size_t rb1 = rb0 + 8*HD_;
        #pragma unroll
        for (int nt = 0; nt < 8; ++nt) {
            int c0 = nt*8 + lc2;
            float2 bi = *(const float2*)(bias + c0);
            *(uint32_t*)(dst + rb0 + c0) = pack2h((acc[nt][0] + bi.x)*sc, (acc[nt][1] + bi.y)*sc);
            *(uint32_t*)(dst + rb1 + c0) = pack2h((acc[nt][2] + bi.x)*sc, (acc[nt][3] + bi.y)*sc);
        }
    }
}

// ================= flash attention, 3-stage cp.async K/V, exp on MUFU =================
#define KPAD 72
#define ATT_STG_B (2*64*KPAD*2)
#define ATT_SMEM (3*ATT_STG_B)

static __device__ __forceinline__ void attn_load_kv(
    uint32_t sbase, int st, size_t qkv_base, int kt, int tid)
{
    uint32_t s0 = sbase + (uint32_t)st*ATT_STG_B;
    #pragma unroll
    for (int i = 0; i < 2; ++i) {
        int id = tid + 256*i;
        int r = id >> 3, c = id & 7;
        size_t g = qkv_base + (size_t)(kt*64 + r)*HD_ + c*8;
        cp16(s0 +              r*(KPAD*2) + c*16, g_kf + g);
        cp16(s0 + 64*KPAD*2 +  r*(KPAD*2) + c*16, g_vf + g);
    }
    CP_COMMIT();
}

__global__ __launch_bounds__(256) void attn_kernel()
{
    extern __shared__ __half smA[];
    uint32_t sbase = smem_u32(smA);

    int bid = blockIdx.x;
    int qt = bid & 7;
    int nh = bid >> 3;
    int tid = threadIdx.x;
    int warp = tid >> 5, lane = tid & 31;
    int lr = lane >> 2, lc2 = (lane & 3) * 2;

    int brow = (lane & 7) + ((lane >> 4) << 3);
    int bcol = ((lane >> 3) & 1) * 8;
    int vrow = ((lane >> 3) & 1) * 8 + (lane & 7);
    int vcol = (lane >> 4) * 8;

    size_t qkv_base = (size_t)nh * S_ * HD_;
    int qrow0 = qt*128 + warp*16;

    uint32_t qf[4][4];
    #pragma unroll
    for (int ks = 0; ks < 4; ++ks) {
        int d = ks*16 + lc2;
        size_t r0 = qkv_base + (size_t)(qrow0 + lr)*HD_;
        size_t r1 = qkv_base + (size_t)(qrow0 + lr + 8)*HD_;
        qf[ks][0] = *(const uint32_t*)(g_qf + r0 + d);
        qf[ks][1] = *(const uint32_t*)(g_qf + r1 + d);
        qf[ks][2] = *(const uint32_t*)(g_qf + r0 + d + 8);
        qf[ks][3] = *(const uint32_t*)(g_qf + r1 + d + 8);
    }

    float oacc[8][4];
    #pragma unroll
    for (int dt = 0; dt < 8; ++dt)
        #pragma unroll
        for (int j = 0; j < 4; ++j) oacc[dt][j] = 0.0f;
    float m0 = -1e30f, m1 = -1e30f, l0 = 0.0f, l1 = 0.0f;

    attn_load_kv(sbase, 0, qkv_base, 0, tid);
    attn_load_kv(sbase, 1, qkv_base, 1, tid);

    for (int kt = 0; kt < 16; ++kt) {
        if (kt == 15) { CP_WAIT0(); } else { CP_WAIT1(); }
        __syncthreads();
        if (kt + 2 < 16)
            attn_load_kv(sbase, (kt+2) % 3, qkv_base, kt+2, tid);

        uint32_t sK_u = sbase + (uint32_t)(kt % 3)*ATT_STG_B;
        uint32_t sV_u = sK_u + 64*KPAD*2;

        float sacc[8][4];
        #pragma unroll
        for (int nt = 0; nt < 8; ++nt)
            #pragma unroll
            for (int j = 0; j < 4; ++j) sacc[nt][j] = 0.0f;
        #pragma unroll
        for (int ks = 0; ks < 4; ++ks) {
            #pragma unroll
            for (int ntp = 0; ntp < 4; ++ntp) {
                uint32_t off = (uint32_t)((ntp*16 + brow)*KPAD + ks*16 + bcol) * 2;
                uint32_t kh[4];
                LDSM4(kh, sK_u + off);
                mma16816(sacc[2*ntp],   qf[ks], kh[0], kh[1]);
                mma16816(sacc[2*ntp+1], qf[ks], kh[2], kh[3]);
            }
        }

        float mx0 = -1e30f, mx1 = -1e30f;
        #pragma unroll
        for (int nt = 0; nt < 8; ++nt) {
            mx0 = fmaxf(mx0, fmaxf(sacc[nt][0], sacc[nt][1]));
            mx1 = fmaxf(mx1, fmaxf(sacc[nt][2], sacc[nt][3]));
        }
        mx0 = fmaxf(mx0, __shfl_xor_sync(0xffffffffu, mx0, 1));
        mx0 = fmaxf(mx0, __shfl_xor_sync(0xffffffffu, mx0, 2));
        mx1 = fmaxf(mx1, __shfl_xor_sync(0xffffffffu, mx1, 1));
        mx1 = fmaxf(mx1, __shfl_xor_sync(0xffffffffu, mx1, 2));
        float mn0 = fmaxf(m0, mx0), mn1 = fmaxf(m1, mx1);
        float al0 = __expf(m0 - mn0), al1 = __expf(m1 - mn1);
        m0 = mn0; m1 = mn1;

        uint32_t pah[4][4];
        float ls0 = 0.0f, ls1 = 0.0f;
        #pragma unroll
        for (int nt = 0; nt < 8; ++nt) {
            float p0 = __expf(sacc[nt][0] - mn0);
            float p1 = __expf(sacc[nt][1] - mn0);
            float p2 = __expf(sacc[nt][2] - mn1);
            float p3 = __expf(sacc[nt][3] - mn1);
            ls0 += p0 + p1; ls1 += p2 + p3;
            int ks = nt >> 1, hf = (nt & 1) * 2;
            pah[ks][hf+0] = pack2h(p0, p1);
            pah[ks][hf+1] = pack2h(p2, p3);
        }
        ls0 += __shfl_xor_sync(0xffffffffu, ls0, 1);
        ls0 += __shfl_xor_sync(0xffffffffu, ls0, 2);
        ls1 += __shfl_xor_sync(0xffffffffu, ls1, 1);
        ls1 += __shfl_xor_sync(0xffffffffu, ls1, 2);
        l0 = l0*al0 + ls0; l1 = l1*al1 + ls1;
        #pragma unroll
        for (int dt = 0; dt < 8; ++dt) {
            oacc[dt][0] *= al0; oacc[dt][1] *= al0;
            oacc[dt][2] *= al1; oacc[dt][3] *= al1;
        }

        #pragma unroll
        for (int ks = 0; ks < 4; ++ks) {
            #pragma unroll
            for (int dtp = 0; dtp < 4; ++dtp) {
                uint32_t off = (uint32_t)((ks*16 + vrow)*KPAD + dtp*16 + vcol) * 2;
                uint32_t vh[4];
                LDSM4T(vh, sV_u + off);
                mma16816(oacc[2*dtp],   pah[ks], vh[0], vh[1]);
                mma16816(oacc[2*dtp+1], pah[ks], vh[2], vh[3]);
            }
        }
    }

    float inv0 = 1.0f / l0, inv1 = 1.0f / l1;
    int n = nh >> 3, hh = nh & 7;
    int row0 = qt*128 + warp*16 + lr;
    size_t b0 = ((size_t)n*S_ + row0)*E_ + hh*HD_;
    size_t b1 = b0 + (size_t)8*E_;
    #pragma unroll
    for (int dt = 0; dt < 8; ++dt) {
        int e = dt*8 + lc2;
        *(uint32_t*)(g_attnf + b0 + e) = pack2h(oacc[dt][0]*inv0, oacc[dt][1]*inv0);
        *(uint32_t*)(g_attnf + b1 + e) = pack2h(oacc[dt][2]*inv1, oacc[dt][3]*inv1);
    }
}

// ================= mma.sync GEMM: fp16, 4-stage BK=16, ldmatrix =================
#define ARR_B 6144
#define STG_B (2*ARR_B)
#define NSTG  4
#define GEMM_MMA_SMEM (NSTG*STG_B)

static __device__ __forceinline__ void mma_load_stage16(
    uint32_t sbase, int st,
    const __half* __restrict__ Af, const __half* __restrict__ Bf,
    int m0, int n0, int k0, int K, int tid)
{
    uint32_t s0 = sbase + st*STG_B;
    int r = tid >> 1, c = tid & 1;
    uint32_t off = (uint32_t)(r*48 + c*16);
    cp16(s0 +         off, Af + (size_t)(m0 + r)*K + k0 + c*8);
    cp16(s0 + ARR_B + off, Bf + (size_t)(n0 + r)*K + k0 + c*8);
    CP_COMMIT();
}

template<int RELU, int RESID, int HOUT, int EMBED>
__global__ __launch_bounds__(256, 2) void gemm_mma(
    const __half* __restrict__ Af, const __half* __restrict__ Bf,
    const float* __restrict__ bias, const float* __restrict__ Rres,
    float* __restrict__ Cf, __half* __restrict__ Ch,
    int Nn, int K)
{
    extern __shared__ __half sm[];
    uint32_t sbase = smem_u32(sm);
    int tid = threadIdx.x;
    int warp = tid >> 5, lane = tid & 31;
    int m0 = blockIdx.y * 128, n0 = blockIdx.x * 128;
    int wm0 = (warp & 3) * 32, wn0 = (warp >> 2) * 64;
    int lr = lane >> 2, lc2 = (lane & 3) * 2;

    int arow = lane & 15, acol = (lane >> 4) * 8;
    int brow = (lane & 7) + ((lane >> 4) << 3);
    int bcol = ((lane >> 3) & 1) * 8;

    float acc[2][8][4];
    #pragma unroll
    for (int a = 0; a < 2; ++a)
        #pragma unroll
        for (int b = 0; b < 8; ++b)
            #pragma unroll
            for (int c = 0; c < 4; ++c) acc[a][b][c] = 0.0f;

    int NKB = K >> 4;

    mma_load_stage16(sbase, 0, Af, Bf, m0, n0, 0,  K, tid);
    mma_load_stage16(sbase, 1, Af, Bf, m0, n0, 16, K, tid);
    mma_load_stage16(sbase, 2, Af, Bf, m0, n0, 32, K, tid);

    for (int kb = 0; kb < NKB; ++kb) {
        int st = kb & 3;
        if (kb >= NKB-3) { CP_WAIT0(); } else { CP_WAIT2(); }
        __syncthreads();

        uint32_t su = sbase + st*STG_B;
        uint32_t af[2][4];
        #pragma unroll
        for (int mt = 0; mt < 2; ++mt) {
            uint32_t ad = su + (uint32_t)((wm0 + mt*16 + arow)*48 + acol*2);
            LDSM4(af[mt], ad);
        }
        #pragma unroll
        for (int ntp = 0; ntp < 4; ++ntp) {
            uint32_t bd = su + ARR_B + (uint32_t)((wn0 + ntp*16 + brow)*48 + bcol*2);
            uint32_t bfr[4];
            LDSM4(bfr, bd);
            #pragma unroll
            for (int mt = 0; mt < 2; ++mt) {
                mma16816(acc[mt][2*ntp],   af[mt], bfr[0], bfr[1]);
                mma16816(acc[mt][2*ntp+1], af[mt], bfr[2], bfr[3]);
            }
        }
        if (kb + 3 < NKB)
            mma_load_stage16(sbase, (kb+3) & 3, Af, Bf, m0, n0, (kb+3)*16, K, tid);
    }

    #pragma unroll
    for (int mt = 0; mt < 2; ++mt) {
        #pragma unroll
        for (int half = 0; half < 2; ++half) {
            int m = m0 + wm0 + mt*16 + half*8 + lr;
            #pragma unroll
            for (int nt = 0; nt < 8; ++nt) {
                int c0 = n0 + wn0 + nt*8 + lc2;
                float2 bi = *(const float2*)(bias + c0);
                float v0 = acc[mt][nt][half*2+0] + bi.x;
                float v1 = acc[mt][nt][half*2+1] + bi.y;
                if (EMBED) {
                    int s = m & (S_-1);
                    float2 pe = *(const float2*)(Rres + (size_t)s*Nn + c0);
                    v0 = fmaxf(v0, 0.f) + pe.x;
                    v1 = fmaxf(v1, 0.f) + pe.y;
                    *(float2*)(Cf + (size_t)m*Nn + c0) = make_float2(v0, v1);
                    *(uint32_t*)(Ch + (size_t)m*Nn + c0) = pack2h(v0, v1);
                } else {
                    if (RESID) {
                        float2 rr = *(const float2*)(Rres + (size_t)m*Nn + c0);
                        v0 += rr.x; v1 += rr.y;
                    }
                    if (RELU) { v0 = fmaxf(v0, 0.f); v1 = fmaxf(v1, 0.f); }
                    if (HOUT) {
                        *(uint32_t*)(Ch + (size_t)m*Nn + c0) = pack2h(v0, v1);
                    } else {
                        *(float2*)(Cf + (size_t)m*Nn + c0) = make_float2(v0, v1);
                    }
                }
            }
        }
    }
}

// ================= final conv on tensor cores: BM=128, BN=64, 128 threads =================
// out[n,o,s] = hf @ Wfin^T + bfin
#define FARR_A 6144        /* 128*48 */
#define FARR_B 3072        /* 64*48 */
#define FSTG   (FARR_A+FARR_B)
#define GEMM_FIN_SMEM (4*FSTG)   /* 36864 */

static __device__ __forceinline__ void fin_load_stage(
    uint32_t sbase, int st, const __half* __restrict__ Af,
    const __half* __restrict__ Bf, int m0, int k0, int tid)
{
    uint32_t s0 = sbase + st*FSTG;
    #pragma unroll
    for (int i = 0; i < 2; ++i) {
        int id = tid + 128*i;
        int r = id >> 1, c = id & 1;
        cp16(s0 + (uint32_t)(r*48 + c*16), Af + (size_t)(m0 + r)*E_ + k0 + c*8);
    }
    {
        int r = tid >> 1, c = tid & 1;
        cp16(s0 + FARR_A + (uint32_t)(r*48 + c*16), Bf + (size_t)r*E_ + k0 + c*8);
    }
    CP_COMMIT();
}

__global__ __launch_bounds__(128) void gemm_fin(
    const __half* __restrict__ Af, const __half* __restrict__ Bf,
    const float* __restrict__ bias, float* __restrict__ C)
{
    extern __shared__ __half sm[];
    uint32_t sbase = smem_u32(sm);
    int tid = threadIdx.x;
    int warp = tid >> 5, lane = tid & 31;
    int m0 = blockIdx.x * 128;
    int wm0 = warp * 32;
    int lr = lane >> 2, lc2 = (lane & 3) * 2;

    int arow = lane & 15, acol = (lane >> 4) * 8;
    int brow = (lane & 7) + ((lane >> 4) << 3);
    int bcol = ((lane >> 3) & 1) * 8;

    float acc[2][8][4];
    #pragma unroll
    for (int a = 0; a < 2; ++a)
        #pragma unroll
        for (int b = 0; b < 8; ++b)
            #pragma unroll
            for (int c = 0; c < 4; ++c) acc[a][b][c] = 0.0f;

    const int NKB = E_ >> 4;   // 32

    fin_load_stage(sbase, 0, Af, Bf, m0, 0,  tid);
    fin_load_stage(sbase, 1, Af, Bf, m0, 16, tid);
    fin_load_stage(sbase, 2, Af, Bf, m0, 32, tid);

    for (int kb = 0; kb < NKB; ++kb) {
        int st = kb & 3;
        if (kb >= NKB-3) { CP_WAIT0(); } else { CP_WAIT2(); }
        __syncthreads();

        uint32_t su = sbase + st*FSTG;
        uint32_t af[2][4];
        #pragma unroll
        for (int mt = 0; mt < 2; ++mt) {
            uint32_t ad = su + (uint32_t)((wm0 + mt*16 + arow)*48 + acol*2);
            LDSM4(af[mt], ad);
        }
        #pragma unroll
        for (int ntp = 0; ntp < 4; ++ntp) {
            uint32_t bd = su + FARR_A + (uint32_t)((ntp*16 + brow)*48 + bcol*2);
            uint32_t bfr[4];
            LDSM4(bfr, bd);
            #pragma unroll
            for (int mt = 0; mt < 2; ++mt) {
                mma16816(acc[mt][2*ntp],   af[mt], bfr[0], bfr[1]);
                mma16816(acc[mt][2*ntp+1], af[mt], bfr[2], bfr[3]);
            }
        }
        if (kb + 3 < NKB)
            fin_load_stage(sbase, (kb+3) & 3, Af, Bf, m0, (kb+3)*16, tid);
    }

    // epilogue: out[n, o, s],  m = n*S + s, col = o
    #pragma unroll
    for (int mt = 0; mt < 2; ++mt) {
        #pragma unroll
        for (int half = 0; half < 2; ++half) {
            int m = m0 + wm0 + mt*16 + half*8 + lr;
            int n = m >> 10, s = m & (S_-1);
            float* cb = C + (size_t)n*O_*S_ + s;
            #pragma unroll
            for (int nt = 0; nt < 8; ++nt) {
                int o = nt*8 + lc2;
                float2 bi = *(const float2*)(bias + o);
                cb[(size_t)o*S_]     = acc[mt][nt][half*2+0] + bi.x;
                cb[(size_t)(o+1)*S_] = acc[mt][nt][half*2+1] + bi.y;
            }
        }
    }
}

// ================= layernorm, float4-vectorized (fp32 + fp16 out) =================
__global__ __launch_bounds__(128) void ln_kernel(
    const float* __restrict__ in, float* __restrict__ out,
    const float* __restrict__ g, const float* __restrict__ b,
    __half* __restrict__ oh)
{
    int row = blockIdx.x;
    int t = threadIdx.x;
    const float* p = in + (size_t)row*E_;
    float4 v4 = *(const float4*)(p + t*4);
    float s  = v4.x + v4.y + v4.z + v4.w;
    float sq = v4.x*v4.x + v4.y*v4.y + v4.z*v4.z + v4.w*v4.w;
    #pragma unroll
    for (int off = 16; off; off >>= 1) {
        s  += __shfl_xor_sync(0xffffffffu, s,  off);
        sq += __shfl_xor_sync(0xffffffffu, sq, off);
    }
    __shared__ float red[2][4];
    int w = t >> 5;
    if ((t & 31) == 0) { red[0][w] = s; red[1][w] = sq; }
    __syncthreads();
    s  = red[0][0] + red[0][1] + red[0][2] + red[0][3];
    sq = red[1][0] + red[1][1] + red[1][2] + red[1][3];
    float mean = s * (1.0f/E_);
    float var = sq * (1.0f/E_) - mean*mean;
    float inv = rsqrtf(var + 1e-5f);
    float4 g4 = *(const float4*)(g + t*4);
    float4 b4 = *(const float4*)(b + t*4);
    float4 o4;
    o4.x = (v4.x - mean)*inv*g4.x + b4.x;
    o4.y = (v4.y - mean)*inv*g4.y + b4.y;
    o4.z = (v4.z - mean)*inv*g4.z + b4.z;
    o4.w = (v4.w - mean)*inv*g4.w + b4.w;
    *(float4*)(out + (size_t)row*E_ + t*4) = o4;
    uint2 h2;
    h2.x = pack2h(o4.x, o4.y);
    h2.y = pack2h(o4.z, o4.w);
    *(uint2*)(oh + (size_t)row*E_ + t*4) = h2;
}

// ================= launch =================
extern "C" void kernel_launch(void* const* d_in, const int* in_sizes, int n_in,
                              void* d_out, int out_size)
{
    const float* x       = (const float*)d_in[0];
    const float* W_first = (const float*)d_in[1];
    const float* b_first = (const float*)d_in[2];
    const float* pos_emb = (const float*)d_in[3];
    const float* Wq      = (const float*)d_in[4];
    const float* bq      = (const float*)d_in[5];
    const float* Wk      = (const float*)d_in[6];
    const float* bk      = (const float*)d_in[7];
    const float* Wv      = (const float*)d_in[8];
    const float* bv      = (const float*)d_in[9];
    const float* Wo      = (const float*)d_in[10];
    const float* bo      = (const float*)d_in[11];
    const float* g1      = (const float*)d_in[12];
    const float* be1     = (const float*)d_in[13];
    const float* Wf1     = (const float*)d_in[14];
    const float* bf1     = (const float*)d_in[15];
    const float* Wf2     = (const float*)d_in[16];
    const float* bf2     = (const float*)d_in[17];
    const float* g2      = (const float*)d_in[18];
    const float* be2     = (const float*)d_in[19];
    const float* Wfin    = (const float*)d_in[20];
    const float* bfin    = (const float*)d_in[21];
    (void)in_sizes; (void)n_in; (void)out_size;

    cudaFuncSetAttribute(gemm_mma<0,1,0,0>, cudaFuncAttributeMaxDynamicSharedMemorySize, GEMM_MMA_SMEM);
    cudaFuncSetAttribute(gemm_mma<1,0,1,0>, cudaFuncAttributeMaxDynamicSharedMemorySize, GEMM_MMA_SMEM);
    cudaFuncSetAttribute(gemm_mma<0,0,0,1>, cudaFuncAttributeMaxDynamicSharedMemorySize, GEMM_MMA_SMEM);
    cudaFuncSetAttribute(gemm_fin, cudaFuncAttributeMaxDynamicSharedMemorySize, GEMM_FIN_SMEM);
    cudaFuncSetAttribute(attn_kernel, cudaFuncAttributeMaxDynamicSharedMemorySize, ATT_SMEM);

    float *h_p, *buf_p, *hx_p;
    cudaGetSymbolAddress((void**)&h_p,   g_h);
    cudaGetSymbolAddress((void**)&buf_p, g_buf);
    cudaGetSymbolAddress((void**)&hx_p,  g_hx);
    __half *xtf_p, *hf_p, *attnf, *hxf, *fff;
    __half *wotf, *wf1tf, *wf2tf, *wqtf, *wktf, *wvtf, *wftf, *wfintf;
    cudaGetSymbolAddress((void**)&xtf_p, g_xtf);
    cudaGetSymbolAddress((void**)&hf_p,  g_hf);
    cudaGetSymbolAddress((void**)&attnf, g_attnf);
    cudaGetSymbolAddress((void**)&hxf,   g_hxf);
    cudaGetSymbolAddress((void**)&fff,   g_fff);
    cudaGetSymbolAddress((void**)&wotf,  g_wotf);
    cudaGetSymbolAddress((void**)&wf1tf, g_wf1tf);
    cudaGetSymbolAddress((void**)&wf2tf, g_wf2tf);
    cudaGetSymbolAddress((void**)&wqtf,  g_wqtf);
    cudaGetSymbolAddress((void**)&wktf,  g_wktf);
    cudaGetSymbolAddress((void**)&wvtf,  g_wvtf);
    cudaGetSymbolAddress((void**)&wftf,  g_wftf);
    cudaGetSymbolAddress((void**)&wfintf,g_wfintf);

    // 0: all weight prep in one launch
    wprep_kernel<<<WPREP_BLOCKS, 256>>>(Wo, Wf1, Wf2, Wq, Wk, Wv, W_first, Wfin);
    // 1: input transpose
    xt_kernel<<<dim3(S_/32, F_/32, N_), dim3(32,8)>>>(x);
    // 2: embed (tensor GEMM)
    gemm_mma<0,0,0,1><<<dim3(E_/128, NS_/128), 256, GEMM_MMA_SMEM>>>(
        xtf_p, wftf, b_first, pos_emb, h_p, hf_p, E_, F_);

    for (int i = 0; i < L_; ++i) {
        qkv_mma<<<dim3(S_/128, N_*H_), 256>>>(
            wqtf + i*HD_*HD_, wktf + i*HD_*HD_, wvtf + i*HD_*HD_,
            bq + i*HD_, bk + i*HD_, bv + i*HD_);
        attn_kernel<<<N_*H_*8, 256, ATT_SMEM>>>();

        gemm_mma<0,1,0,0><<<dim3(E_/128, NS_/128), 256, GEMM_MMA_SMEM>>>(
            attnf, wotf + (size_t)i*E_*E_,
            bo + i*E_, h_p, buf_p, (__half*)0, E_, E_);
        ln_kernel<<<NS_, 128>>>(buf_p, hx_p, g1 + i*E_, be1 + i*E_, hxf);

        gemm_mma<1,0,1,0><<<dim3(FF_/128, NS_/128), 256, GEMM_MMA_SMEM>>>(
            hxf, wf1tf + (size_t)i*(size_t)E_*FF_,
            bf1 + i*FF_, (const float*)0, (float*)0, fff, FF_, E_);

        gemm_mma<0,1,0,0><<<dim3(E_/128, NS_/128), 256, GEMM_MMA_SMEM>>>(
            fff, wf2tf + (size_t)i*(size_t)FF_*E_,
            bf2 + i*E_, hx_p, buf_p, (__half*)0, E_, FF_);
        ln_kernel<<<NS_, 128>>>(buf_p, h_p, g2 + i*E_, be2 + i*E_, hf_p);
    }

    // final conv on tensor cores
    gemm_fin<<<NS_/128, 128, GEMM_FIN_SMEM>>>(hf_p, wfintf, bfin, (float*)d_out);
}